// round 13
// baseline (speedup 1.0000x reference)
#include <cuda_runtime.h>
#include <cuda_fp16.h>
#include <math.h>
#include <stdint.h>
#include <string.h>

// ---------------- problem constants ----------------
#define Tn     4096
#define Sn     2048
#define DIMn   2048
#define NHn    16
#define NOPEn  128
#define ROPEn  64
#define QDn    192
#define VHn    128
#define KVRn   512
#define NEn    8
#define MINTERn 1408
#define SHIn   2816
#define QPROJ  3072
#define KVAP   576
#define KVBP   4096
#define MOE_ROWS 9216
#define MOE_TILES 72
#define ZSn    32

// ---------------- fp32 scratch ----------------
__device__ float g_kv[(size_t)Tn*KVAP];
__device__ float g_kpe[(size_t)Tn*ROPEn];
__device__ float g_h[(size_t)Tn*DIMn];
__device__ float g_eo[(size_t)MOE_ROWS*DIMn];
__device__ float g_sh[(size_t)Tn*DIMn];
__device__ int   g_counts[NEn];
__device__ int   g_off[NEn+1];
__device__ int   g_tile_expert[MOE_TILES];
__device__ int   g_bucket_ts[NEn*Tn];
__device__ float g_bucket_gate[NEn*Tn];
__device__ int   g_flat_tok[MOE_ROWS];
__device__ int   g_tok2row[Tn*2];
__device__ float g_tok2gate[Tn*2];
// ---------------- fp16 scratch ----------------
__device__ __half g_nx_h[(size_t)Tn*DIMn];
__device__ __half g_ckv_h[(size_t)Tn*KVRn];
__device__ __half g_qh[(size_t)Tn*QPROJ];
__device__ __half g_kvb_h[(size_t)Tn*KVBP];
__device__ __half g_kcat_h[(size_t)ZSn*Sn*QDn];
__device__ __half g_vT_h[(size_t)ZSn*VHn*Sn];
__device__ __half g_attn_h[(size_t)Tn*DIMn];
__device__ __half g_nh_h[(size_t)Tn*DIMn];
__device__ __half g_xg_h[(size_t)MOE_ROWS*DIMn];
__device__ __half g_t13h[(size_t)MOE_ROWS*2*MINTERn];
__device__ __half g_t1h[(size_t)MOE_ROWS*MINTERn];
__device__ __half g_s13h[(size_t)Tn*2*SHIn];
__device__ __half g_s1h[(size_t)Tn*SHIn];
// fp16 weight copies
__device__ __half g_wq_h[(size_t)QPROJ*DIMn];
__device__ __half g_wkva_h[(size_t)KVAP*DIMn];
__device__ __half g_wkvb_h[(size_t)KVBP*KVRn];
__device__ __half g_wo_h[(size_t)DIMn*DIMn];
__device__ __half g_ew13_h[(size_t)NEn*2*MINTERn*DIMn];
__device__ __half g_ew2_h[(size_t)NEn*DIMn*MINTERn];
__device__ __half g_sw13_h[(size_t)2*SHIn*DIMn];
__device__ __half g_sw2_h[(size_t)DIMn*SHIn];

// ---------------- helpers ----------------
__device__ __forceinline__ uint32_t h2u(__half2 h) {
    uint32_t u; memcpy(&u, &h, 4); return u;
}
__device__ __forceinline__ void mma16(float* c, const uint32_t* a, const uint32_t* b) {
    asm volatile("mma.sync.aligned.m16n8k16.row.col.f32.f16.f16.f32 "
        "{%0,%1,%2,%3}, {%4,%5,%6,%7}, {%8,%9}, {%0,%1,%2,%3};"
        : "+f"(c[0]), "+f"(c[1]), "+f"(c[2]), "+f"(c[3])
        : "r"(a[0]), "r"(a[1]), "r"(a[2]), "r"(a[3]), "r"(b[0]), "r"(b[1]));
}
__device__ __forceinline__ void ldsm4(uint32_t* r, uint32_t addr) {
    asm volatile("ldmatrix.sync.aligned.m8n8.x4.shared.b16 {%0,%1,%2,%3}, [%4];"
        : "=r"(r[0]), "=r"(r[1]), "=r"(r[2]), "=r"(r[3]) : "r"(addr));
}
__device__ __forceinline__ void cpasync16(uint32_t dst, const void* src, int sz) {
    asm volatile("cp.async.cg.shared.global [%0], [%1], 16, %2;"
                 :: "r"(dst), "l"(src), "r"(sz));
}
__device__ __forceinline__ void cpcommit() { asm volatile("cp.async.commit_group;"); }
__device__ __forceinline__ void cpwait1() { asm volatile("cp.async.wait_group 1;"); }
__device__ __forceinline__ void cpwait2() { asm volatile("cp.async.wait_group 2;"); }

// ---------------- fp16 tensor GEMM, 128x128 CTA, 4-stage, 2 CTAs/SM ----------------
// flags: 1 add addend(fp32 out), 8 fp16 out
#define LDPH 20
#define AROWB (LDPH*4)               // 80 bytes
#define TNW 128
#define NTT 4
#define ABY (128*AROWB)
#define STG (2*ABY)
#define HG_SMEM (4*STG)              // 81920 B

__global__ __launch_bounds__(256, 2) void hgemm_k(
    const __half* __restrict__ A, const __half* __restrict__ B, void* __restrict__ Cv,
    const float* __restrict__ addend,
    int M, int N, int K, int lda, int ldb, int ldc,
    long sA0, long sA1, long sB0, long sB1, long sC0, long sC1, int ZH,
    const int* __restrict__ tileExpert, long wStride, int flags)
{
    int bx = blockIdx.x, by = blockIdx.y, z = blockIdx.z;
    if (tileExpert) { int te = tileExpert[by]; if (te < 0) return; B += (long)te * wStride; }
    int zb = z / ZH, zh = z - zb * ZH;
    A += zb * sA0 + (long)zh * sA1;
    B += zb * sB0 + (long)zh * sB1;
    int NT = K >> 5;

    extern __shared__ char smraw[];
    uint32_t sb = (uint32_t)__cvta_generic_to_shared(smraw);

    int tid = threadIdx.x;
    int wid = tid >> 5, lane = tid & 31;
    int wy = wid & 1, wx = wid >> 1;

    int grp = lane >> 3, lrow = lane & 7;
    uint32_t aoff = (uint32_t)((wy * 64 + (grp & 1) * 8 + lrow) * AROWB + (grp >> 1) * 16);
    uint32_t boff = (uint32_t)((wx * 32 + (grp >> 1) * 8 + lrow) * AROWB + (grp & 1) * 16);

    int ar0 = tid >> 2, ac0 = tid & 3;
    int bsz[2];
#pragma unroll
    for (int ch = 0; ch < 2; ch++) {
        int row = ar0 + ch * 64;
        bsz[ch] = ((bx * TNW + row) < N) ? 16 : 0;
    }
    const __half* bsrc0 = B;

    auto issue = [&](int s, int k0) {
        uint32_t Ab = sb + s * STG;
        uint32_t Bb = Ab + ABY;
#pragma unroll
        for (int ch = 0; ch < 2; ch++) {
            int row = ar0 + ch * 64;
            const __half* src = A + (long)(by * 128 + row) * lda + k0 + ac0 * 8;
            cpasync16(Ab + row * AROWB + ac0 * 16, src, 16);
        }
#pragma unroll
        for (int ch = 0; ch < 2; ch++) {
            int row = ar0 + ch * 64;
            const __half* src = bsz[ch] ? (B + (long)(bx * TNW + row) * ldb + k0 + ac0 * 8) : bsrc0;
            cpasync16(Bb + row * AROWB + ac0 * 16, src, bsz[ch]);
        }
    };

#pragma unroll
    for (int s = 0; s < 3; s++) {
        if (s < NT) issue(s, s * 32);
        cpcommit();
    }

    float acc[4][NTT][4];
#pragma unroll
    for (int mt = 0; mt < 4; mt++)
#pragma unroll
        for (int nt = 0; nt < NTT; nt++)
#pragma unroll
            for (int i = 0; i < 4; i++) acc[mt][nt][i] = 0.f;

    for (int it = 0; it < NT; ++it) {
        cpwait2();
        __syncthreads();
        if (it + 3 < NT) issue((it + 3) & 3, (it + 3) * 32);
        cpcommit();

        int st = it & 3;
        uint32_t Abase = sb + st * STG + aoff;
        uint32_t Bbase = sb + st * STG + ABY + boff;
#pragma unroll
        for (int ks = 0; ks < 2; ks++) {
            uint32_t af[4][4], bf[NTT][2];
#pragma unroll
            for (int mt = 0; mt < 4; mt++)
                ldsm4(af[mt], Abase + mt * (16 * AROWB) + ks * 32);
#pragma unroll
            for (int p = 0; p < NTT / 2; p++) {
                uint32_t r[4];
                ldsm4(r, Bbase + p * (16 * AROWB) + ks * 32);
                bf[2 * p][0] = r[0]; bf[2 * p][1] = r[1];
                bf[2 * p + 1][0] = r[2]; bf[2 * p + 1][1] = r[3];
            }
#pragma unroll
            for (int mt = 0; mt < 4; mt++)
#pragma unroll
                for (int nt = 0; nt < NTT; nt++)
                    mma16(acc[mt][nt], af[mt], bf[nt]);
        }
        __syncthreads();
    }

    bool doadd = (flags & 1) != 0;
    bool outh = (flags & 8) != 0;
    float* Cf = (float*)Cv + zb * sC0 + (long)zh * sC1;
    __half* Ch = (__half*)Cv + zb * sC0 + (long)zh * sC1;
    const float* Af = addend ? (addend + zb * sC0 + (long)zh * sC1) : nullptr;
    int elr = lane >> 2, elk = lane & 3;
#pragma unroll
    for (int mt = 0; mt < 4; mt++) {
        int m0 = by * 128 + wy * 64 + mt * 16 + elr;
#pragma unroll
        for (int nt = 0; nt < NTT; nt++) {
            int c0 = bx * TNW + wx * 32 + nt * 8 + 2 * elk;
            if (c0 < N) {
                float2 v0 = make_float2(acc[mt][nt][0], acc[mt][nt][1]);
                float2 v1 = make_float2(acc[mt][nt][2], acc[mt][nt][3]);
                if (outh) {
                    *(__half2*)(Ch + (long)m0 * ldc + c0) = __float22half2_rn(v0);
                    *(__half2*)(Ch + (long)(m0 + 8) * ldc + c0) = __float22half2_rn(v1);
                } else {
                    if (doadd) {
                        float2 o0 = *(const float2*)(Af + (long)m0 * ldc + c0);
                        float2 o1 = *(const float2*)(Af + (long)(m0 + 8) * ldc + c0);
                        v0.x += o0.x; v0.y += o0.y; v1.x += o1.x; v1.y += o1.y;
                    }
                    *(float2*)(Cf + (long)m0 * ldc + c0) = v0;
                    *(float2*)(Cf + (long)(m0 + 8) * ldc + c0) = v1;
                }
            }
        }
    }
}

// ---------------- fused flash attention ----------------
#define QROWB 400
#define VROWB 272
#define FA_QS 0
#define FA_KS (128*QROWB)
#define FA_VS (2*128*QROWB)
#define FA_PS (FA_VS + 128*VROWB)
#define FA_RA (FA_PS + 128*VROWB)
#define FA_RB (FA_RA + 2048)
#define FA_SMEM (FA_RB + 2048)

__global__ __launch_bounds__(256) void fattn_k(
    const __half* __restrict__ qh, const __half* __restrict__ kcat,
    const __half* __restrict__ vT, __half* __restrict__ attn)
{
    int by = (int)gridDim.x - 1 - blockIdx.x;
    int z = blockIdx.y;
    int zb = z >> 4, zh = z & 15;

    extern __shared__ char smraw[];
    uint32_t sb = (uint32_t)__cvta_generic_to_shared(smraw);
    float* rowA = (float*)(smraw + FA_RA);
    float* rowB = (float*)(smraw + FA_RB);

    int tid = threadIdx.x;
    int wid = tid >> 5, lane = tid & 31;
    int wy = wid & 1, wx = wid >> 1;
    int grp = lane >> 3, lrow = lane & 7;
    int elr = lane >> 2, elk = lane & 3;

    uint32_t aoffQ = (uint32_t)((wy * 64 + (grp & 1) * 8 + lrow) * QROWB + (grp >> 1) * 16);
    uint32_t boffK = (uint32_t)((wx * 32 + (grp >> 1) * 8 + lrow) * QROWB + (grp & 1) * 16);
    uint32_t aoffP = (uint32_t)((wy * 64 + (grp & 1) * 8 + lrow) * VROWB + (grp >> 1) * 16);
    uint32_t boffV = (uint32_t)((wx * 32 + (grp >> 1) * 8 + lrow) * VROWB + (grp & 1) * 16);

    const __half* Qg = qh + ((long)zb * Sn + (long)by * 128) * QPROJ + zh * QDn;
    const __half* Kg = kcat + (long)z * Sn * QDn;
    const __half* Vg = vT + (long)z * VHn * Sn;

    auto issueK = [&](int kb) {
#pragma unroll
        for (int ch = 0; ch < 12; ch++) {
            int idx = tid + ch * 256;
            int row = idx / 24, cq = idx - row * 24;
            cpasync16(sb + FA_KS + row * QROWB + cq * 16,
                      Kg + ((long)kb * 128 + row) * QDn + cq * 8, 16);
        }
    };
    auto issueV = [&](int kb) {
#pragma unroll
        for (int ch = 0; ch < 8; ch++) {
            int idx = tid + ch * 256;
            int row = idx >> 4, cq = idx & 15;
            cpasync16(sb + FA_VS + row * VROWB + cq * 16,
                      Vg + (long)row * Sn + kb * 128 + cq * 8, 16);
        }
    };

#pragma unroll
    for (int ch = 0; ch < 12; ch++) {
        int idx = tid + ch * 256;
        int row = idx / 24, cq = idx - row * 24;
        cpasync16(sb + FA_QS + row * QROWB + cq * 16, Qg + (long)row * QPROJ + cq * 8, 16);
    }
    cpcommit();
    issueK(0); cpcommit();
    issueV(0); cpcommit();

    float accO[4][4][4];
    float mold[4][2], lrun[4][2];
#pragma unroll
    for (int mt = 0; mt < 4; mt++) {
#pragma unroll
        for (int nt = 0; nt < 4; nt++)
#pragma unroll
            for (int i = 0; i < 4; i++) accO[mt][nt][i] = 0.f;
        mold[mt][0] = -3.4e38f; mold[mt][1] = -3.4e38f;
        lrun[mt][0] = 0.f; lrun[mt][1] = 0.f;
    }

    for (int kb = 0; kb <= by; kb++) {
        cpwait1();
        __syncthreads();

        float accS[4][4][4];
#pragma unroll
        for (int mt = 0; mt < 4; mt++)
#pragma unroll
            for (int nt = 0; nt < 4; nt++)
#pragma unroll
                for (int i = 0; i < 4; i++) accS[mt][nt][i] = 0.f;
#pragma unroll
        for (int ks = 0; ks < 12; ks++) {
            uint32_t af[4][4], bf[4][2];
#pragma unroll
            for (int mt = 0; mt < 4; mt++)
                ldsm4(af[mt], sb + FA_QS + aoffQ + mt * (16 * QROWB) + ks * 32);
#pragma unroll
            for (int p = 0; p < 2; p++) {
                uint32_t r[4];
                ldsm4(r, sb + FA_KS + boffK + p * (16 * QROWB) + ks * 32);
                bf[2 * p][0] = r[0]; bf[2 * p][1] = r[1];
                bf[2 * p + 1][0] = r[2]; bf[2 * p + 1][1] = r[3];
            }
#pragma unroll
            for (int mt = 0; mt < 4; mt++)
#pragma unroll
                for (int nt = 0; nt < 4; nt++)
                    mma16(accS[mt][nt], af[mt], bf[nt]);
        }
        if (kb == by) {
#pragma unroll
            for (int mt = 0; mt < 4; mt++) {
                int r0 = wy * 64 + mt * 16 + elr, r1 = r0 + 8;
#pragma unroll
                for (int nt = 0; nt < 4; nt++) {
                    int c = wx * 32 + nt * 8 + 2 * elk;
                    if (c > r0)     accS[mt][nt][0] = -3.4e38f;
                    if (c + 1 > r0) accS[mt][nt][1] = -3.4e38f;
                    if (c > r1)     accS[mt][nt][2] = -3.4e38f;
                    if (c + 1 > r1) accS[mt][nt][3] = -3.4e38f;
                }
            }
        }
        float lmax[4][2];
#pragma unroll
        for (int mt = 0; mt < 4; mt++) {
            float a = -3.4e38f, b = -3.4e38f;
#pragma unroll
            for (int nt = 0; nt < 4; nt++) {
                a = fmaxf(a, fmaxf(accS[mt][nt][0], accS[mt][nt][1]));
                b = fmaxf(b, fmaxf(accS[mt][nt][2], accS[mt][nt][3]));
            }
            lmax[mt][0] = a; lmax[mt][1] = b;
        }
#pragma unroll
        for (int off = 1; off <= 2; off <<= 1)
#pragma unroll
            for (int mt = 0; mt < 4; mt++) {
                lmax[mt][0] = fmaxf(lmax[mt][0], __shfl_xor_sync(0xffffffffu, lmax[mt][0], off));
                lmax[mt][1] = fmaxf(lmax[mt][1], __shfl_xor_sync(0xffffffffu, lmax[mt][1], off));
            }
        if (elk == 0) {
#pragma unroll
            for (int mt = 0; mt < 4; mt++) {
                int m = wy * 64 + mt * 16 + elr;
                rowA[wx * 128 + m] = lmax[mt][0];
                rowA[wx * 128 + m + 8] = lmax[mt][1];
            }
        }
        __syncthreads();
        if (kb + 1 <= by) issueK(kb + 1);
        cpcommit();

        float mnew[4][2];
#pragma unroll
        for (int mt = 0; mt < 4; mt++) {
#pragma unroll
            for (int hf = 0; hf < 2; hf++) {
                int m = wy * 64 + mt * 16 + elr + hf * 8;
                float v = fmaxf(fmaxf(rowA[m], rowA[128 + m]),
                                fmaxf(rowA[256 + m], rowA[384 + m]));
                mnew[mt][hf] = fmaxf(mold[mt][hf], v);
            }
        }
        float lsum[4][2];
#pragma unroll
        for (int mt = 0; mt < 4; mt++) { lsum[mt][0] = 0.f; lsum[mt][1] = 0.f; }
#pragma unroll
        for (int mt = 0; mt < 4; mt++) {
            int r0 = wy * 64 + mt * 16 + elr;
#pragma unroll
            for (int nt = 0; nt < 4; nt++) {
                int c = wx * 32 + nt * 8 + 2 * elk;
                float p0 = __expf(accS[mt][nt][0] - mnew[mt][0]);
                float p1 = __expf(accS[mt][nt][1] - mnew[mt][0]);
                float p2 = __expf(accS[mt][nt][2] - mnew[mt][1]);
                float p3 = __expf(accS[mt][nt][3] - mnew[mt][1]);
                lsum[mt][0] += p0 + p1;
                lsum[mt][1] += p2 + p3;
                *(__half2*)(smraw + FA_PS + r0 * VROWB + c * 2) =
                    __float22half2_rn(make_float2(p0, p1));
                *(__half2*)(smraw + FA_PS + (r0 + 8) * VROWB + c * 2) =
                    __float22half2_rn(make_float2(p2, p3));
            }
        }
#pragma unroll
        for (int off = 1; off <= 2; off <<= 1)
#pragma unroll
            for (int mt = 0; mt < 4; mt++) {
                lsum[mt][0] += __shfl_xor_sync(0xffffffffu, lsum[mt][0], off);
                lsum[mt][1] += __shfl_xor_sync(0xffffffffu, lsum[mt][1], off);
            }
        if (elk == 0) {
#pragma unroll
            for (int mt = 0; mt < 4; mt++) {
                int m = wy * 64 + mt * 16 + elr;
                rowB[wx * 128 + m] = lsum[mt][0];
                rowB[wx * 128 + m + 8] = lsum[mt][1];
            }
        }
        cpwait1();
        __syncthreads();

#pragma unroll
        for (int mt = 0; mt < 4; mt++) {
#pragma unroll
            for (int hf = 0; hf < 2; hf++) {
                int m = wy * 64 + mt * 16 + elr + hf * 8;
                float rs = rowB[m] + rowB[128 + m] + rowB[256 + m] + rowB[384 + m];
                float fsc = __expf(mold[mt][hf] - mnew[mt][hf]);
                lrun[mt][hf] = lrun[mt][hf] * fsc + rs;
                mold[mt][hf] = mnew[mt][hf];
#pragma unroll
                for (int nt = 0; nt < 4; nt++) {
                    accO[mt][nt][hf * 2 + 0] *= fsc;
                    accO[mt][nt][hf * 2 + 1] *= fsc;
                }
            }
        }
#pragma unroll
        for (int ks = 0; ks < 8; ks++) {
            uint32_t af[4][4], bf[4][2];
#pragma unroll
            for (int mt = 0; mt < 4; mt++)
                ldsm4(af[mt], sb + FA_PS + aoffP + mt * (16 * VROWB) + ks * 32);
#pragma unroll
            for (int p = 0; p < 2; p++) {
                uint32_t r[4];
                ldsm4(r, sb + FA_VS + boffV + p * (16 * VROWB) + ks * 32);
                bf[2 * p][0] = r[0]; bf[2 * p][1] = r[1];
                bf[2 * p + 1][0] = r[2]; bf[2 * p + 1][1] = r[3];
            }
#pragma unroll
            for (int mt = 0; mt < 4; mt++)
#pragma unroll
                for (int nt = 0; nt < 4; nt++)
                    mma16(accO[mt][nt], af[mt], bf[nt]);
        }
        __syncthreads();
        if (kb + 1 <= by) issueV(kb + 1);
        cpcommit();
    }

    __half* Og = attn + (long)zb * Sn * DIMn + zh * VHn;
#pragma unroll
    for (int mt = 0; mt < 4; mt++) {
        float i0 = 1.f / lrun[mt][0], i1 = 1.f / lrun[mt][1];
        int m = by * 128 + wy * 64 + mt * 16 + elr;
#pragma unroll
        for (int nt = 0; nt < 4; nt++) {
            int d = wx * 32 + nt * 8 + 2 * elk;
            *(__half2*)(Og + (long)m * DIMn + d) =
                __float22half2_rn(make_float2(accO[mt][nt][0] * i0, accO[mt][nt][1] * i0));
            *(__half2*)(Og + (long)(m + 8) * DIMn + d) =
                __float22half2_rn(make_float2(accO[mt][nt][2] * i1, accO[mt][nt][3] * i1));
        }
    }
}

// ---------------- vectorized weight fp32 -> fp16 (8 floats / thread) ----------------
__global__ void cvt8_k(const float4* __restrict__ src, uint4* __restrict__ dst, long n8)
{
    long i = (long)blockIdx.x * blockDim.x + threadIdx.x;
    if (i < n8) {
        float4 a = src[2 * i], b = src[2 * i + 1];
        uint4 o;
        o.x = h2u(__floats2half2_rn(a.x, a.y));
        o.y = h2u(__floats2half2_rn(a.z, a.w));
        o.z = h2u(__floats2half2_rn(b.x, b.y));
        o.w = h2u(__floats2half2_rn(b.z, b.w));
        dst[i] = o;
    }
}
__global__ void cvtmoe8_k(const float4* __restrict__ src, uint4* __restrict__ dst,
                          long perExp8, long dstStride8, long dstOff8, long total8)
{
    long i = (long)blockIdx.x * blockDim.x + threadIdx.x;
    if (i < total8) {
        long e = i / perExp8, r = i - e * perExp8;
        float4 a = src[2 * i], b = src[2 * i + 1];
        uint4 o;
        o.x = h2u(__floats2half2_rn(a.x, a.y));
        o.y = h2u(__floats2half2_rn(a.z, a.w));
        o.z = h2u(__floats2half2_rn(b.x, b.y));
        o.w = h2u(__floats2half2_rn(b.z, b.w));
        dst[e * dstStride8 + dstOff8 + r] = o;
    }
}

// ---------------- reductions ----------------
__device__ __forceinline__ float warpSum(float v) {
#pragma unroll
    for (int o = 16; o; o >>= 1) v += __shfl_xor_sync(0xffffffffu, v, o);
    return v;
}

// ---------------- rmsnorm: fp32 in -> fp16 out ----------------
__global__ void rmsnorm_h(const float* __restrict__ x, const float* __restrict__ w,
                          __half* __restrict__ y, int D, int ldx, int ldy)
{
    long t = blockIdx.x;
    const float* xr = x + t * ldx;
    __half* yr = y + t * ldy;
    float s = 0.f;
    for (int d = threadIdx.x; d < D; d += blockDim.x) { float v = xr[d]; s += v * v; }
    __shared__ float sh[32];
    __shared__ float bc;
    s = warpSum(s);
    int lane = threadIdx.x & 31, wp = threadIdx.x >> 5;
    if (!lane) sh[wp] = s;
    __syncthreads();
    if (threadIdx.x < 32) {
        float r = (threadIdx.x < (blockDim.x >> 5)) ? sh[threadIdx.x] : 0.f;
        r = warpSum(r);
        if (!threadIdx.x) bc = rsqrtf(r / D + 1e-6f);
    }
    __syncthreads();
    float sc = bc;
    for (int d = threadIdx.x; d < D; d += blockDim.x)
        yr[d] = __float2half_rn(xr[d] * sc * w[d]);
}

// ---------------- rope on k_pe (fp32) ----------------
__global__ void rope_kpe_k(const float* __restrict__ kv, const float* __restrict__ fc,
                           const float* __restrict__ fs, float* __restrict__ kpe)
{
    long t = blockIdx.x;
    int j = threadIdx.x;
    int pos = (int)(t % Sn);
    float x1 = kv[t * KVAP + KVRn + 2 * j];
    float x2 = kv[t * KVAP + KVRn + 2 * j + 1];
    float c = fc[pos * 32 + j], s = fs[pos * 32 + j];
    kpe[t * ROPEn + 2 * j]     = x1 * c - x2 * s;
    kpe[t * ROPEn + 2 * j + 1] = x1 * s + x2 * c;
}

// ---------------- rope + scale on q: fp16 in-place ----------------
__global__ void ropescale_qh(__half* __restrict__ qh, const float* __restrict__ fc,
                             const float* __restrict__ fs)
{
    long th = blockIdx.x;
    int pos = (int)((th >> 4) % Sn);
    __half* r = qh + th * QDn;
    int i = threadIdx.x;
    const float sc = 0.07216878364870322f;   // 1/sqrt(192)
    if (i < 64) {
        r[2 * i]     = __float2half_rn(__half2float(r[2 * i]) * sc);
        r[2 * i + 1] = __float2half_rn(__half2float(r[2 * i + 1]) * sc);
    } else {
        int j = i - 64;
        float x1 = __half2float(r[128 + 2 * j]), x2 = __half2float(r[128 + 2 * j + 1]);
        float c = fc[pos * 32 + j], s = fs[pos * 32 + j];
        r[128 + 2 * j]     = __float2half_rn((x1 * c - x2 * s) * sc);
        r[128 + 2 * j + 1] = __float2half_rn((x1 * s + x2 * c) * sc);
    }
}

// ---------------- [k_nope | k_pe] concat (kvb fp16) ----------------
__global__ void kcat_h(const __half* __restrict__ kvb, const float* __restrict__ kpe,
                       __half* __restrict__ kcat)
{
    int s = blockIdx.x, z = blockIdx.y, j = threadIdx.x;
    long t = (long)(z >> 4) * Sn + s;
    __half v = (j < NOPEn) ? kvb[t * KVBP + (z & 15) * 256 + j]
                           : __float2half_rn(kpe[t * ROPEn + (j - NOPEn)]);
    kcat[((long)z * Sn + s) * QDn + j] = v;
}

// ---------------- transpose V (kvb fp16) -> vT fp16 ----------------
__global__ void vtrans_h(const __half* __restrict__ kvb, __half* __restrict__ vT)
{
    __shared__ float tsm[32][33];
    int z = blockIdx.z, zb = z >> 4, zh = z & 15;
    int kt = blockIdx.x * 32, dt = blockIdx.y * 32;
    int tx = threadIdx.x, ty = threadIdx.y;
#pragma unroll
    for (int i = 0; i < 4; i++) {
        int k = kt + ty + i * 8;
        tsm[ty + i * 8][tx] =
            __half2float(kvb[((long)zb * Sn + k) * KVBP + zh * 256 + NOPEn + dt + tx]);
    }
    __syncthreads();
#pragma unroll
    for (int i = 0; i < 4; i++) {
        int d = dt + ty + i * 8;
        vT[((long)z * VHn + d) * Sn + kt + tx] = __float2half_rn(tsm[tx][ty + i * 8]);
    }
}

// ---------------- router (reads fp16 nh) ----------------
__global__ void router_h(const __half* __restrict__ nh, const float* __restrict__ rw,
                         int* __restrict__ counts, int* __restrict__ bucket_ts,
                         float* __restrict__ bucket_gate)
{
    long t = blockIdx.x;
    int wp = threadIdx.x >> 5, lane = threadIdx.x & 31;
    const __half* xr = nh + t * DIMn;
    float s = 0.f;
    for (int d = lane; d < DIMn; d += 32) s += __half2float(xr[d]) * rw[(long)wp * DIMn + d];
    s = warpSum(s);
    __shared__ float logit[NEn];
    if (!lane) logit[wp] = s;
    __syncthreads();
    if (threadIdx.x == 0) {
        float mx = logit[0];
#pragma unroll
        for (int e = 1; e < NEn; e++) mx = fmaxf(mx, logit[e]);
        float p[NEn];
#pragma unroll
        for (int e = 0; e < NEn; e++) p[e] = expf(logit[e] - mx);
        int i0 = 0;
#pragma unroll
        for (int e = 1; e < NEn; e++) if (p[e] > p[i0]) i0 = e;
        int i1 = (i0 == 0) ? 1 : 0;
#pragma unroll
        for (int e = 0; e < NEn; e++) if (e != i0 && p[e] > p[i1]) i1 = e;
        float denom = p[i0] + p[i1];
        float g0 = p[i0] / denom, g1 = p[i1] / denom;
        int pos0 = atomicAdd(&counts[i0], 1);
        bucket_ts[i0 * Tn + pos0] = (int)(t * 2);
        bucket_gate[i0 * Tn + pos0] = g0;
        int pos1 = atomicAdd(&counts[i1], 1);
        bucket_ts[i1 * Tn + pos1] = (int)(t * 2 + 1);
        bucket_gate[i1 * Tn + pos1] = g1;
    }
}

__global__ void offsets_k(const int* __restrict__ counts, int* __restrict__ off,
                          int* __restrict__ tile_expert)
{
    for (int tl = 0; tl < MOE_TILES; tl++) tile_expert[tl] = -1;
    int o = 0;
    for (int e = 0; e < NEn; e++) {
        off[e] = o;
        int nt = (counts[e] + 127) >> 7;
        for (int i = 0; i < nt; i++) tile_expert[(o >> 7) + i] = e;
        o += nt * 128;
    }
    off[NEn] = o;
}

__global__ void compact_k(const int* __restrict__ counts, const int* __restrict__ off,
                          const int* __restrict__ bucket_ts, const float* __restrict__ bucket_gate,
                          int* __restrict__ flat_tok, int* __restrict__ tok2row,
                          float* __restrict__ tok2gate)
{
    int e = blockIdx.x;
    int cnt = counts[e], base = off[e];
    for (int i = threadIdx.x; i < cnt; i += blockDim.x) {
        int ts = bucket_ts[e * Tn + i];
        int r = base + i;
        flat_tok[r] = ts >> 1;
        tok2row[ts] = r;
        tok2gate[ts] = bucket_gate[e * Tn + i];
    }
}

__global__ void gather_h(const __half* __restrict__ nh, const int* __restrict__ flat_tok,
                         __half* __restrict__ xg)
{
    long r = blockIdx.x;
    int t = flat_tok[r];
    uint4* dst = (uint4*)(xg + r * DIMn);
    int nch = DIMn / 8;
    if (t < 0) {
        uint4 zz = make_uint4(0u, 0u, 0u, 0u);
        for (int i = threadIdx.x; i < nch; i += blockDim.x) dst[i] = zz;
    } else {
        const uint4* src = (const uint4*)(nh + (long)t * DIMn);
        for (int i = threadIdx.x; i < nch; i += blockDim.x) dst[i] = src[i];
    }
}

__global__ void silumul2_h(const __half* __restrict__ t13, __half* __restrict__ outp,
                           int inter, long rows)
{
    long h2pr = inter / 2;
    long i = (long)blockIdx.x * blockDim.x + threadIdx.x;
    if (i < rows * h2pr) {
        long r = i / h2pr, j = i - r * h2pr;
        const __half2* pa = (const __half2*)(t13 + (size_t)r * 2 * inter);
        const __half2* pb = (const __half2*)(t13 + (size_t)r * 2 * inter + inter);
        float2 x = __half22float2(pa[j]);
        float2 y = __half22float2(pb[j]);
        float s0 = x.x / (1.f + expf(-x.x));
        float s1 = x.y / (1.f + expf(-x.y));
        ((__half2*)(outp + (size_t)r * inter))[j] =
            __float22half2_rn(make_float2(s0 * y.x, s1 * y.y));
    }
}

__global__ void combine_k(const float* __restrict__ h, const float* __restrict__ sh,
                          const float* __restrict__ eo, const int* __restrict__ tok2row,
                          const float* __restrict__ tok2gate, float* __restrict__ out)
{
    long t = blockIdx.x;
    int r0 = tok2row[t * 2], r1 = tok2row[t * 2 + 1];
    float g0 = tok2gate[t * 2], g1 = tok2gate[t * 2 + 1];
    const float4* H = (const float4*)(h + t * DIMn);
    const float4* SH = (const float4*)(sh + t * DIMn);
    const float4* E0 = (const float4*)(eo + (long)r0 * DIMn);
    const float4* E1 = (const float4*)(eo + (long)r1 * DIMn);
    float4* O = (float4*)(out + t * DIMn);
    for (int i = threadIdx.x; i < DIMn / 4; i += blockDim.x) {
        float4 a = H[i], b = SH[i], c = E0[i], d = E1[i];
        float4 o;
        o.x = a.x + b.x + g0 * c.x + g1 * d.x;
        o.y = a.y + b.y + g0 * c.y + g1 * d.y;
        o.z = a.z + b.z + g0 * c.z + g1 * d.z;
        o.w = a.w + b.w + g0 * c.w + g1 * d.w;
        O[i] = o;
    }
}

// ---------------- host ----------------
#define SYM(p, s) do { void* _q = nullptr; cudaGetSymbolAddress(&_q, s); p = (decltype(p))_q; } while (0)

static void launch_hgemm(const __half* A, const __half* B, void* C, const float* addend,
                         int M, int N, int K, int lda, int ldb, int ldc,
                         long sA0, long sA1, long sB0, long sB1, long sC0, long sC1,
                         int ZH, int Z, const int* tileExpert, long wStride, int flags)
{
    dim3 grid((N + TNW - 1) / TNW, M / 128, Z);
    hgemm_k<<<grid, 256, HG_SMEM>>>(A, B, C, addend, M, N, K, lda, ldb, ldc,
        sA0, sA1, sB0, sB1, sC0, sC1, ZH, tileExpert, wStride, flags);
}

static void launch_cvt(const float* src, __half* dst, long n)
{
    long n8 = n / 8;
    cvt8_k<<<(int)((n8 + 255) / 256), 256>>>((const float4*)src, (uint4*)dst, n8);
}

extern "C" void kernel_launch(void* const* d_in, const int* in_sizes, int n_in,
                              void* d_out, int out_size)
{
    cudaFuncSetAttribute(hgemm_k, cudaFuncAttributeMaxDynamicSharedMemorySize, HG_SMEM);
    cudaFuncSetAttribute(fattn_k, cudaFuncAttributeMaxDynamicSharedMemorySize, FA_SMEM);

    const float* x       = (const float*)d_in[0];
    const float* fcos    = (const float*)d_in[1];
    const float* fsin    = (const float*)d_in[2];
    const float* attn_w  = (const float*)d_in[3];
    const float* wq      = (const float*)d_in[4];
    const float* wkv_a   = (const float*)d_in[5];
    const float* kv_w    = (const float*)d_in[6];
    const float* wkv_b   = (const float*)d_in[7];
    const float* wo      = (const float*)d_in[8];
    const float* ffn_w   = (const float*)d_in[9];
    const float* rw      = (const float*)d_in[10];
    const float* e_w1    = (const float*)d_in[11];
    const float* e_w3    = (const float*)d_in[12];
    const float* e_w2    = (const float*)d_in[13];
    const float* s_w1    = (const float*)d_in[14];
    const float* s_w3    = (const float*)d_in[15];
    const float* s_w2    = (const float*)d_in[16];
    float* out = (float*)d_out;

    float *kv, *kpe, *h, *eo, *sh;
    __half *nx_h, *ckv_h, *qh, *kvb_h, *kcat, *vT, *attn_h, *nh_h, *xg, *t13h, *t1h, *s13h, *s1h;
    __half *wq_h, *wkva_h, *wkvb_h, *wo_h, *ew13_h, *ew2_h, *sw13_h, *sw2_h;
    int *counts, *off, *tile_expert, *bucket_ts, *flat_tok, *tok2row;
    float *bucket_gate, *tok2gate;
    SYM(kv, g_kv); SYM(kpe, g_kpe);
    SYM(h, g_h); SYM(eo, g_eo); SYM(sh, g_sh);
    SYM(nx_h, g_nx_h); SYM(ckv_h, g_ckv_h); SYM(qh, g_qh); SYM(kvb_h, g_kvb_h);
    SYM(kcat, g_kcat_h); SYM(vT, g_vT_h); SYM(attn_h, g_attn_h); SYM(nh_h, g_nh_h);
    SYM(xg, g_xg_h); SYM(t13h, g_t13h); SYM(t1h, g_t1h); SYM(s13h, g_s13h); SYM(s1h, g_s1h);
    SYM(wq_h, g_wq_h); SYM(wkva_h, g_wkva_h); SYM(wkvb_h, g_wkvb_h); SYM(wo_h, g_wo_h);
    SYM(ew13_h, g_ew13_h); SYM(ew2_h, g_ew2_h); SYM(sw13_h, g_sw13_h); SYM(sw2_h, g_sw2_h);
    SYM(counts, g_counts); SYM(off, g_off); SYM(tile_expert, g_tile_expert);
    SYM(bucket_ts, g_bucket_ts); SYM(bucket_gate, g_bucket_gate);
    SYM(flat_tok, g_flat_tok); SYM(tok2row, g_tok2row); SYM(tok2gate, g_tok2gate);

    const long PE8 = (long)MINTERn * DIMn / 8;

    // 0. weight conversion (8-wide)
    launch_cvt(wq, wq_h, (long)QPROJ * DIMn);
    launch_cvt(wkv_a, wkva_h, (long)KVAP * DIMn);
    launch_cvt(wkv_b, wkvb_h, (long)KVBP * KVRn);
    launch_cvt(wo, wo_h, (long)DIMn * DIMn);
    {
        long tot8 = (long)NEn * PE8;
        int blocks = (int)((tot8 + 255) / 256);
        cvtmoe8_k<<<blocks, 256>>>((const float4*)e_w1, (uint4*)ew13_h, PE8, 2 * PE8, 0, tot8);
        cvtmoe8_k<<<blocks, 256>>>((const float4*)e_w3, (uint4*)ew13_h, PE8, 2 * PE8, PE8, tot8);
    }
    launch_cvt(e_w2, ew2_h, (long)NEn * DIMn * MINTERn);
    launch_cvt(s_w1, sw13_h, (long)SHIn * DIMn);
    launch_cvt(s_w3, sw13_h + (size_t)SHIn * DIMn, (long)SHIn * DIMn);
    launch_cvt(s_w2, sw2_h, (long)DIMn * SHIn);

    // 1. attention-input rmsnorm -> fp16
    rmsnorm_h<<<Tn, 256>>>(x, attn_w, nx_h, DIMn, DIMn, DIMn);
    // 2. q projection -> fp16 qh directly
    launch_hgemm(nx_h, wq_h, qh, nullptr, Tn, QPROJ, DIMn, DIMn, DIMn, QPROJ,
                 0, 0, 0, 0, 0, 0, 1, 1, nullptr, 0, 8);
    // 3. kv_a projection (fp32 out)
    launch_hgemm(nx_h, wkva_h, kv, nullptr, Tn, KVAP, DIMn, DIMn, DIMn, KVAP,
                 0, 0, 0, 0, 0, 0, 1, 1, nullptr, 0, 0);
    // 4. c_kv rmsnorm -> fp16
    rmsnorm_h<<<Tn, 256>>>(kv, kv_w, ckv_h, KVRn, KVAP, KVRn);
    // 5. rope k_pe
    rope_kpe_k<<<Tn, 32>>>(kv, fcos, fsin, kpe);
    // 6. kv_b projection -> fp16 kvb
    launch_hgemm(ckv_h, wkvb_h, kvb_h, nullptr, Tn, KVBP, KVRn, KVRn, KVRn, KVBP,
                 0, 0, 0, 0, 0, 0, 1, 1, nullptr, 0, 8);
    // 7. rope + scale q, fp16 in-place
    ropescale_qh<<<Tn * NHn, 96>>>(qh, fcos, fsin);
    // 8. kcat + vT (fp16 sources)
    { dim3 g(Sn, ZSn); kcat_h<<<g, QDn>>>(kvb_h, kpe, kcat); }
    { dim3 g(Sn / 32, VHn / 32, ZSn); dim3 b(32, 8); vtrans_h<<<g, b>>>(kvb_h, vT); }
    // 9-11. fused flash attention -> attn fp16
    { dim3 g(16, ZSn); fattn_k<<<g, 256, FA_SMEM>>>(qh, kcat, vT, attn_h); }
    // 12. h = x + attn @ wo^T
    launch_hgemm(attn_h, wo_h, h, x, Tn, DIMn, DIMn, DIMn, DIMn, DIMn,
                 0, 0, 0, 0, 0, 0, 1, 1, nullptr, 0, 1);
    // 13. ffn rmsnorm -> fp16
    rmsnorm_h<<<Tn, 256>>>(h, ffn_w, nh_h, DIMn, DIMn, DIMn);
    // 14. routing
    cudaMemsetAsync(counts, 0, NEn * sizeof(int), 0);
    cudaMemsetAsync(flat_tok, 0xFF, MOE_ROWS * sizeof(int), 0);
    router_h<<<Tn, 256>>>(nh_h, rw, counts, bucket_ts, bucket_gate);
    offsets_k<<<1, 1>>>(counts, off, tile_expert);
    compact_k<<<NEn, 256>>>(counts, off, bucket_ts, bucket_gate, flat_tok, tok2row, tok2gate);
    gather_h<<<MOE_ROWS, 256>>>(nh_h, flat_tok, xg);
    // 15. expert FFN (grouped, fused w1||w3)
    launch_hgemm(xg, ew13_h, t13h, nullptr, MOE_ROWS, 2 * MINTERn, DIMn,
                 DIMn, DIMn, 2 * MINTERn,
                 0, 0, 0, 0, 0, 0, 1, 1, tile_expert, 2L * MINTERn * DIMn, 8);
    {
        long n2 = (long)MOE_ROWS * MINTERn / 2;
        silumul2_h<<<(int)((n2 + 255) / 256), 256>>>(t13h, t1h, MINTERn, MOE_ROWS);
    }
    launch_hgemm(t1h, ew2_h, eo, nullptr, MOE_ROWS, DIMn, MINTERn, MINTERn, MINTERn, DIMn,
                 0, 0, 0, 0, 0, 0, 1, 1, tile_expert, (long)DIMn * MINTERn, 0);
    // 16. shared FFN (fused w1||w3)
    launch_hgemm(nh_h, sw13_h, s13h, nullptr, Tn, 2 * SHIn, DIMn, DIMn, DIMn, 2 * SHIn,
                 0, 0, 0, 0, 0, 0, 1, 1, nullptr, 0, 8);
    {
        long n2 = (long)Tn * SHIn / 2;
        silumul2_h<<<(int)((n2 + 255) / 256), 256>>>(s13h, s1h, SHIn, Tn);
    }
    launch_hgemm(s1h, sw2_h, sh, nullptr, Tn, DIMn, SHIn, SHIn, SHIn, DIMn,
                 0, 0, 0, 0, 0, 0, 1, 1, nullptr, 0, 0);
    // 17. combine
    combine_k<<<Tn, 256>>>(h, sh, eo, tok2row, tok2gate, out);
}

// round 14
// speedup vs baseline: 1.4865x; 1.4865x over previous
#include <cuda_runtime.h>
#include <cuda_fp16.h>
#include <math.h>
#include <stdint.h>
#include <string.h>

// ---------------- problem constants ----------------
#define Tn     4096
#define Sn     2048
#define DIMn   2048
#define NHn    16
#define NOPEn  128
#define ROPEn  64
#define QDn    192
#define VHn    128
#define KVRn   512
#define NEn    8
#define MINTERn 1408
#define SHIn   2816
#define QPROJ  3072
#define KVAP   576
#define KVBP   4096
#define MOE_ROWS 9216
#define MOE_TILES 72
#define ZSn    32

// ---------------- fp32 scratch ----------------
__device__ float g_q[(size_t)Tn*QPROJ];
__device__ float g_kv[(size_t)Tn*KVAP];
__device__ float g_kpe[(size_t)Tn*ROPEn];
__device__ float g_kvb[(size_t)Tn*KVBP];
__device__ float g_h[(size_t)Tn*DIMn];
__device__ float g_eo[(size_t)MOE_ROWS*DIMn];
__device__ float g_sh[(size_t)Tn*DIMn];
__device__ int   g_counts[NEn];
__device__ int   g_off[NEn+1];
__device__ int   g_tile_expert[MOE_TILES];
__device__ int   g_bucket_ts[NEn*Tn];
__device__ float g_bucket_gate[NEn*Tn];
__device__ int   g_flat_tok[MOE_ROWS];
__device__ int   g_tok2row[Tn*2];
__device__ float g_tok2gate[Tn*2];
// ---------------- fp16 scratch ----------------
__device__ __half g_nx_h[(size_t)Tn*DIMn];
__device__ __half g_ckv_h[(size_t)Tn*KVRn];
__device__ __half g_qh[(size_t)Tn*QPROJ];
__device__ __half g_kcat_h[(size_t)ZSn*Sn*QDn];
__device__ __half g_vT_h[(size_t)ZSn*VHn*Sn];
__device__ __half g_attn_h[(size_t)Tn*DIMn];
__device__ __half g_nh_h[(size_t)Tn*DIMn];
__device__ __half g_xg_h[(size_t)MOE_ROWS*DIMn];
__device__ __half g_t13h[(size_t)MOE_ROWS*2*MINTERn];
__device__ __half g_t1h[(size_t)MOE_ROWS*MINTERn];
__device__ __half g_s13h[(size_t)Tn*2*SHIn];
__device__ __half g_s1h[(size_t)Tn*SHIn];
// fp16 weight copies
__device__ __half g_wq_h[(size_t)QPROJ*DIMn];
__device__ __half g_wkva_h[(size_t)KVAP*DIMn];
__device__ __half g_wkvb_h[(size_t)KVBP*KVRn];
__device__ __half g_wo_h[(size_t)DIMn*DIMn];
__device__ __half g_ew13_h[(size_t)NEn*2*MINTERn*DIMn];
__device__ __half g_ew2_h[(size_t)NEn*DIMn*MINTERn];
__device__ __half g_sw13_h[(size_t)2*SHIn*DIMn];
__device__ __half g_sw2_h[(size_t)DIMn*SHIn];

// ---------------- helpers ----------------
__device__ __forceinline__ uint32_t h2u(__half2 h) {
    uint32_t u; memcpy(&u, &h, 4); return u;
}
__device__ __forceinline__ void mma16(float* c, const uint32_t* a, const uint32_t* b) {
    asm volatile("mma.sync.aligned.m16n8k16.row.col.f32.f16.f16.f32 "
        "{%0,%1,%2,%3}, {%4,%5,%6,%7}, {%8,%9}, {%0,%1,%2,%3};"
        : "+f"(c[0]), "+f"(c[1]), "+f"(c[2]), "+f"(c[3])
        : "r"(a[0]), "r"(a[1]), "r"(a[2]), "r"(a[3]), "r"(b[0]), "r"(b[1]));
}
__device__ __forceinline__ void ldsm4(uint32_t* r, uint32_t addr) {
    asm volatile("ldmatrix.sync.aligned.m8n8.x4.shared.b16 {%0,%1,%2,%3}, [%4];"
        : "=r"(r[0]), "=r"(r[1]), "=r"(r[2]), "=r"(r[3]) : "r"(addr));
}
__device__ __forceinline__ void cpasync16(uint32_t dst, const void* src, int sz) {
    asm volatile("cp.async.cg.shared.global [%0], [%1], 16, %2;"
                 :: "r"(dst), "l"(src), "r"(sz));
}
__device__ __forceinline__ void cpcommit() { asm volatile("cp.async.commit_group;"); }
__device__ __forceinline__ void cpwait1() { asm volatile("cp.async.wait_group 1;"); }
__device__ __forceinline__ void cpwait2() { asm volatile("cp.async.wait_group 2;"); }

// ---------------- fp16 tensor GEMM, 128x128 CTA, 4-stage, 2 CTAs/SM ----------------
// flags: 1 add addend(fp32 out), 8 fp16 out
#define LDPH 20
#define AROWB (LDPH*4)               // 80 bytes
#define TNW 128
#define NTT 4
#define ABY (128*AROWB)
#define STG (2*ABY)
#define HG_SMEM (4*STG)              // 81920 B

__global__ __launch_bounds__(256, 2) void hgemm_k(
    const __half* __restrict__ A, const __half* __restrict__ B, void* __restrict__ Cv,
    const float* __restrict__ addend,
    int M, int N, int K, int lda, int ldb, int ldc,
    long sA0, long sA1, long sB0, long sB1, long sC0, long sC1, int ZH,
    const int* __restrict__ tileExpert, long wStride, int flags)
{
    int bx = blockIdx.x, by = blockIdx.y, z = blockIdx.z;
    if (tileExpert) { int te = tileExpert[by]; if (te < 0) return; B += (long)te * wStride; }
    int zb = z / ZH, zh = z - zb * ZH;
    A += zb * sA0 + (long)zh * sA1;
    B += zb * sB0 + (long)zh * sB1;
    int NT = K >> 5;

    extern __shared__ char smraw[];
    uint32_t sb = (uint32_t)__cvta_generic_to_shared(smraw);

    int tid = threadIdx.x;
    int wid = tid >> 5, lane = tid & 31;
    int wy = wid & 1, wx = wid >> 1;

    int grp = lane >> 3, lrow = lane & 7;
    uint32_t aoff = (uint32_t)((wy * 64 + (grp & 1) * 8 + lrow) * AROWB + (grp >> 1) * 16);
    uint32_t boff = (uint32_t)((wx * 32 + (grp >> 1) * 8 + lrow) * AROWB + (grp & 1) * 16);

    int ar0 = tid >> 2, ac0 = tid & 3;
    int bsz[2];
#pragma unroll
    for (int ch = 0; ch < 2; ch++) {
        int row = ar0 + ch * 64;
        bsz[ch] = ((bx * TNW + row) < N) ? 16 : 0;
    }
    const __half* bsrc0 = B;

    auto issue = [&](int s, int k0) {
        uint32_t Ab = sb + s * STG;
        uint32_t Bb = Ab + ABY;
#pragma unroll
        for (int ch = 0; ch < 2; ch++) {
            int row = ar0 + ch * 64;
            const __half* src = A + (long)(by * 128 + row) * lda + k0 + ac0 * 8;
            cpasync16(Ab + row * AROWB + ac0 * 16, src, 16);
        }
#pragma unroll
        for (int ch = 0; ch < 2; ch++) {
            int row = ar0 + ch * 64;
            const __half* src = bsz[ch] ? (B + (long)(bx * TNW + row) * ldb + k0 + ac0 * 8) : bsrc0;
            cpasync16(Bb + row * AROWB + ac0 * 16, src, bsz[ch]);
        }
    };

#pragma unroll
    for (int s = 0; s < 3; s++) {
        if (s < NT) issue(s, s * 32);
        cpcommit();
    }

    float acc[4][NTT][4];
#pragma unroll
    for (int mt = 0; mt < 4; mt++)
#pragma unroll
        for (int nt = 0; nt < NTT; nt++)
#pragma unroll
            for (int i = 0; i < 4; i++) acc[mt][nt][i] = 0.f;

    for (int it = 0; it < NT; ++it) {
        cpwait2();
        __syncthreads();
        if (it + 3 < NT) issue((it + 3) & 3, (it + 3) * 32);
        cpcommit();

        int st = it & 3;
        uint32_t Abase = sb + st * STG + aoff;
        uint32_t Bbase = sb + st * STG + ABY + boff;
#pragma unroll
        for (int ks = 0; ks < 2; ks++) {
            uint32_t af[4][4], bf[NTT][2];
#pragma unroll
            for (int mt = 0; mt < 4; mt++)
                ldsm4(af[mt], Abase + mt * (16 * AROWB) + ks * 32);
#pragma unroll
            for (int p = 0; p < NTT / 2; p++) {
                uint32_t r[4];
                ldsm4(r, Bbase + p * (16 * AROWB) + ks * 32);
                bf[2 * p][0] = r[0]; bf[2 * p][1] = r[1];
                bf[2 * p + 1][0] = r[2]; bf[2 * p + 1][1] = r[3];
            }
#pragma unroll
            for (int mt = 0; mt < 4; mt++)
#pragma unroll
                for (int nt = 0; nt < NTT; nt++)
                    mma16(acc[mt][nt], af[mt], bf[nt]);
        }
        __syncthreads();
    }

    bool doadd = (flags & 1) != 0;
    bool outh = (flags & 8) != 0;
    float* Cf = (float*)Cv + zb * sC0 + (long)zh * sC1;
    __half* Ch = (__half*)Cv + zb * sC0 + (long)zh * sC1;
    const float* Af = addend ? (addend + zb * sC0 + (long)zh * sC1) : nullptr;
    int elr = lane >> 2, elk = lane & 3;
#pragma unroll
    for (int mt = 0; mt < 4; mt++) {
        int m0 = by * 128 + wy * 64 + mt * 16 + elr;
#pragma unroll
        for (int nt = 0; nt < NTT; nt++) {
            int c0 = bx * TNW + wx * 32 + nt * 8 + 2 * elk;
            if (c0 < N) {
                float2 v0 = make_float2(acc[mt][nt][0], acc[mt][nt][1]);
                float2 v1 = make_float2(acc[mt][nt][2], acc[mt][nt][3]);
                if (outh) {
                    *(__half2*)(Ch + (long)m0 * ldc + c0) = __float22half2_rn(v0);
                    *(__half2*)(Ch + (long)(m0 + 8) * ldc + c0) = __float22half2_rn(v1);
                } else {
                    if (doadd) {
                        float2 o0 = *(const float2*)(Af + (long)m0 * ldc + c0);
                        float2 o1 = *(const float2*)(Af + (long)(m0 + 8) * ldc + c0);
                        v0.x += o0.x; v0.y += o0.y; v1.x += o1.x; v1.y += o1.y;
                    }
                    *(float2*)(Cf + (long)m0 * ldc + c0) = v0;
                    *(float2*)(Cf + (long)(m0 + 8) * ldc + c0) = v1;
                }
            }
        }
    }
}

// ---------------- fused flash attention ----------------
#define QROWB 400
#define VROWB 272
#define FA_QS 0
#define FA_KS (128*QROWB)
#define FA_VS (2*128*QROWB)
#define FA_PS (FA_VS + 128*VROWB)
#define FA_RA (FA_PS + 128*VROWB)
#define FA_RB (FA_RA + 2048)
#define FA_SMEM (FA_RB + 2048)

__global__ __launch_bounds__(256) void fattn_k(
    const __half* __restrict__ qh, const __half* __restrict__ kcat,
    const __half* __restrict__ vT, __half* __restrict__ attn)
{
    int by = (int)gridDim.x - 1 - blockIdx.x;
    int z = blockIdx.y;
    int zb = z >> 4, zh = z & 15;

    extern __shared__ char smraw[];
    uint32_t sb = (uint32_t)__cvta_generic_to_shared(smraw);
    float* rowA = (float*)(smraw + FA_RA);
    float* rowB = (float*)(smraw + FA_RB);

    int tid = threadIdx.x;
    int wid = tid >> 5, lane = tid & 31;
    int wy = wid & 1, wx = wid >> 1;
    int grp = lane >> 3, lrow = lane & 7;
    int elr = lane >> 2, elk = lane & 3;

    uint32_t aoffQ = (uint32_t)((wy * 64 + (grp & 1) * 8 + lrow) * QROWB + (grp >> 1) * 16);
    uint32_t boffK = (uint32_t)((wx * 32 + (grp >> 1) * 8 + lrow) * QROWB + (grp & 1) * 16);
    uint32_t aoffP = (uint32_t)((wy * 64 + (grp & 1) * 8 + lrow) * VROWB + (grp >> 1) * 16);
    uint32_t boffV = (uint32_t)((wx * 32 + (grp >> 1) * 8 + lrow) * VROWB + (grp & 1) * 16);

    const __half* Qg = qh + ((long)zb * Sn + (long)by * 128) * QPROJ + zh * QDn;
    const __half* Kg = kcat + (long)z * Sn * QDn;
    const __half* Vg = vT + (long)z * VHn * Sn;

    auto issueK = [&](int kb) {
#pragma unroll
        for (int ch = 0; ch < 12; ch++) {
            int idx = tid + ch * 256;
            int row = idx / 24, cq = idx - row * 24;
            cpasync16(sb + FA_KS + row * QROWB + cq * 16,
                      Kg + ((long)kb * 128 + row) * QDn + cq * 8, 16);
        }
    };
    auto issueV = [&](int kb) {
#pragma unroll
        for (int ch = 0; ch < 8; ch++) {
            int idx = tid + ch * 256;
            int row = idx >> 4, cq = idx & 15;
            cpasync16(sb + FA_VS + row * VROWB + cq * 16,
                      Vg + (long)row * Sn + kb * 128 + cq * 8, 16);
        }
    };

#pragma unroll
    for (int ch = 0; ch < 12; ch++) {
        int idx = tid + ch * 256;
        int row = idx / 24, cq = idx - row * 24;
        cpasync16(sb + FA_QS + row * QROWB + cq * 16, Qg + (long)row * QPROJ + cq * 8, 16);
    }
    cpcommit();
    issueK(0); cpcommit();
    issueV(0); cpcommit();

    float accO[4][4][4];
    float mold[4][2], lrun[4][2];
#pragma unroll
    for (int mt = 0; mt < 4; mt++) {
#pragma unroll
        for (int nt = 0; nt < 4; nt++)
#pragma unroll
            for (int i = 0; i < 4; i++) accO[mt][nt][i] = 0.f;
        mold[mt][0] = -3.4e38f; mold[mt][1] = -3.4e38f;
        lrun[mt][0] = 0.f; lrun[mt][1] = 0.f;
    }

    for (int kb = 0; kb <= by; kb++) {
        cpwait1();
        __syncthreads();

        float accS[4][4][4];
#pragma unroll
        for (int mt = 0; mt < 4; mt++)
#pragma unroll
            for (int nt = 0; nt < 4; nt++)
#pragma unroll
                for (int i = 0; i < 4; i++) accS[mt][nt][i] = 0.f;
#pragma unroll
        for (int ks = 0; ks < 12; ks++) {
            uint32_t af[4][4], bf[4][2];
#pragma unroll
            for (int mt = 0; mt < 4; mt++)
                ldsm4(af[mt], sb + FA_QS + aoffQ + mt * (16 * QROWB) + ks * 32);
#pragma unroll
            for (int p = 0; p < 2; p++) {
                uint32_t r[4];
                ldsm4(r, sb + FA_KS + boffK + p * (16 * QROWB) + ks * 32);
                bf[2 * p][0] = r[0]; bf[2 * p][1] = r[1];
                bf[2 * p + 1][0] = r[2]; bf[2 * p + 1][1] = r[3];
            }
#pragma unroll
            for (int mt = 0; mt < 4; mt++)
#pragma unroll
                for (int nt = 0; nt < 4; nt++)
                    mma16(accS[mt][nt], af[mt], bf[nt]);
        }
        if (kb == by) {
#pragma unroll
            for (int mt = 0; mt < 4; mt++) {
                int r0 = wy * 64 + mt * 16 + elr, r1 = r0 + 8;
#pragma unroll
                for (int nt = 0; nt < 4; nt++) {
                    int c = wx * 32 + nt * 8 + 2 * elk;
                    if (c > r0)     accS[mt][nt][0] = -3.4e38f;
                    if (c + 1 > r0) accS[mt][nt][1] = -3.4e38f;
                    if (c > r1)     accS[mt][nt][2] = -3.4e38f;
                    if (c + 1 > r1) accS[mt][nt][3] = -3.4e38f;
                }
            }
        }
        float lmax[4][2];
#pragma unroll
        for (int mt = 0; mt < 4; mt++) {
            float a = -3.4e38f, b = -3.4e38f;
#pragma unroll
            for (int nt = 0; nt < 4; nt++) {
                a = fmaxf(a, fmaxf(accS[mt][nt][0], accS[mt][nt][1]));
                b = fmaxf(b, fmaxf(accS[mt][nt][2], accS[mt][nt][3]));
            }
            lmax[mt][0] = a; lmax[mt][1] = b;
        }
#pragma unroll
        for (int off = 1; off <= 2; off <<= 1)
#pragma unroll
            for (int mt = 0; mt < 4; mt++) {
                lmax[mt][0] = fmaxf(lmax[mt][0], __shfl_xor_sync(0xffffffffu, lmax[mt][0], off));
                lmax[mt][1] = fmaxf(lmax[mt][1], __shfl_xor_sync(0xffffffffu, lmax[mt][1], off));
            }
        if (elk == 0) {
#pragma unroll
            for (int mt = 0; mt < 4; mt++) {
                int m = wy * 64 + mt * 16 + elr;
                rowA[wx * 128 + m] = lmax[mt][0];
                rowA[wx * 128 + m + 8] = lmax[mt][1];
            }
        }
        __syncthreads();
        if (kb + 1 <= by) issueK(kb + 1);
        cpcommit();

        float mnew[4][2];
#pragma unroll
        for (int mt = 0; mt < 4; mt++) {
#pragma unroll
            for (int hf = 0; hf < 2; hf++) {
                int m = wy * 64 + mt * 16 + elr + hf * 8;
                float v = fmaxf(fmaxf(rowA[m], rowA[128 + m]),
                                fmaxf(rowA[256 + m], rowA[384 + m]));
                mnew[mt][hf] = fmaxf(mold[mt][hf], v);
            }
        }
        float lsum[4][2];
#pragma unroll
        for (int mt = 0; mt < 4; mt++) { lsum[mt][0] = 0.f; lsum[mt][1] = 0.f; }
#pragma unroll
        for (int mt = 0; mt < 4; mt++) {
            int r0 = wy * 64 + mt * 16 + elr;
#pragma unroll
            for (int nt = 0; nt < 4; nt++) {
                int c = wx * 32 + nt * 8 + 2 * elk;
                float p0 = __expf(accS[mt][nt][0] - mnew[mt][0]);
                float p1 = __expf(accS[mt][nt][1] - mnew[mt][0]);
                float p2 = __expf(accS[mt][nt][2] - mnew[mt][1]);
                float p3 = __expf(accS[mt][nt][3] - mnew[mt][1]);
                lsum[mt][0] += p0 + p1;
                lsum[mt][1] += p2 + p3;
                *(__half2*)(smraw + FA_PS + r0 * VROWB + c * 2) =
                    __float22half2_rn(make_float2(p0, p1));
                *(__half2*)(smraw + FA_PS + (r0 + 8) * VROWB + c * 2) =
                    __float22half2_rn(make_float2(p2, p3));
            }
        }
#pragma unroll
        for (int off = 1; off <= 2; off <<= 1)
#pragma unroll
            for (int mt = 0; mt < 4; mt++) {
                lsum[mt][0] += __shfl_xor_sync(0xffffffffu, lsum[mt][0], off);
                lsum[mt][1] += __shfl_xor_sync(0xffffffffu, lsum[mt][1], off);
            }
        if (elk == 0) {
#pragma unroll
            for (int mt = 0; mt < 4; mt++) {
                int m = wy * 64 + mt * 16 + elr;
                rowB[wx * 128 + m] = lsum[mt][0];
                rowB[wx * 128 + m + 8] = lsum[mt][1];
            }
        }
        cpwait1();
        __syncthreads();

#pragma unroll
        for (int mt = 0; mt < 4; mt++) {
#pragma unroll
            for (int hf = 0; hf < 2; hf++) {
                int m = wy * 64 + mt * 16 + elr + hf * 8;
                float rs = rowB[m] + rowB[128 + m] + rowB[256 + m] + rowB[384 + m];
                float fsc = __expf(mold[mt][hf] - mnew[mt][hf]);
                lrun[mt][hf] = lrun[mt][hf] * fsc + rs;
                mold[mt][hf] = mnew[mt][hf];
#pragma unroll
                for (int nt = 0; nt < 4; nt++) {
                    accO[mt][nt][hf * 2 + 0] *= fsc;
                    accO[mt][nt][hf * 2 + 1] *= fsc;
                }
            }
        }
#pragma unroll
        for (int ks = 0; ks < 8; ks++) {
            uint32_t af[4][4], bf[4][2];
#pragma unroll
            for (int mt = 0; mt < 4; mt++)
                ldsm4(af[mt], sb + FA_PS + aoffP + mt * (16 * VROWB) + ks * 32);
#pragma unroll
            for (int p = 0; p < 2; p++) {
                uint32_t r[4];
                ldsm4(r, sb + FA_VS + boffV + p * (16 * VROWB) + ks * 32);
                bf[2 * p][0] = r[0]; bf[2 * p][1] = r[1];
                bf[2 * p + 1][0] = r[2]; bf[2 * p + 1][1] = r[3];
            }
#pragma unroll
            for (int mt = 0; mt < 4; mt++)
#pragma unroll
                for (int nt = 0; nt < 4; nt++)
                    mma16(accO[mt][nt], af[mt], bf[nt]);
        }
        __syncthreads();
        if (kb + 1 <= by) issueV(kb + 1);
        cpcommit();
    }

    __half* Og = attn + (long)zb * Sn * DIMn + zh * VHn;
#pragma unroll
    for (int mt = 0; mt < 4; mt++) {
        float i0 = 1.f / lrun[mt][0], i1 = 1.f / lrun[mt][1];
        int m = by * 128 + wy * 64 + mt * 16 + elr;
#pragma unroll
        for (int nt = 0; nt < 4; nt++) {
            int d = wx * 32 + nt * 8 + 2 * elk;
            *(__half2*)(Og + (long)m * DIMn + d) =
                __float22half2_rn(make_float2(accO[mt][nt][0] * i0, accO[mt][nt][1] * i0));
            *(__half2*)(Og + (long)(m + 8) * DIMn + d) =
                __float22half2_rn(make_float2(accO[mt][nt][2] * i1, accO[mt][nt][3] * i1));
        }
    }
}

// ---------------- coalesced weight fp32 -> fp16 (4 floats / thread) ----------------
__global__ void cvt4_k(const float4* __restrict__ src, uint2* __restrict__ dst, long n4)
{
    long i = (long)blockIdx.x * blockDim.x + threadIdx.x;
    if (i < n4) {
        float4 a = src[i];
        uint2 o;
        o.x = h2u(__floats2half2_rn(a.x, a.y));
        o.y = h2u(__floats2half2_rn(a.z, a.w));
        dst[i] = o;
    }
}
__global__ void cvtmoe4_k(const float4* __restrict__ src, uint2* __restrict__ dst,
                          long perExp4, long dstStride4, long dstOff4, long total4)
{
    long i = (long)blockIdx.x * blockDim.x + threadIdx.x;
    if (i < total4) {
        long e = i / perExp4, r = i - e * perExp4;
        float4 a = src[i];
        uint2 o;
        o.x = h2u(__floats2half2_rn(a.x, a.y));
        o.y = h2u(__floats2half2_rn(a.z, a.w));
        dst[e * dstStride4 + dstOff4 + r] = o;
    }
}

// ---------------- reductions ----------------
__device__ __forceinline__ float warpSum(float v) {
#pragma unroll
    for (int o = 16; o; o >>= 1) v += __shfl_xor_sync(0xffffffffu, v, o);
    return v;
}

// ---------------- rmsnorm: fp32 in -> fp16 out ----------------
__global__ void rmsnorm_h(const float* __restrict__ x, const float* __restrict__ w,
                          __half* __restrict__ y, int D, int ldx, int ldy)
{
    long t = blockIdx.x;
    const float* xr = x + t * ldx;
    __half* yr = y + t * ldy;
    float s = 0.f;
    for (int d = threadIdx.x; d < D; d += blockDim.x) { float v = xr[d]; s += v * v; }
    __shared__ float sh[32];
    __shared__ float bc;
    s = warpSum(s);
    int lane = threadIdx.x & 31, wp = threadIdx.x >> 5;
    if (!lane) sh[wp] = s;
    __syncthreads();
    if (threadIdx.x < 32) {
        float r = (threadIdx.x < (blockDim.x >> 5)) ? sh[threadIdx.x] : 0.f;
        r = warpSum(r);
        if (!threadIdx.x) bc = rsqrtf(r / D + 1e-6f);
    }
    __syncthreads();
    float sc = bc;
    for (int d = threadIdx.x; d < D; d += blockDim.x)
        yr[d] = __float2half_rn(xr[d] * sc * w[d]);
}

// ---------------- rope on k_pe (fp32) ----------------
__global__ void rope_kpe_k(const float* __restrict__ kv, const float* __restrict__ fc,
                           const float* __restrict__ fs, float* __restrict__ kpe)
{
    long t = blockIdx.x;
    int j = threadIdx.x;
    int pos = (int)(t % Sn);
    float x1 = kv[t * KVAP + KVRn + 2 * j];
    float x2 = kv[t * KVAP + KVRn + 2 * j + 1];
    float c = fc[pos * 32 + j], s = fs[pos * 32 + j];
    kpe[t * ROPEn + 2 * j]     = x1 * c - x2 * s;
    kpe[t * ROPEn + 2 * j + 1] = x1 * s + x2 * c;
}

// ---------------- rope + scale on q: fp32 in -> fp16 out ----------------
__global__ void ropescale_qh(const float* __restrict__ q, const float* __restrict__ fc,
                             const float* __restrict__ fs, __half* __restrict__ qh)
{
    long th = blockIdx.x;
    int pos = (int)((th >> 4) % Sn);
    const float* r = q + th * QDn;
    __half* o = qh + th * QDn;
    int i = threadIdx.x;
    const float sc = 0.07216878364870322f;   // 1/sqrt(192)
    if (i < 64) {
        o[2 * i]     = __float2half_rn(r[2 * i] * sc);
        o[2 * i + 1] = __float2half_rn(r[2 * i + 1] * sc);
    } else {
        int j = i - 64;
        float x1 = r[128 + 2 * j], x2 = r[128 + 2 * j + 1];
        float c = fc[pos * 32 + j], s = fs[pos * 32 + j];
        o[128 + 2 * j]     = __float2half_rn((x1 * c - x2 * s) * sc);
        o[128 + 2 * j + 1] = __float2half_rn((x1 * s + x2 * c) * sc);
    }
}

// ---------------- [k_nope | k_pe] concat -> fp16 ----------------
__global__ void kcat_h(const float* __restrict__ kvb, const float* __restrict__ kpe,
                       __half* __restrict__ kcat)
{
    int s = blockIdx.x, z = blockIdx.y, j = threadIdx.x;
    long t = (long)(z >> 4) * Sn + s;
    float v = (j < NOPEn) ? kvb[t * KVBP + (z & 15) * 256 + j]
                          : kpe[t * ROPEn + (j - NOPEn)];
    kcat[((long)z * Sn + s) * QDn + j] = __float2half_rn(v);
}

// ---------------- transpose V -> vT fp16 ----------------
__global__ void vtrans_h(const float* __restrict__ kvb, __half* __restrict__ vT)
{
    __shared__ float tsm[32][33];
    int z = blockIdx.z, zb = z >> 4, zh = z & 15;
    int kt = blockIdx.x * 32, dt = blockIdx.y * 32;
    int tx = threadIdx.x, ty = threadIdx.y;
#pragma unroll
    for (int i = 0; i < 4; i++) {
        int k = kt + ty + i * 8;
        tsm[ty + i * 8][tx] = kvb[((long)zb * Sn + k) * KVBP + zh * 256 + NOPEn + dt + tx];
    }
    __syncthreads();
#pragma unroll
    for (int i = 0; i < 4; i++) {
        int d = dt + ty + i * 8;
        vT[((long)z * VHn + d) * Sn + kt + tx] = __float2half_rn(tsm[tx][ty + i * 8]);
    }
}

// ---------------- router (reads fp16 nh) ----------------
__global__ void router_h(const __half* __restrict__ nh, const float* __restrict__ rw,
                         int* __restrict__ counts, int* __restrict__ bucket_ts,
                         float* __restrict__ bucket_gate)
{
    long t = blockIdx.x;
    int wp = threadIdx.x >> 5, lane = threadIdx.x & 31;
    const __half* xr = nh + t * DIMn;
    float s = 0.f;
    for (int d = lane; d < DIMn; d += 32) s += __half2float(xr[d]) * rw[(long)wp * DIMn + d];
    s = warpSum(s);
    __shared__ float logit[NEn];
    if (!lane) logit[wp] = s;
    __syncthreads();
    if (threadIdx.x == 0) {
        float mx = logit[0];
#pragma unroll
        for (int e = 1; e < NEn; e++) mx = fmaxf(mx, logit[e]);
        float p[NEn];
#pragma unroll
        for (int e = 0; e < NEn; e++) p[e] = expf(logit[e] - mx);
        int i0 = 0;
#pragma unroll
        for (int e = 1; e < NEn; e++) if (p[e] > p[i0]) i0 = e;
        int i1 = (i0 == 0) ? 1 : 0;
#pragma unroll
        for (int e = 0; e < NEn; e++) if (e != i0 && p[e] > p[i1]) i1 = e;
        float denom = p[i0] + p[i1];
        float g0 = p[i0] / denom, g1 = p[i1] / denom;
        int pos0 = atomicAdd(&counts[i0], 1);
        bucket_ts[i0 * Tn + pos0] = (int)(t * 2);
        bucket_gate[i0 * Tn + pos0] = g0;
        int pos1 = atomicAdd(&counts[i1], 1);
        bucket_ts[i1 * Tn + pos1] = (int)(t * 2 + 1);
        bucket_gate[i1 * Tn + pos1] = g1;
    }
}

__global__ void offsets_k(const int* __restrict__ counts, int* __restrict__ off,
                          int* __restrict__ tile_expert)
{
    for (int tl = 0; tl < MOE_TILES; tl++) tile_expert[tl] = -1;
    int o = 0;
    for (int e = 0; e < NEn; e++) {
        off[e] = o;
        int nt = (counts[e] + 127) >> 7;
        for (int i = 0; i < nt; i++) tile_expert[(o >> 7) + i] = e;
        o += nt * 128;
    }
    off[NEn] = o;
}

__global__ void compact_k(const int* __restrict__ counts, const int* __restrict__ off,
                          const int* __restrict__ bucket_ts, const float* __restrict__ bucket_gate,
                          int* __restrict__ flat_tok, int* __restrict__ tok2row,
                          float* __restrict__ tok2gate)
{
    int e = blockIdx.x;
    int cnt = counts[e], base = off[e];
    for (int i = threadIdx.x; i < cnt; i += blockDim.x) {
        int ts = bucket_ts[e * Tn + i];
        int r = base + i;
        flat_tok[r] = ts >> 1;
        tok2row[ts] = r;
        tok2gate[ts] = bucket_gate[e * Tn + i];
    }
}

__global__ void gather_h(const __half* __restrict__ nh, const int* __restrict__ flat_tok,
                         __half* __restrict__ xg)
{
    long r = blockIdx.x;
    int t = flat_tok[r];
    uint4* dst = (uint4*)(xg + r * DIMn);
    int nch = DIMn / 8;
    if (t < 0) {
        uint4 zz = make_uint4(0u, 0u, 0u, 0u);
        for (int i = threadIdx.x; i < nch; i += blockDim.x) dst[i] = zz;
    } else {
        const uint4* src = (const uint4*)(nh + (long)t * DIMn);
        for (int i = threadIdx.x; i < nch; i += blockDim.x) dst[i] = src[i];
    }
}

__global__ void silumul2_h(const __half* __restrict__ t13, __half* __restrict__ outp,
                           int inter, long rows)
{
    long h2pr = inter / 2;
    long i = (long)blockIdx.x * blockDim.x + threadIdx.x;
    if (i < rows * h2pr) {
        long r = i / h2pr, j = i - r * h2pr;
        const __half2* pa = (const __half2*)(t13 + (size_t)r * 2 * inter);
        const __half2* pb = (const __half2*)(t13 + (size_t)r * 2 * inter + inter);
        float2 x = __half22float2(pa[j]);
        float2 y = __half22float2(pb[j]);
        float s0 = x.x / (1.f + expf(-x.x));
        float s1 = x.y / (1.f + expf(-x.y));
        ((__half2*)(outp + (size_t)r * inter))[j] =
            __float22half2_rn(make_float2(s0 * y.x, s1 * y.y));
    }
}

__global__ void combine_k(const float* __restrict__ h, const float* __restrict__ sh,
                          const float* __restrict__ eo, const int* __restrict__ tok2row,
                          const float* __restrict__ tok2gate, float* __restrict__ out)
{
    long t = blockIdx.x;
    int r0 = tok2row[t * 2], r1 = tok2row[t * 2 + 1];
    float g0 = tok2gate[t * 2], g1 = tok2gate[t * 2 + 1];
    const float4* H = (const float4*)(h + t * DIMn);
    const float4* SH = (const float4*)(sh + t * DIMn);
    const float4* E0 = (const float4*)(eo + (long)r0 * DIMn);
    const float4* E1 = (const float4*)(eo + (long)r1 * DIMn);
    float4* O = (float4*)(out + t * DIMn);
    for (int i = threadIdx.x; i < DIMn / 4; i += blockDim.x) {
        float4 a = H[i], b = SH[i], c = E0[i], d = E1[i];
        float4 o;
        o.x = a.x + b.x + g0 * c.x + g1 * d.x;
        o.y = a.y + b.y + g0 * c.y + g1 * d.y;
        o.z = a.z + b.z + g0 * c.z + g1 * d.z;
        o.w = a.w + b.w + g0 * c.w + g1 * d.w;
        O[i] = o;
    }
}

// ---------------- host ----------------
#define SYM(p, s) do { void* _q = nullptr; cudaGetSymbolAddress(&_q, s); p = (decltype(p))_q; } while (0)

static void launch_hgemm(const __half* A, const __half* B, void* C, const float* addend,
                         int M, int N, int K, int lda, int ldb, int ldc,
                         long sA0, long sA1, long sB0, long sB1, long sC0, long sC1,
                         int ZH, int Z, const int* tileExpert, long wStride, int flags)
{
    dim3 grid((N + TNW - 1) / TNW, M / 128, Z);
    hgemm_k<<<grid, 256, HG_SMEM>>>(A, B, C, addend, M, N, K, lda, ldb, ldc,
        sA0, sA1, sB0, sB1, sC0, sC1, ZH, tileExpert, wStride, flags);
}

static void launch_cvt(const float* src, __half* dst, long n)
{
    long n4 = n / 4;
    cvt4_k<<<(int)((n4 + 255) / 256), 256>>>((const float4*)src, (uint2*)dst, n4);
}

extern "C" void kernel_launch(void* const* d_in, const int* in_sizes, int n_in,
                              void* d_out, int out_size)
{
    cudaFuncSetAttribute(hgemm_k, cudaFuncAttributeMaxDynamicSharedMemorySize, HG_SMEM);
    cudaFuncSetAttribute(fattn_k, cudaFuncAttributeMaxDynamicSharedMemorySize, FA_SMEM);

    const float* x       = (const float*)d_in[0];
    const float* fcos    = (const float*)d_in[1];
    const float* fsin    = (const float*)d_in[2];
    const float* attn_w  = (const float*)d_in[3];
    const float* wq      = (const float*)d_in[4];
    const float* wkv_a   = (const float*)d_in[5];
    const float* kv_w    = (const float*)d_in[6];
    const float* wkv_b   = (const float*)d_in[7];
    const float* wo      = (const float*)d_in[8];
    const float* ffn_w   = (const float*)d_in[9];
    const float* rw      = (const float*)d_in[10];
    const float* e_w1    = (const float*)d_in[11];
    const float* e_w3    = (const float*)d_in[12];
    const float* e_w2    = (const float*)d_in[13];
    const float* s_w1    = (const float*)d_in[14];
    const float* s_w3    = (const float*)d_in[15];
    const float* s_w2    = (const float*)d_in[16];
    float* out = (float*)d_out;

    float *q, *kv, *kpe, *kvb, *h, *eo, *sh;
    __half *nx_h, *ckv_h, *qh, *kcat, *vT, *attn_h, *nh_h, *xg, *t13h, *t1h, *s13h, *s1h;
    __half *wq_h, *wkva_h, *wkvb_h, *wo_h, *ew13_h, *ew2_h, *sw13_h, *sw2_h;
    int *counts, *off, *tile_expert, *bucket_ts, *flat_tok, *tok2row;
    float *bucket_gate, *tok2gate;
    SYM(q, g_q); SYM(kv, g_kv); SYM(kpe, g_kpe); SYM(kvb, g_kvb);
    SYM(h, g_h); SYM(eo, g_eo); SYM(sh, g_sh);
    SYM(nx_h, g_nx_h); SYM(ckv_h, g_ckv_h); SYM(qh, g_qh); SYM(kcat, g_kcat_h);
    SYM(vT, g_vT_h); SYM(attn_h, g_attn_h); SYM(nh_h, g_nh_h);
    SYM(xg, g_xg_h); SYM(t13h, g_t13h); SYM(t1h, g_t1h); SYM(s13h, g_s13h); SYM(s1h, g_s1h);
    SYM(wq_h, g_wq_h); SYM(wkva_h, g_wkva_h); SYM(wkvb_h, g_wkvb_h); SYM(wo_h, g_wo_h);
    SYM(ew13_h, g_ew13_h); SYM(ew2_h, g_ew2_h); SYM(sw13_h, g_sw13_h); SYM(sw2_h, g_sw2_h);
    SYM(counts, g_counts); SYM(off, g_off); SYM(tile_expert, g_tile_expert);
    SYM(bucket_ts, g_bucket_ts); SYM(bucket_gate, g_bucket_gate);
    SYM(flat_tok, g_flat_tok); SYM(tok2row, g_tok2row); SYM(tok2gate, g_tok2gate);

    const long PE4 = (long)MINTERn * DIMn / 4;

    // 0. weight conversion (coalesced 4-wide)
    launch_cvt(wq, wq_h, (long)QPROJ * DIMn);
    launch_cvt(wkv_a, wkva_h, (long)KVAP * DIMn);
    launch_cvt(wkv_b, wkvb_h, (long)KVBP * KVRn);
    launch_cvt(wo, wo_h, (long)DIMn * DIMn);
    {
        long tot4 = (long)NEn * PE4;
        int blocks = (int)((tot4 + 255) / 256);
        cvtmoe4_k<<<blocks, 256>>>((const float4*)e_w1, (uint2*)ew13_h, PE4, 2 * PE4, 0, tot4);
        cvtmoe4_k<<<blocks, 256>>>((const float4*)e_w3, (uint2*)ew13_h, PE4, 2 * PE4, PE4, tot4);
    }
    launch_cvt(e_w2, ew2_h, (long)NEn * DIMn * MINTERn);
    launch_cvt(s_w1, sw13_h, (long)SHIn * DIMn);
    launch_cvt(s_w3, sw13_h + (size_t)SHIn * DIMn, (long)SHIn * DIMn);
    launch_cvt(s_w2, sw2_h, (long)DIMn * SHIn);

    // 1. attention-input rmsnorm -> fp16
    rmsnorm_h<<<Tn, 256>>>(x, attn_w, nx_h, DIMn, DIMn, DIMn);
    // 2. q projection (fp32 out)
    launch_hgemm(nx_h, wq_h, q, nullptr, Tn, QPROJ, DIMn, DIMn, DIMn, QPROJ,
                 0, 0, 0, 0, 0, 0, 1, 1, nullptr, 0, 0);
    // 3. kv_a projection (fp32 out)
    launch_hgemm(nx_h, wkva_h, kv, nullptr, Tn, KVAP, DIMn, DIMn, DIMn, KVAP,
                 0, 0, 0, 0, 0, 0, 1, 1, nullptr, 0, 0);
    // 4. c_kv rmsnorm -> fp16
    rmsnorm_h<<<Tn, 256>>>(kv, kv_w, ckv_h, KVRn, KVAP, KVRn);
    // 5. rope k_pe
    rope_kpe_k<<<Tn, 32>>>(kv, fcos, fsin, kpe);
    // 6. kv_b projection (fp32 out)
    launch_hgemm(ckv_h, wkvb_h, kvb, nullptr, Tn, KVBP, KVRn, KVRn, KVRn, KVBP,
                 0, 0, 0, 0, 0, 0, 1, 1, nullptr, 0, 0);
    // 7. rope + scale q -> fp16
    ropescale_qh<<<Tn * NHn, 96>>>(q, fcos, fsin, qh);
    // 8. kcat + vT -> fp16
    { dim3 g(Sn, ZSn); kcat_h<<<g, QDn>>>(kvb, kpe, kcat); }
    { dim3 g(Sn / 32, VHn / 32, ZSn); dim3 b(32, 8); vtrans_h<<<g, b>>>(kvb, vT); }
    // 9-11. fused flash attention -> attn fp16
    { dim3 g(16, ZSn); fattn_k<<<g, 256, FA_SMEM>>>(qh, kcat, vT, attn_h); }
    // 12. h = x + attn @ wo^T
    launch_hgemm(attn_h, wo_h, h, x, Tn, DIMn, DIMn, DIMn, DIMn, DIMn,
                 0, 0, 0, 0, 0, 0, 1, 1, nullptr, 0, 1);
    // 13. ffn rmsnorm -> fp16
    rmsnorm_h<<<Tn, 256>>>(h, ffn_w, nh_h, DIMn, DIMn, DIMn);
    // 14. routing
    cudaMemsetAsync(counts, 0, NEn * sizeof(int), 0);
    cudaMemsetAsync(flat_tok, 0xFF, MOE_ROWS * sizeof(int), 0);
    router_h<<<Tn, 256>>>(nh_h, rw, counts, bucket_ts, bucket_gate);
    offsets_k<<<1, 1>>>(counts, off, tile_expert);
    compact_k<<<NEn, 256>>>(counts, off, bucket_ts, bucket_gate, flat_tok, tok2row, tok2gate);
    gather_h<<<MOE_ROWS, 256>>>(nh_h, flat_tok, xg);
    // 15. expert FFN (grouped, fused w1||w3)
    launch_hgemm(xg, ew13_h, t13h, nullptr, MOE_ROWS, 2 * MINTERn, DIMn,
                 DIMn, DIMn, 2 * MINTERn,
                 0, 0, 0, 0, 0, 0, 1, 1, tile_expert, 2L * MINTERn * DIMn, 8);
    {
        long n2 = (long)MOE_ROWS * MINTERn / 2;
        silumul2_h<<<(int)((n2 + 255) / 256), 256>>>(t13h, t1h, MINTERn, MOE_ROWS);
    }
    launch_hgemm(t1h, ew2_h, eo, nullptr, MOE_ROWS, DIMn, MINTERn, MINTERn, MINTERn, DIMn,
                 0, 0, 0, 0, 0, 0, 1, 1, tile_expert, (long)DIMn * MINTERn, 0);
    // 16. shared FFN (fused w1||w3)
    launch_hgemm(nh_h, sw13_h, s13h, nullptr, Tn, 2 * SHIn, DIMn, DIMn, DIMn, 2 * SHIn,
                 0, 0, 0, 0, 0, 0, 1, 1, nullptr, 0, 8);
    {
        long n2 = (long)Tn * SHIn / 2;
        silumul2_h<<<(int)((n2 + 255) / 256), 256>>>(s13h, s1h, SHIn, Tn);
    }
    launch_hgemm(s1h, sw2_h, sh, nullptr, Tn, DIMn, SHIn, SHIn, SHIn, DIMn,
                 0, 0, 0, 0, 0, 0, 1, 1, nullptr, 0, 0);
    // 17. combine
    combine_k<<<Tn, 256>>>(h, sh, eo, tok2row, tok2gate, out);
}

// round 15
// speedup vs baseline: 1.4936x; 1.0048x over previous
#include <cuda_runtime.h>
#include <cuda_fp16.h>
#include <math.h>
#include <stdint.h>
#include <string.h>

// ---------------- problem constants ----------------
#define Tn     4096
#define Sn     2048
#define DIMn   2048
#define NHn    16
#define NOPEn  128
#define ROPEn  64
#define QDn    192
#define VHn    128
#define KVRn   512
#define NEn    8
#define MINTERn 1408
#define SHIn   2816
#define QPROJ  3072
#define KVAP   576
#define KVBP   4096
#define MOE_ROWS 9216
#define MOE_TILES 72
#define ZSn    32

// ---------------- fp32 scratch ----------------
__device__ float g_q[(size_t)Tn*QPROJ];
__device__ float g_kv[(size_t)Tn*KVAP];
__device__ float g_kpe[(size_t)Tn*ROPEn];
__device__ float g_kvb[(size_t)Tn*KVBP];
__device__ float g_h[(size_t)Tn*DIMn];
__device__ int   g_counts[NEn];
__device__ int   g_off[NEn+1];
__device__ int   g_tile_expert[MOE_TILES];
__device__ int   g_bucket_ts[NEn*Tn];
__device__ float g_bucket_gate[NEn*Tn];
__device__ int   g_flat_tok[MOE_ROWS];
__device__ int   g_tok2row[Tn*2];
__device__ float g_tok2gate[Tn*2];
// ---------------- fp16 scratch ----------------
__device__ __half g_nx_h[(size_t)Tn*DIMn];
__device__ __half g_ckv_h[(size_t)Tn*KVRn];
__device__ __half g_qh[(size_t)Tn*QPROJ];
__device__ __half g_kcat_h[(size_t)ZSn*Sn*QDn];
__device__ __half g_vT_h[(size_t)ZSn*VHn*Sn];
__device__ __half g_attn_h[(size_t)Tn*DIMn];
__device__ __half g_nh_h[(size_t)Tn*DIMn];
__device__ __half g_xg_h[(size_t)MOE_ROWS*DIMn];
__device__ __half g_t13h[(size_t)MOE_ROWS*2*MINTERn];
__device__ __half g_t1h[(size_t)MOE_ROWS*MINTERn];
__device__ __half g_s13h[(size_t)Tn*2*SHIn];
__device__ __half g_s1h[(size_t)Tn*SHIn];
__device__ __half g_eo_h[(size_t)MOE_ROWS*DIMn];
__device__ __half g_sh_h[(size_t)Tn*DIMn];
// fp16 weight copies
__device__ __half g_wq_h[(size_t)QPROJ*DIMn];
__device__ __half g_wkva_h[(size_t)KVAP*DIMn];
__device__ __half g_wkvb_h[(size_t)KVBP*KVRn];
__device__ __half g_wo_h[(size_t)DIMn*DIMn];
__device__ __half g_ew13_h[(size_t)NEn*2*MINTERn*DIMn];
__device__ __half g_ew2_h[(size_t)NEn*DIMn*MINTERn];
__device__ __half g_sw13_h[(size_t)2*SHIn*DIMn];
__device__ __half g_sw2_h[(size_t)DIMn*SHIn];

// ---------------- helpers ----------------
__device__ __forceinline__ uint32_t h2u(__half2 h) {
    uint32_t u; memcpy(&u, &h, 4); return u;
}
__device__ __forceinline__ void mma16(float* c, const uint32_t* a, const uint32_t* b) {
    asm volatile("mma.sync.aligned.m16n8k16.row.col.f32.f16.f16.f32 "
        "{%0,%1,%2,%3}, {%4,%5,%6,%7}, {%8,%9}, {%0,%1,%2,%3};"
        : "+f"(c[0]), "+f"(c[1]), "+f"(c[2]), "+f"(c[3])
        : "r"(a[0]), "r"(a[1]), "r"(a[2]), "r"(a[3]), "r"(b[0]), "r"(b[1]));
}
__device__ __forceinline__ void ldsm4(uint32_t* r, uint32_t addr) {
    asm volatile("ldmatrix.sync.aligned.m8n8.x4.shared.b16 {%0,%1,%2,%3}, [%4];"
        : "=r"(r[0]), "=r"(r[1]), "=r"(r[2]), "=r"(r[3]) : "r"(addr));
}
__device__ __forceinline__ void cpasync16(uint32_t dst, const void* src, int sz) {
    asm volatile("cp.async.cg.shared.global [%0], [%1], 16, %2;"
                 :: "r"(dst), "l"(src), "r"(sz));
}
__device__ __forceinline__ void cpcommit() { asm volatile("cp.async.commit_group;"); }
__device__ __forceinline__ void cpwait1() { asm volatile("cp.async.wait_group 1;"); }
__device__ __forceinline__ void cpwait2() { asm volatile("cp.async.wait_group 2;"); }

// ---------------- fp16 tensor GEMM, 128x128 CTA, 4-stage, 2 CTAs/SM ----------------
// flags: 1 add addend(fp32 out), 8 fp16 out
#define LDPH 20
#define AROWB (LDPH*4)               // 80 bytes
#define TNW 128
#define NTT 4
#define ABY (128*AROWB)
#define STG (2*ABY)
#define HG_SMEM (4*STG)              // 81920 B

__global__ __launch_bounds__(256, 2) void hgemm_k(
    const __half* __restrict__ A, const __half* __restrict__ B, void* __restrict__ Cv,
    const float* __restrict__ addend,
    int M, int N, int K, int lda, int ldb, int ldc,
    long sA0, long sA1, long sB0, long sB1, long sC0, long sC1, int ZH,
    const int* __restrict__ tileExpert, long wStride, int flags)
{
    int bx = blockIdx.x, by = blockIdx.y, z = blockIdx.z;
    if (tileExpert) { int te = tileExpert[by]; if (te < 0) return; B += (long)te * wStride; }
    int zb = z / ZH, zh = z - zb * ZH;
    A += zb * sA0 + (long)zh * sA1;
    B += zb * sB0 + (long)zh * sB1;
    int NT = K >> 5;

    extern __shared__ char smraw[];
    uint32_t sb = (uint32_t)__cvta_generic_to_shared(smraw);

    int tid = threadIdx.x;
    int wid = tid >> 5, lane = tid & 31;
    int wy = wid & 1, wx = wid >> 1;

    int grp = lane >> 3, lrow = lane & 7;
    uint32_t aoff = (uint32_t)((wy * 64 + (grp & 1) * 8 + lrow) * AROWB + (grp >> 1) * 16);
    uint32_t boff = (uint32_t)((wx * 32 + (grp >> 1) * 8 + lrow) * AROWB + (grp & 1) * 16);

    int ar0 = tid >> 2, ac0 = tid & 3;
    int bsz[2];
#pragma unroll
    for (int ch = 0; ch < 2; ch++) {
        int row = ar0 + ch * 64;
        bsz[ch] = ((bx * TNW + row) < N) ? 16 : 0;
    }
    const __half* bsrc0 = B;

    auto issue = [&](int s, int k0) {
        uint32_t Ab = sb + s * STG;
        uint32_t Bb = Ab + ABY;
#pragma unroll
        for (int ch = 0; ch < 2; ch++) {
            int row = ar0 + ch * 64;
            const __half* src = A + (long)(by * 128 + row) * lda + k0 + ac0 * 8;
            cpasync16(Ab + row * AROWB + ac0 * 16, src, 16);
        }
#pragma unroll
        for (int ch = 0; ch < 2; ch++) {
            int row = ar0 + ch * 64;
            const __half* src = bsz[ch] ? (B + (long)(bx * TNW + row) * ldb + k0 + ac0 * 8) : bsrc0;
            cpasync16(Bb + row * AROWB + ac0 * 16, src, bsz[ch]);
        }
    };

#pragma unroll
    for (int s = 0; s < 3; s++) {
        if (s < NT) issue(s, s * 32);
        cpcommit();
    }

    float acc[4][NTT][4];
#pragma unroll
    for (int mt = 0; mt < 4; mt++)
#pragma unroll
        for (int nt = 0; nt < NTT; nt++)
#pragma unroll
            for (int i = 0; i < 4; i++) acc[mt][nt][i] = 0.f;

    for (int it = 0; it < NT; ++it) {
        cpwait2();
        __syncthreads();
        if (it + 3 < NT) issue((it + 3) & 3, (it + 3) * 32);
        cpcommit();

        int st = it & 3;
        uint32_t Abase = sb + st * STG + aoff;
        uint32_t Bbase = sb + st * STG + ABY + boff;
#pragma unroll
        for (int ks = 0; ks < 2; ks++) {
            uint32_t af[4][4], bf[NTT][2];
#pragma unroll
            for (int mt = 0; mt < 4; mt++)
                ldsm4(af[mt], Abase + mt * (16 * AROWB) + ks * 32);
#pragma unroll
            for (int p = 0; p < NTT / 2; p++) {
                uint32_t r[4];
                ldsm4(r, Bbase + p * (16 * AROWB) + ks * 32);
                bf[2 * p][0] = r[0]; bf[2 * p][1] = r[1];
                bf[2 * p + 1][0] = r[2]; bf[2 * p + 1][1] = r[3];
            }
#pragma unroll
            for (int mt = 0; mt < 4; mt++)
#pragma unroll
                for (int nt = 0; nt < NTT; nt++)
                    mma16(acc[mt][nt], af[mt], bf[nt]);
        }
        __syncthreads();
    }

    bool doadd = (flags & 1) != 0;
    bool outh = (flags & 8) != 0;
    float* Cf = (float*)Cv + zb * sC0 + (long)zh * sC1;
    __half* Ch = (__half*)Cv + zb * sC0 + (long)zh * sC1;
    const float* Af = addend ? (addend + zb * sC0 + (long)zh * sC1) : nullptr;
    int elr = lane >> 2, elk = lane & 3;
#pragma unroll
    for (int mt = 0; mt < 4; mt++) {
        int m0 = by * 128 + wy * 64 + mt * 16 + elr;
#pragma unroll
        for (int nt = 0; nt < NTT; nt++) {
            int c0 = bx * TNW + wx * 32 + nt * 8 + 2 * elk;
            if (c0 < N) {
                float2 v0 = make_float2(acc[mt][nt][0], acc[mt][nt][1]);
                float2 v1 = make_float2(acc[mt][nt][2], acc[mt][nt][3]);
                if (outh) {
                    *(__half2*)(Ch + (long)m0 * ldc + c0) = __float22half2_rn(v0);
                    *(__half2*)(Ch + (long)(m0 + 8) * ldc + c0) = __float22half2_rn(v1);
                } else {
                    if (doadd) {
                        float2 o0 = *(const float2*)(Af + (long)m0 * ldc + c0);
                        float2 o1 = *(const float2*)(Af + (long)(m0 + 8) * ldc + c0);
                        v0.x += o0.x; v0.y += o0.y; v1.x += o1.x; v1.y += o1.y;
                    }
                    *(float2*)(Cf + (long)m0 * ldc + c0) = v0;
                    *(float2*)(Cf + (long)(m0 + 8) * ldc + c0) = v1;
                }
            }
        }
    }
}

// ---------------- fused flash attention ----------------
#define QROWB 400
#define VROWB 272
#define FA_QS 0
#define FA_KS (128*QROWB)
#define FA_VS (2*128*QROWB)
#define FA_PS (FA_VS + 128*VROWB)
#define FA_RA (FA_PS + 128*VROWB)
#define FA_RB (FA_RA + 2048)
#define FA_SMEM (FA_RB + 2048)

__global__ __launch_bounds__(256) void fattn_k(
    const __half* __restrict__ qh, const __half* __restrict__ kcat,
    const __half* __restrict__ vT, __half* __restrict__ attn)
{
    int by = (int)gridDim.x - 1 - blockIdx.x;
    int z = blockIdx.y;
    int zb = z >> 4, zh = z & 15;

    extern __shared__ char smraw[];
    uint32_t sb = (uint32_t)__cvta_generic_to_shared(smraw);
    float* rowA = (float*)(smraw + FA_RA);
    float* rowB = (float*)(smraw + FA_RB);

    int tid = threadIdx.x;
    int wid = tid >> 5, lane = tid & 31;
    int wy = wid & 1, wx = wid >> 1;
    int grp = lane >> 3, lrow = lane & 7;
    int elr = lane >> 2, elk = lane & 3;

    uint32_t aoffQ = (uint32_t)((wy * 64 + (grp & 1) * 8 + lrow) * QROWB + (grp >> 1) * 16);
    uint32_t boffK = (uint32_t)((wx * 32 + (grp >> 1) * 8 + lrow) * QROWB + (grp & 1) * 16);
    uint32_t aoffP = (uint32_t)((wy * 64 + (grp & 1) * 8 + lrow) * VROWB + (grp >> 1) * 16);
    uint32_t boffV = (uint32_t)((wx * 32 + (grp >> 1) * 8 + lrow) * VROWB + (grp & 1) * 16);

    const __half* Qg = qh + ((long)zb * Sn + (long)by * 128) * QPROJ + zh * QDn;
    const __half* Kg = kcat + (long)z * Sn * QDn;
    const __half* Vg = vT + (long)z * VHn * Sn;

    auto issueK = [&](int kb) {
#pragma unroll
        for (int ch = 0; ch < 12; ch++) {
            int idx = tid + ch * 256;
            int row = idx / 24, cq = idx - row * 24;
            cpasync16(sb + FA_KS + row * QROWB + cq * 16,
                      Kg + ((long)kb * 128 + row) * QDn + cq * 8, 16);
        }
    };
    auto issueV = [&](int kb) {
#pragma unroll
        for (int ch = 0; ch < 8; ch++) {
            int idx = tid + ch * 256;
            int row = idx >> 4, cq = idx & 15;
            cpasync16(sb + FA_VS + row * VROWB + cq * 16,
                      Vg + (long)row * Sn + kb * 128 + cq * 8, 16);
        }
    };

#pragma unroll
    for (int ch = 0; ch < 12; ch++) {
        int idx = tid + ch * 256;
        int row = idx / 24, cq = idx - row * 24;
        cpasync16(sb + FA_QS + row * QROWB + cq * 16, Qg + (long)row * QPROJ + cq * 8, 16);
    }
    cpcommit();
    issueK(0); cpcommit();
    issueV(0); cpcommit();

    float accO[4][4][4];
    float mold[4][2], lrun[4][2];
#pragma unroll
    for (int mt = 0; mt < 4; mt++) {
#pragma unroll
        for (int nt = 0; nt < 4; nt++)
#pragma unroll
            for (int i = 0; i < 4; i++) accO[mt][nt][i] = 0.f;
        mold[mt][0] = -3.4e38f; mold[mt][1] = -3.4e38f;
        lrun[mt][0] = 0.f; lrun[mt][1] = 0.f;
    }

    for (int kb = 0; kb <= by; kb++) {
        cpwait1();
        __syncthreads();

        float accS[4][4][4];
#pragma unroll
        for (int mt = 0; mt < 4; mt++)
#pragma unroll
            for (int nt = 0; nt < 4; nt++)
#pragma unroll
                for (int i = 0; i < 4; i++) accS[mt][nt][i] = 0.f;
#pragma unroll
        for (int ks = 0; ks < 12; ks++) {
            uint32_t af[4][4], bf[4][2];
#pragma unroll
            for (int mt = 0; mt < 4; mt++)
                ldsm4(af[mt], sb + FA_QS + aoffQ + mt * (16 * QROWB) + ks * 32);
#pragma unroll
            for (int p = 0; p < 2; p++) {
                uint32_t r[4];
                ldsm4(r, sb + FA_KS + boffK + p * (16 * QROWB) + ks * 32);
                bf[2 * p][0] = r[0]; bf[2 * p][1] = r[1];
                bf[2 * p + 1][0] = r[2]; bf[2 * p + 1][1] = r[3];
            }
#pragma unroll
            for (int mt = 0; mt < 4; mt++)
#pragma unroll
                for (int nt = 0; nt < 4; nt++)
                    mma16(accS[mt][nt], af[mt], bf[nt]);
        }
        if (kb == by) {
#pragma unroll
            for (int mt = 0; mt < 4; mt++) {
                int r0 = wy * 64 + mt * 16 + elr, r1 = r0 + 8;
#pragma unroll
                for (int nt = 0; nt < 4; nt++) {
                    int c = wx * 32 + nt * 8 + 2 * elk;
                    if (c > r0)     accS[mt][nt][0] = -3.4e38f;
                    if (c + 1 > r0) accS[mt][nt][1] = -3.4e38f;
                    if (c > r1)     accS[mt][nt][2] = -3.4e38f;
                    if (c + 1 > r1) accS[mt][nt][3] = -3.4e38f;
                }
            }
        }
        float lmax[4][2];
#pragma unroll
        for (int mt = 0; mt < 4; mt++) {
            float a = -3.4e38f, b = -3.4e38f;
#pragma unroll
            for (int nt = 0; nt < 4; nt++) {
                a = fmaxf(a, fmaxf(accS[mt][nt][0], accS[mt][nt][1]));
                b = fmaxf(b, fmaxf(accS[mt][nt][2], accS[mt][nt][3]));
            }
            lmax[mt][0] = a; lmax[mt][1] = b;
        }
#pragma unroll
        for (int off = 1; off <= 2; off <<= 1)
#pragma unroll
            for (int mt = 0; mt < 4; mt++) {
                lmax[mt][0] = fmaxf(lmax[mt][0], __shfl_xor_sync(0xffffffffu, lmax[mt][0], off));
                lmax[mt][1] = fmaxf(lmax[mt][1], __shfl_xor_sync(0xffffffffu, lmax[mt][1], off));
            }
        if (elk == 0) {
#pragma unroll
            for (int mt = 0; mt < 4; mt++) {
                int m = wy * 64 + mt * 16 + elr;
                rowA[wx * 128 + m] = lmax[mt][0];
                rowA[wx * 128 + m + 8] = lmax[mt][1];
            }
        }
        __syncthreads();
        if (kb + 1 <= by) issueK(kb + 1);
        cpcommit();

        float mnew[4][2];
#pragma unroll
        for (int mt = 0; mt < 4; mt++) {
#pragma unroll
            for (int hf = 0; hf < 2; hf++) {
                int m = wy * 64 + mt * 16 + elr + hf * 8;
                float v = fmaxf(fmaxf(rowA[m], rowA[128 + m]),
                                fmaxf(rowA[256 + m], rowA[384 + m]));
                mnew[mt][hf] = fmaxf(mold[mt][hf], v);
            }
        }
        float lsum[4][2];
#pragma unroll
        for (int mt = 0; mt < 4; mt++) { lsum[mt][0] = 0.f; lsum[mt][1] = 0.f; }
#pragma unroll
        for (int mt = 0; mt < 4; mt++) {
            int r0 = wy * 64 + mt * 16 + elr;
#pragma unroll
            for (int nt = 0; nt < 4; nt++) {
                int c = wx * 32 + nt * 8 + 2 * elk;
                float p0 = __expf(accS[mt][nt][0] - mnew[mt][0]);
                float p1 = __expf(accS[mt][nt][1] - mnew[mt][0]);
                float p2 = __expf(accS[mt][nt][2] - mnew[mt][1]);
                float p3 = __expf(accS[mt][nt][3] - mnew[mt][1]);
                lsum[mt][0] += p0 + p1;
                lsum[mt][1] += p2 + p3;
                *(__half2*)(smraw + FA_PS + r0 * VROWB + c * 2) =
                    __float22half2_rn(make_float2(p0, p1));
                *(__half2*)(smraw + FA_PS + (r0 + 8) * VROWB + c * 2) =
                    __float22half2_rn(make_float2(p2, p3));
            }
        }
#pragma unroll
        for (int off = 1; off <= 2; off <<= 1)
#pragma unroll
            for (int mt = 0; mt < 4; mt++) {
                lsum[mt][0] += __shfl_xor_sync(0xffffffffu, lsum[mt][0], off);
                lsum[mt][1] += __shfl_xor_sync(0xffffffffu, lsum[mt][1], off);
            }
        if (elk == 0) {
#pragma unroll
            for (int mt = 0; mt < 4; mt++) {
                int m = wy * 64 + mt * 16 + elr;
                rowB[wx * 128 + m] = lsum[mt][0];
                rowB[wx * 128 + m + 8] = lsum[mt][1];
            }
        }
        cpwait1();
        __syncthreads();

#pragma unroll
        for (int mt = 0; mt < 4; mt++) {
#pragma unroll
            for (int hf = 0; hf < 2; hf++) {
                int m = wy * 64 + mt * 16 + elr + hf * 8;
                float rs = rowB[m] + rowB[128 + m] + rowB[256 + m] + rowB[384 + m];
                float fsc = __expf(mold[mt][hf] - mnew[mt][hf]);
                lrun[mt][hf] = lrun[mt][hf] * fsc + rs;
                mold[mt][hf] = mnew[mt][hf];
#pragma unroll
                for (int nt = 0; nt < 4; nt++) {
                    accO[mt][nt][hf * 2 + 0] *= fsc;
                    accO[mt][nt][hf * 2 + 1] *= fsc;
                }
            }
        }
#pragma unroll
        for (int ks = 0; ks < 8; ks++) {
            uint32_t af[4][4], bf[4][2];
#pragma unroll
            for (int mt = 0; mt < 4; mt++)
                ldsm4(af[mt], sb + FA_PS + aoffP + mt * (16 * VROWB) + ks * 32);
#pragma unroll
            for (int p = 0; p < 2; p++) {
                uint32_t r[4];
                ldsm4(r, sb + FA_VS + boffV + p * (16 * VROWB) + ks * 32);
                bf[2 * p][0] = r[0]; bf[2 * p][1] = r[1];
                bf[2 * p + 1][0] = r[2]; bf[2 * p + 1][1] = r[3];
            }
#pragma unroll
            for (int mt = 0; mt < 4; mt++)
#pragma unroll
                for (int nt = 0; nt < 4; nt++)
                    mma16(accO[mt][nt], af[mt], bf[nt]);
        }
        __syncthreads();
        if (kb + 1 <= by) issueV(kb + 1);
        cpcommit();
    }

    __half* Og = attn + (long)zb * Sn * DIMn + zh * VHn;
#pragma unroll
    for (int mt = 0; mt < 4; mt++) {
        float i0 = 1.f / lrun[mt][0], i1 = 1.f / lrun[mt][1];
        int m = by * 128 + wy * 64 + mt * 16 + elr;
#pragma unroll
        for (int nt = 0; nt < 4; nt++) {
            int d = wx * 32 + nt * 8 + 2 * elk;
            *(__half2*)(Og + (long)m * DIMn + d) =
                __float22half2_rn(make_float2(accO[mt][nt][0] * i0, accO[mt][nt][1] * i0));
            *(__half2*)(Og + (long)(m + 8) * DIMn + d) =
                __float22half2_rn(make_float2(accO[mt][nt][2] * i1, accO[mt][nt][3] * i1));
        }
    }
}

// ---------------- coalesced weight fp32 -> fp16 (grid-stride, MLP ~4) ----------------
__global__ void cvt4_k(const float4* __restrict__ src, uint2* __restrict__ dst, long n4)
{
    long stride = (long)gridDim.x * blockDim.x;
    for (long i = (long)blockIdx.x * blockDim.x + threadIdx.x; i < n4; i += stride) {
        float4 a = src[i];
        uint2 o;
        o.x = h2u(__floats2half2_rn(a.x, a.y));
        o.y = h2u(__floats2half2_rn(a.z, a.w));
        dst[i] = o;
    }
}
__global__ void cvtmoe4_k(const float4* __restrict__ src, uint2* __restrict__ dst,
                          long perExp4, long dstStride4, long dstOff4, long total4)
{
    long stride = (long)gridDim.x * blockDim.x;
    for (long i = (long)blockIdx.x * blockDim.x + threadIdx.x; i < total4; i += stride) {
        long e = i / perExp4, r = i - e * perExp4;
        float4 a = src[i];
        uint2 o;
        o.x = h2u(__floats2half2_rn(a.x, a.y));
        o.y = h2u(__floats2half2_rn(a.z, a.w));
        dst[e * dstStride4 + dstOff4 + r] = o;
    }
}

// ---------------- reductions ----------------
__device__ __forceinline__ float warpSum(float v) {
#pragma unroll
    for (int o = 16; o; o >>= 1) v += __shfl_xor_sync(0xffffffffu, v, o);
    return v;
}

// ---------------- rmsnorm: fp32 in -> fp16 out ----------------
__global__ void rmsnorm_h(const float* __restrict__ x, const float* __restrict__ w,
                          __half* __restrict__ y, int D, int ldx, int ldy)
{
    long t = blockIdx.x;
    const float* xr = x + t * ldx;
    __half* yr = y + t * ldy;
    float s = 0.f;
    for (int d = threadIdx.x; d < D; d += blockDim.x) { float v = xr[d]; s += v * v; }
    __shared__ float sh[32];
    __shared__ float bc;
    s = warpSum(s);
    int lane = threadIdx.x & 31, wp = threadIdx.x >> 5;
    if (!lane) sh[wp] = s;
    __syncthreads();
    if (threadIdx.x < 32) {
        float r = (threadIdx.x < (blockDim.x >> 5)) ? sh[threadIdx.x] : 0.f;
        r = warpSum(r);
        if (!threadIdx.x) bc = rsqrtf(r / D + 1e-6f);
    }
    __syncthreads();
    float sc = bc;
    for (int d = threadIdx.x; d < D; d += blockDim.x)
        yr[d] = __float2half_rn(xr[d] * sc * w[d]);
}

// ---------------- rope on k_pe (fp32) ----------------
__global__ void rope_kpe_k(const float* __restrict__ kv, const float* __restrict__ fc,
                           const float* __restrict__ fs, float* __restrict__ kpe)
{
    long t = blockIdx.x;
    int j = threadIdx.x;
    int pos = (int)(t % Sn);
    float x1 = kv[t * KVAP + KVRn + 2 * j];
    float x2 = kv[t * KVAP + KVRn + 2 * j + 1];
    float c = fc[pos * 32 + j], s = fs[pos * 32 + j];
    kpe[t * ROPEn + 2 * j]     = x1 * c - x2 * s;
    kpe[t * ROPEn + 2 * j + 1] = x1 * s + x2 * c;
}

// ---------------- rope + scale on q: fp32 in -> fp16 out ----------------
__global__ void ropescale_qh(const float* __restrict__ q, const float* __restrict__ fc,
                             const float* __restrict__ fs, __half* __restrict__ qh)
{
    long th = blockIdx.x;
    int pos = (int)((th >> 4) % Sn);
    const float* r = q + th * QDn;
    __half* o = qh + th * QDn;
    int i = threadIdx.x;
    const float sc = 0.07216878364870322f;   // 1/sqrt(192)
    if (i < 64) {
        o[2 * i]     = __float2half_rn(r[2 * i] * sc);
        o[2 * i + 1] = __float2half_rn(r[2 * i + 1] * sc);
    } else {
        int j = i - 64;
        float x1 = r[128 + 2 * j], x2 = r[128 + 2 * j + 1];
        float c = fc[pos * 32 + j], s = fs[pos * 32 + j];
        o[128 + 2 * j]     = __float2half_rn((x1 * c - x2 * s) * sc);
        o[128 + 2 * j + 1] = __float2half_rn((x1 * s + x2 * c) * sc);
    }
}

// ---------------- [k_nope | k_pe] concat -> fp16 ----------------
__global__ void kcat_h(const float* __restrict__ kvb, const float* __restrict__ kpe,
                       __half* __restrict__ kcat)
{
    int s = blockIdx.x, z = blockIdx.y, j = threadIdx.x;
    long t = (long)(z >> 4) * Sn + s;
    float v = (j < NOPEn) ? kvb[t * KVBP + (z & 15) * 256 + j]
                          : kpe[t * ROPEn + (j - NOPEn)];
    kcat[((long)z * Sn + s) * QDn + j] = __float2half_rn(v);
}

// ---------------- transpose V -> vT fp16 ----------------
__global__ void vtrans_h(const float* __restrict__ kvb, __half* __restrict__ vT)
{
    __shared__ float tsm[32][33];
    int z = blockIdx.z, zb = z >> 4, zh = z & 15;
    int kt = blockIdx.x * 32, dt = blockIdx.y * 32;
    int tx = threadIdx.x, ty = threadIdx.y;
#pragma unroll
    for (int i = 0; i < 4; i++) {
        int k = kt + ty + i * 8;
        tsm[ty + i * 8][tx] = kvb[((long)zb * Sn + k) * KVBP + zh * 256 + NOPEn + dt + tx];
    }
    __syncthreads();
#pragma unroll
    for (int i = 0; i < 4; i++) {
        int d = dt + ty + i * 8;
        vT[((long)z * VHn + d) * Sn + kt + tx] = __float2half_rn(tsm[tx][ty + i * 8]);
    }
}

// ---------------- router (reads fp16 nh) ----------------
__global__ void router_h(const __half* __restrict__ nh, const float* __restrict__ rw,
                         int* __restrict__ counts, int* __restrict__ bucket_ts,
                         float* __restrict__ bucket_gate)
{
    long t = blockIdx.x;
    int wp = threadIdx.x >> 5, lane = threadIdx.x & 31;
    const __half* xr = nh + t * DIMn;
    float s = 0.f;
    for (int d = lane; d < DIMn; d += 32) s += __half2float(xr[d]) * rw[(long)wp * DIMn + d];
    s = warpSum(s);
    __shared__ float logit[NEn];
    if (!lane) logit[wp] = s;
    __syncthreads();
    if (threadIdx.x == 0) {
        float mx = logit[0];
#pragma unroll
        for (int e = 1; e < NEn; e++) mx = fmaxf(mx, logit[e]);
        float p[NEn];
#pragma unroll
        for (int e = 0; e < NEn; e++) p[e] = expf(logit[e] - mx);
        int i0 = 0;
#pragma unroll
        for (int e = 1; e < NEn; e++) if (p[e] > p[i0]) i0 = e;
        int i1 = (i0 == 0) ? 1 : 0;
#pragma unroll
        for (int e = 0; e < NEn; e++) if (e != i0 && p[e] > p[i1]) i1 = e;
        float denom = p[i0] + p[i1];
        float g0 = p[i0] / denom, g1 = p[i1] / denom;
        int pos0 = atomicAdd(&counts[i0], 1);
        bucket_ts[i0 * Tn + pos0] = (int)(t * 2);
        bucket_gate[i0 * Tn + pos0] = g0;
        int pos1 = atomicAdd(&counts[i1], 1);
        bucket_ts[i1 * Tn + pos1] = (int)(t * 2 + 1);
        bucket_gate[i1 * Tn + pos1] = g1;
    }
}

__global__ void offsets_k(const int* __restrict__ counts, int* __restrict__ off,
                          int* __restrict__ tile_expert)
{
    for (int tl = 0; tl < MOE_TILES; tl++) tile_expert[tl] = -1;
    int o = 0;
    for (int e = 0; e < NEn; e++) {
        off[e] = o;
        int nt = (counts[e] + 127) >> 7;
        for (int i = 0; i < nt; i++) tile_expert[(o >> 7) + i] = e;
        o += nt * 128;
    }
    off[NEn] = o;
}

__global__ void compact_k(const int* __restrict__ counts, const int* __restrict__ off,
                          const int* __restrict__ bucket_ts, const float* __restrict__ bucket_gate,
                          int* __restrict__ flat_tok, int* __restrict__ tok2row,
                          float* __restrict__ tok2gate)
{
    int e = blockIdx.x;
    int cnt = counts[e], base = off[e];
    for (int i = threadIdx.x; i < cnt; i += blockDim.x) {
        int ts = bucket_ts[e * Tn + i];
        int r = base + i;
        flat_tok[r] = ts >> 1;
        tok2row[ts] = r;
        tok2gate[ts] = bucket_gate[e * Tn + i];
    }
}

__global__ void gather_h(const __half* __restrict__ nh, const int* __restrict__ flat_tok,
                         __half* __restrict__ xg)
{
    long r = blockIdx.x;
    int t = flat_tok[r];
    uint4* dst = (uint4*)(xg + r * DIMn);
    int nch = DIMn / 8;
    if (t < 0) {
        uint4 zz = make_uint4(0u, 0u, 0u, 0u);
        for (int i = threadIdx.x; i < nch; i += blockDim.x) dst[i] = zz;
    } else {
        const uint4* src = (const uint4*)(nh + (long)t * DIMn);
        for (int i = threadIdx.x; i < nch; i += blockDim.x) dst[i] = src[i];
    }
}

__global__ void silumul2_h(const __half* __restrict__ t13, __half* __restrict__ outp,
                           int inter, long rows)
{
    long h2pr = inter / 2;
    long i = (long)blockIdx.x * blockDim.x + threadIdx.x;
    if (i < rows * h2pr) {
        long r = i / h2pr, j = i - r * h2pr;
        const __half2* pa = (const __half2*)(t13 + (size_t)r * 2 * inter);
        const __half2* pb = (const __half2*)(t13 + (size_t)r * 2 * inter + inter);
        float2 x = __half22float2(pa[j]);
        float2 y = __half22float2(pb[j]);
        float s0 = x.x / (1.f + expf(-x.x));
        float s1 = x.y / (1.f + expf(-x.y));
        ((__half2*)(outp + (size_t)r * inter))[j] =
            __float22half2_rn(make_float2(s0 * y.x, s1 * y.y));
    }
}

// ---------------- combine: h fp32 + sh fp16 + gated eo fp16 ----------------
__global__ void combine_k(const float* __restrict__ h, const __half* __restrict__ sh,
                          const __half* __restrict__ eo, const int* __restrict__ tok2row,
                          const float* __restrict__ tok2gate, float* __restrict__ out)
{
    long t = blockIdx.x;
    int r0 = tok2row[t * 2], r1 = tok2row[t * 2 + 1];
    float g0 = tok2gate[t * 2], g1 = tok2gate[t * 2 + 1];
    const float4* H = (const float4*)(h + t * DIMn);
    const __half2* SH = (const __half2*)(sh + t * DIMn);
    const __half2* E0 = (const __half2*)(eo + (long)r0 * DIMn);
    const __half2* E1 = (const __half2*)(eo + (long)r1 * DIMn);
    float4* O = (float4*)(out + t * DIMn);
    for (int i = threadIdx.x; i < DIMn / 4; i += blockDim.x) {
        float4 a = H[i];
        float2 s0 = __half22float2(SH[2 * i]),     s1 = __half22float2(SH[2 * i + 1]);
        float2 c0 = __half22float2(E0[2 * i]),     c1 = __half22float2(E0[2 * i + 1]);
        float2 d0 = __half22float2(E1[2 * i]),     d1 = __half22float2(E1[2 * i + 1]);
        float4 o;
        o.x = a.x + s0.x + g0 * c0.x + g1 * d0.x;
        o.y = a.y + s0.y + g0 * c0.y + g1 * d0.y;
        o.z = a.z + s1.x + g0 * c1.x + g1 * d1.x;
        o.w = a.w + s1.y + g0 * c1.y + g1 * d1.y;
        O[i] = o;
    }
}

// ---------------- host ----------------
#define SYM(p, s) do { void* _q = nullptr; cudaGetSymbolAddress(&_q, s); p = (decltype(p))_q; } while (0)

static void launch_hgemm(const __half* A, const __half* B, void* C, const float* addend,
                         int M, int N, int K, int lda, int ldb, int ldc,
                         long sA0, long sA1, long sB0, long sB1, long sC0, long sC1,
                         int ZH, int Z, const int* tileExpert, long wStride, int flags)
{
    dim3 grid((N + TNW - 1) / TNW, M / 128, Z);
    hgemm_k<<<grid, 256, HG_SMEM>>>(A, B, C, addend, M, N, K, lda, ldb, ldc,
        sA0, sA1, sB0, sB1, sC0, sC1, ZH, tileExpert, wStride, flags);
}

static void launch_cvt(const float* src, __half* dst, long n)
{
    long n4 = n / 4;
    int blocks = (int)((n4 / 4 + 255) / 256);
    if (blocks < 148) blocks = 148;
    cvt4_k<<<blocks, 256>>>((const float4*)src, (uint2*)dst, n4);
}

extern "C" void kernel_launch(void* const* d_in, const int* in_sizes, int n_in,
                              void* d_out, int out_size)
{
    cudaFuncSetAttribute(hgemm_k, cudaFuncAttributeMaxDynamicSharedMemorySize, HG_SMEM);
    cudaFuncSetAttribute(fattn_k, cudaFuncAttributeMaxDynamicSharedMemorySize, FA_SMEM);

    const float* x       = (const float*)d_in[0];
    const float* fcos    = (const float*)d_in[1];
    const float* fsin    = (const float*)d_in[2];
    const float* attn_w  = (const float*)d_in[3];
    const float* wq      = (const float*)d_in[4];
    const float* wkv_a   = (const float*)d_in[5];
    const float* kv_w    = (const float*)d_in[6];
    const float* wkv_b   = (const float*)d_in[7];
    const float* wo      = (const float*)d_in[8];
    const float* ffn_w   = (const float*)d_in[9];
    const float* rw      = (const float*)d_in[10];
    const float* e_w1    = (const float*)d_in[11];
    const float* e_w3    = (const float*)d_in[12];
    const float* e_w2    = (const float*)d_in[13];
    const float* s_w1    = (const float*)d_in[14];
    const float* s_w3    = (const float*)d_in[15];
    const float* s_w2    = (const float*)d_in[16];
    float* out = (float*)d_out;

    float *q, *kv, *kpe, *kvb, *h;
    __half *nx_h, *ckv_h, *qh, *kcat, *vT, *attn_h, *nh_h, *xg, *t13h, *t1h, *s13h, *s1h;
    __half *eo_h, *sh_h;
    __half *wq_h, *wkva_h, *wkvb_h, *wo_h, *ew13_h, *ew2_h, *sw13_h, *sw2_h;
    int *counts, *off, *tile_expert, *bucket_ts, *flat_tok, *tok2row;
    float *bucket_gate, *tok2gate;
    SYM(q, g_q); SYM(kv, g_kv); SYM(kpe, g_kpe); SYM(kvb, g_kvb); SYM(h, g_h);
    SYM(nx_h, g_nx_h); SYM(ckv_h, g_ckv_h); SYM(qh, g_qh); SYM(kcat, g_kcat_h);
    SYM(vT, g_vT_h); SYM(attn_h, g_attn_h); SYM(nh_h, g_nh_h);
    SYM(xg, g_xg_h); SYM(t13h, g_t13h); SYM(t1h, g_t1h); SYM(s13h, g_s13h); SYM(s1h, g_s1h);
    SYM(eo_h, g_eo_h); SYM(sh_h, g_sh_h);
    SYM(wq_h, g_wq_h); SYM(wkva_h, g_wkva_h); SYM(wkvb_h, g_wkvb_h); SYM(wo_h, g_wo_h);
    SYM(ew13_h, g_ew13_h); SYM(ew2_h, g_ew2_h); SYM(sw13_h, g_sw13_h); SYM(sw2_h, g_sw2_h);
    SYM(counts, g_counts); SYM(off, g_off); SYM(tile_expert, g_tile_expert);
    SYM(bucket_ts, g_bucket_ts); SYM(bucket_gate, g_bucket_gate);
    SYM(flat_tok, g_flat_tok); SYM(tok2row, g_tok2row); SYM(tok2gate, g_tok2gate);

    const long PE4 = (long)MINTERn * DIMn / 4;

    // 0. weight conversion (coalesced, grid-stride)
    launch_cvt(wq, wq_h, (long)QPROJ * DIMn);
    launch_cvt(wkv_a, wkva_h, (long)KVAP * DIMn);
    launch_cvt(wkv_b, wkvb_h, (long)KVBP * KVRn);
    launch_cvt(wo, wo_h, (long)DIMn * DIMn);
    {
        long tot4 = (long)NEn * PE4;
        int blocks = (int)((tot4 / 4 + 255) / 256);
        cvtmoe4_k<<<blocks, 256>>>((const float4*)e_w1, (uint2*)ew13_h, PE4, 2 * PE4, 0, tot4);
        cvtmoe4_k<<<blocks, 256>>>((const float4*)e_w3, (uint2*)ew13_h, PE4, 2 * PE4, PE4, tot4);
    }
    launch_cvt(e_w2, ew2_h, (long)NEn * DIMn * MINTERn);
    launch_cvt(s_w1, sw13_h, (long)SHIn * DIMn);
    launch_cvt(s_w3, sw13_h + (size_t)SHIn * DIMn, (long)SHIn * DIMn);
    launch_cvt(s_w2, sw2_h, (long)DIMn * SHIn);

    // 1. attention-input rmsnorm -> fp16
    rmsnorm_h<<<Tn, 256>>>(x, attn_w, nx_h, DIMn, DIMn, DIMn);
    // 2. q projection (fp32 out)
    launch_hgemm(nx_h, wq_h, q, nullptr, Tn, QPROJ, DIMn, DIMn, DIMn, QPROJ,
                 0, 0, 0, 0, 0, 0, 1, 1, nullptr, 0, 0);
    // 3. kv_a projection (fp32 out)
    launch_hgemm(nx_h, wkva_h, kv, nullptr, Tn, KVAP, DIMn, DIMn, DIMn, KVAP,
                 0, 0, 0, 0, 0, 0, 1, 1, nullptr, 0, 0);
    // 4. c_kv rmsnorm -> fp16
    rmsnorm_h<<<Tn, 256>>>(kv, kv_w, ckv_h, KVRn, KVAP, KVRn);
    // 5. rope k_pe
    rope_kpe_k<<<Tn, 32>>>(kv, fcos, fsin, kpe);
    // 6. kv_b projection (fp32 out)
    launch_hgemm(ckv_h, wkvb_h, kvb, nullptr, Tn, KVBP, KVRn, KVRn, KVRn, KVBP,
                 0, 0, 0, 0, 0, 0, 1, 1, nullptr, 0, 0);
    // 7. rope + scale q -> fp16
    ropescale_qh<<<Tn * NHn, 96>>>(q, fcos, fsin, qh);
    // 8. kcat + vT -> fp16
    { dim3 g(Sn, ZSn); kcat_h<<<g, QDn>>>(kvb, kpe, kcat); }
    { dim3 g(Sn / 32, VHn / 32, ZSn); dim3 b(32, 8); vtrans_h<<<g, b>>>(kvb, vT); }
    // 9-11. fused flash attention -> attn fp16
    { dim3 g(16, ZSn); fattn_k<<<g, 256, FA_SMEM>>>(qh, kcat, vT, attn_h); }
    // 12. h = x + attn @ wo^T
    launch_hgemm(attn_h, wo_h, h, x, Tn, DIMn, DIMn, DIMn, DIMn, DIMn,
                 0, 0, 0, 0, 0, 0, 1, 1, nullptr, 0, 1);
    // 13. ffn rmsnorm -> fp16
    rmsnorm_h<<<Tn, 256>>>(h, ffn_w, nh_h, DIMn, DIMn, DIMn);
    // 14. routing
    cudaMemsetAsync(counts, 0, NEn * sizeof(int), 0);
    cudaMemsetAsync(flat_tok, 0xFF, MOE_ROWS * sizeof(int), 0);
    router_h<<<Tn, 256>>>(nh_h, rw, counts, bucket_ts, bucket_gate);
    offsets_k<<<1, 1>>>(counts, off, tile_expert);
    compact_k<<<NEn, 256>>>(counts, off, bucket_ts, bucket_gate, flat_tok, tok2row, tok2gate);
    gather_h<<<MOE_ROWS, 256>>>(nh_h, flat_tok, xg);
    // 15. expert FFN (grouped, fused w1||w3; fp16 eo)
    launch_hgemm(xg, ew13_h, t13h, nullptr, MOE_ROWS, 2 * MINTERn, DIMn,
                 DIMn, DIMn, 2 * MINTERn,
                 0, 0, 0, 0, 0, 0, 1, 1, tile_expert, 2L * MINTERn * DIMn, 8);
    {
        long n2 = (long)MOE_ROWS * MINTERn / 2;
        silumul2_h<<<(int)((n2 + 255) / 256), 256>>>(t13h, t1h, MINTERn, MOE_ROWS);
    }
    launch_hgemm(t1h, ew2_h, eo_h, nullptr, MOE_ROWS, DIMn, MINTERn, MINTERn, MINTERn, DIMn,
                 0, 0, 0, 0, 0, 0, 1, 1, tile_expert, (long)DIMn * MINTERn, 8);
    // 16. shared FFN (fused w1||w3; fp16 sh)
    launch_hgemm(nh_h, sw13_h, s13h, nullptr, Tn, 2 * SHIn, DIMn, DIMn, DIMn, 2 * SHIn,
                 0, 0, 0, 0, 0, 0, 1, 1, nullptr, 0, 8);
    {
        long n2 = (long)Tn * SHIn / 2;
        silumul2_h<<<(int)((n2 + 255) / 256), 256>>>(s13h, s1h, SHIn, Tn);
    }
    launch_hgemm(s1h, sw2_h, sh_h, nullptr, Tn, DIMn, SHIn, SHIn, SHIn, DIMn,
                 0, 0, 0, 0, 0, 0, 1, 1, nullptr, 0, 8);
    // 17. combine
    combine_k<<<Tn, 256>>>(h, sh_h, eo_h, tok2row, tok2gate, out);
}

// round 16
// speedup vs baseline: 1.5189x; 1.0170x over previous
#include <cuda_runtime.h>
#include <cuda_fp16.h>
#include <math.h>
#include <stdint.h>
#include <string.h>

// ---------------- problem constants ----------------
#define Tn     4096
#define Sn     2048
#define DIMn   2048
#define NHn    16
#define NOPEn  128
#define ROPEn  64
#define QDn    192
#define VHn    128
#define KVRn   512
#define NEn    8
#define MINTERn 1408
#define SHIn   2816
#define QPROJ  3072
#define KVAP   576
#define QKVP   3648            // QPROJ + KVAP
#define KVBP   4096
#define MOE_ROWS 9216
#define MOE_TILES 72
#define ZSn    32

// ---------------- fp32 scratch ----------------
__device__ float g_qkv[(size_t)Tn*QKVP];
__device__ float g_kpe[(size_t)Tn*ROPEn];
__device__ float g_kvb[(size_t)Tn*KVBP];
__device__ float g_h[(size_t)Tn*DIMn];
__device__ int   g_counts[NEn];
__device__ int   g_off[NEn+1];
__device__ int   g_tile_expert[MOE_TILES];
__device__ int   g_bucket_ts[NEn*Tn];
__device__ float g_bucket_gate[NEn*Tn];
__device__ int   g_flat_tok[MOE_ROWS];
__device__ int   g_tok2row[Tn*2];
__device__ float g_tok2gate[Tn*2];
// ---------------- fp16 scratch ----------------
__device__ __half g_nx_h[(size_t)Tn*DIMn];
__device__ __half g_ckv_h[(size_t)Tn*KVRn];
__device__ __half g_qh[(size_t)Tn*QPROJ];
__device__ __half g_kcat_h[(size_t)ZSn*Sn*QDn];
__device__ __half g_vT_h[(size_t)ZSn*VHn*Sn];
__device__ __half g_attn_h[(size_t)Tn*DIMn];
__device__ __half g_nh_h[(size_t)Tn*DIMn];
__device__ __half g_xg_h[(size_t)MOE_ROWS*DIMn];
__device__ __half g_t13h[(size_t)MOE_ROWS*2*MINTERn];
__device__ __half g_t1h[(size_t)MOE_ROWS*MINTERn];
__device__ __half g_s13h[(size_t)Tn*2*SHIn];
__device__ __half g_s1h[(size_t)Tn*SHIn];
__device__ __half g_eo_h[(size_t)MOE_ROWS*DIMn];
__device__ __half g_sh_h[(size_t)Tn*DIMn];
// fp16 weight copies
__device__ __half g_wqa_h[(size_t)QKVP*DIMn];
__device__ __half g_wkvb_h[(size_t)KVBP*KVRn];
__device__ __half g_wo_h[(size_t)DIMn*DIMn];
__device__ __half g_ew13_h[(size_t)NEn*2*MINTERn*DIMn];
__device__ __half g_ew2_h[(size_t)NEn*DIMn*MINTERn];
__device__ __half g_sw13_h[(size_t)2*SHIn*DIMn];
__device__ __half g_sw2_h[(size_t)DIMn*SHIn];

// ---------------- helpers ----------------
__device__ __forceinline__ uint32_t h2u(__half2 h) {
    uint32_t u; memcpy(&u, &h, 4); return u;
}
__device__ __forceinline__ void mma16(float* c, const uint32_t* a, const uint32_t* b) {
    asm volatile("mma.sync.aligned.m16n8k16.row.col.f32.f16.f16.f32 "
        "{%0,%1,%2,%3}, {%4,%5,%6,%7}, {%8,%9}, {%0,%1,%2,%3};"
        : "+f"(c[0]), "+f"(c[1]), "+f"(c[2]), "+f"(c[3])
        : "r"(a[0]), "r"(a[1]), "r"(a[2]), "r"(a[3]), "r"(b[0]), "r"(b[1]));
}
__device__ __forceinline__ void ldsm4(uint32_t* r, uint32_t addr) {
    asm volatile("ldmatrix.sync.aligned.m8n8.x4.shared.b16 {%0,%1,%2,%3}, [%4];"
        : "=r"(r[0]), "=r"(r[1]), "=r"(r[2]), "=r"(r[3]) : "r"(addr));
}
__device__ __forceinline__ void cpasync16(uint32_t dst, const void* src, int sz) {
    asm volatile("cp.async.cg.shared.global [%0], [%1], 16, %2;"
                 :: "r"(dst), "l"(src), "r"(sz));
}
__device__ __forceinline__ void cpcommit() { asm volatile("cp.async.commit_group;"); }
__device__ __forceinline__ void cpwait1() { asm volatile("cp.async.wait_group 1;"); }
__device__ __forceinline__ void cpwait2() { asm volatile("cp.async.wait_group 2;"); }

// ---------------- fp16 tensor GEMM, 128x128 CTA, 4-stage, 2 CTAs/SM ----------------
// flags: 1 add addend(fp32 out), 8 fp16 out
#define LDPH 20
#define AROWB (LDPH*4)               // 80 bytes
#define TNW 128
#define NTT 4
#define ABY (128*AROWB)
#define STG (2*ABY)
#define HG_SMEM (4*STG)              // 81920 B

__global__ __launch_bounds__(256, 2) void hgemm_k(
    const __half* __restrict__ A, const __half* __restrict__ B, void* __restrict__ Cv,
    const float* __restrict__ addend,
    int M, int N, int K, int lda, int ldb, int ldc,
    long sA0, long sA1, long sB0, long sB1, long sC0, long sC1, int ZH,
    const int* __restrict__ tileExpert, long wStride, int flags)
{
    int bx = blockIdx.x, by = blockIdx.y, z = blockIdx.z;
    if (tileExpert) { int te = tileExpert[by]; if (te < 0) return; B += (long)te * wStride; }
    int zb = z / ZH, zh = z - zb * ZH;
    A += zb * sA0 + (long)zh * sA1;
    B += zb * sB0 + (long)zh * sB1;
    int NT = K >> 5;

    extern __shared__ char smraw[];
    uint32_t sb = (uint32_t)__cvta_generic_to_shared(smraw);

    int tid = threadIdx.x;
    int wid = tid >> 5, lane = tid & 31;
    int wy = wid & 1, wx = wid >> 1;

    int grp = lane >> 3, lrow = lane & 7;
    uint32_t aoff = (uint32_t)((wy * 64 + (grp & 1) * 8 + lrow) * AROWB + (grp >> 1) * 16);
    uint32_t boff = (uint32_t)((wx * 32 + (grp >> 1) * 8 + lrow) * AROWB + (grp & 1) * 16);

    int ar0 = tid >> 2, ac0 = tid & 3;
    int bsz[2];
#pragma unroll
    for (int ch = 0; ch < 2; ch++) {
        int row = ar0 + ch * 64;
        bsz[ch] = ((bx * TNW + row) < N) ? 16 : 0;
    }
    const __half* bsrc0 = B;

    auto issue = [&](int s, int k0) {
        uint32_t Ab = sb + s * STG;
        uint32_t Bb = Ab + ABY;
#pragma unroll
        for (int ch = 0; ch < 2; ch++) {
            int row = ar0 + ch * 64;
            const __half* src = A + (long)(by * 128 + row) * lda + k0 + ac0 * 8;
            cpasync16(Ab + row * AROWB + ac0 * 16, src, 16);
        }
#pragma unroll
        for (int ch = 0; ch < 2; ch++) {
            int row = ar0 + ch * 64;
            const __half* src = bsz[ch] ? (B + (long)(bx * TNW + row) * ldb + k0 + ac0 * 8) : bsrc0;
            cpasync16(Bb + row * AROWB + ac0 * 16, src, bsz[ch]);
        }
    };

#pragma unroll
    for (int s = 0; s < 3; s++) {
        if (s < NT) issue(s, s * 32);
        cpcommit();
    }

    float acc[4][NTT][4];
#pragma unroll
    for (int mt = 0; mt < 4; mt++)
#pragma unroll
        for (int nt = 0; nt < NTT; nt++)
#pragma unroll
            for (int i = 0; i < 4; i++) acc[mt][nt][i] = 0.f;

    for (int it = 0; it < NT; ++it) {
        cpwait2();
        __syncthreads();
        if (it + 3 < NT) issue((it + 3) & 3, (it + 3) * 32);
        cpcommit();

        int st = it & 3;
        uint32_t Abase = sb + st * STG + aoff;
        uint32_t Bbase = sb + st * STG + ABY + boff;
#pragma unroll
        for (int ks = 0; ks < 2; ks++) {
            uint32_t af[4][4], bf[NTT][2];
#pragma unroll
            for (int mt = 0; mt < 4; mt++)
                ldsm4(af[mt], Abase + mt * (16 * AROWB) + ks * 32);
#pragma unroll
            for (int p = 0; p < NTT / 2; p++) {
                uint32_t r[4];
                ldsm4(r, Bbase + p * (16 * AROWB) + ks * 32);
                bf[2 * p][0] = r[0]; bf[2 * p][1] = r[1];
                bf[2 * p + 1][0] = r[2]; bf[2 * p + 1][1] = r[3];
            }
#pragma unroll
            for (int mt = 0; mt < 4; mt++)
#pragma unroll
                for (int nt = 0; nt < NTT; nt++)
                    mma16(acc[mt][nt], af[mt], bf[nt]);
        }
        __syncthreads();
    }

    bool doadd = (flags & 1) != 0;
    bool outh = (flags & 8) != 0;
    float* Cf = (float*)Cv + zb * sC0 + (long)zh * sC1;
    __half* Ch = (__half*)Cv + zb * sC0 + (long)zh * sC1;
    const float* Af = addend ? (addend + zb * sC0 + (long)zh * sC1) : nullptr;
    int elr = lane >> 2, elk = lane & 3;
#pragma unroll
    for (int mt = 0; mt < 4; mt++) {
        int m0 = by * 128 + wy * 64 + mt * 16 + elr;
#pragma unroll
        for (int nt = 0; nt < NTT; nt++) {
            int c0 = bx * TNW + wx * 32 + nt * 8 + 2 * elk;
            if (c0 < N) {
                float2 v0 = make_float2(acc[mt][nt][0], acc[mt][nt][1]);
                float2 v1 = make_float2(acc[mt][nt][2], acc[mt][nt][3]);
                if (outh) {
                    *(__half2*)(Ch + (long)m0 * ldc + c0) = __float22half2_rn(v0);
                    *(__half2*)(Ch + (long)(m0 + 8) * ldc + c0) = __float22half2_rn(v1);
                } else {
                    if (doadd) {
                        float2 o0 = *(const float2*)(Af + (long)m0 * ldc + c0);
                        float2 o1 = *(const float2*)(Af + (long)(m0 + 8) * ldc + c0);
                        v0.x += o0.x; v0.y += o0.y; v1.x += o1.x; v1.y += o1.y;
                    }
                    *(float2*)(Cf + (long)m0 * ldc + c0) = v0;
                    *(float2*)(Cf + (long)(m0 + 8) * ldc + c0) = v1;
                }
            }
        }
    }
}

// ---------------- fused flash attention ----------------
#define QROWB 400
#define VROWB 272
#define FA_QS 0
#define FA_KS (128*QROWB)
#define FA_VS (2*128*QROWB)
#define FA_PS (FA_VS + 128*VROWB)
#define FA_RA (FA_PS + 128*VROWB)
#define FA_RB (FA_RA + 2048)
#define FA_SMEM (FA_RB + 2048)

__global__ __launch_bounds__(256) void fattn_k(
    const __half* __restrict__ qh, const __half* __restrict__ kcat,
    const __half* __restrict__ vT, __half* __restrict__ attn)
{
    int by = (int)gridDim.x - 1 - blockIdx.x;
    int z = blockIdx.y;
    int zb = z >> 4, zh = z & 15;

    extern __shared__ char smraw[];
    uint32_t sb = (uint32_t)__cvta_generic_to_shared(smraw);
    float* rowA = (float*)(smraw + FA_RA);
    float* rowB = (float*)(smraw + FA_RB);

    int tid = threadIdx.x;
    int wid = tid >> 5, lane = tid & 31;
    int wy = wid & 1, wx = wid >> 1;
    int grp = lane >> 3, lrow = lane & 7;
    int elr = lane >> 2, elk = lane & 3;

    uint32_t aoffQ = (uint32_t)((wy * 64 + (grp & 1) * 8 + lrow) * QROWB + (grp >> 1) * 16);
    uint32_t boffK = (uint32_t)((wx * 32 + (grp >> 1) * 8 + lrow) * QROWB + (grp & 1) * 16);
    uint32_t aoffP = (uint32_t)((wy * 64 + (grp & 1) * 8 + lrow) * VROWB + (grp >> 1) * 16);
    uint32_t boffV = (uint32_t)((wx * 32 + (grp >> 1) * 8 + lrow) * VROWB + (grp & 1) * 16);

    const __half* Qg = qh + ((long)zb * Sn + (long)by * 128) * QPROJ + zh * QDn;
    const __half* Kg = kcat + (long)z * Sn * QDn;
    const __half* Vg = vT + (long)z * VHn * Sn;

    auto issueK = [&](int kb) {
#pragma unroll
        for (int ch = 0; ch < 12; ch++) {
            int idx = tid + ch * 256;
            int row = idx / 24, cq = idx - row * 24;
            cpasync16(sb + FA_KS + row * QROWB + cq * 16,
                      Kg + ((long)kb * 128 + row) * QDn + cq * 8, 16);
        }
    };
    auto issueV = [&](int kb) {
#pragma unroll
        for (int ch = 0; ch < 8; ch++) {
            int idx = tid + ch * 256;
            int row = idx >> 4, cq = idx & 15;
            cpasync16(sb + FA_VS + row * VROWB + cq * 16,
                      Vg + (long)row * Sn + kb * 128 + cq * 8, 16);
        }
    };

#pragma unroll
    for (int ch = 0; ch < 12; ch++) {
        int idx = tid + ch * 256;
        int row = idx / 24, cq = idx - row * 24;
        cpasync16(sb + FA_QS + row * QROWB + cq * 16, Qg + (long)row * QPROJ + cq * 8, 16);
    }
    cpcommit();
    issueK(0); cpcommit();
    issueV(0); cpcommit();

    float accO[4][4][4];
    float mold[4][2], lrun[4][2];
#pragma unroll
    for (int mt = 0; mt < 4; mt++) {
#pragma unroll
        for (int nt = 0; nt < 4; nt++)
#pragma unroll
            for (int i = 0; i < 4; i++) accO[mt][nt][i] = 0.f;
        mold[mt][0] = -3.4e38f; mold[mt][1] = -3.4e38f;
        lrun[mt][0] = 0.f; lrun[mt][1] = 0.f;
    }

    for (int kb = 0; kb <= by; kb++) {
        cpwait1();
        __syncthreads();

        float accS[4][4][4];
#pragma unroll
        for (int mt = 0; mt < 4; mt++)
#pragma unroll
            for (int nt = 0; nt < 4; nt++)
#pragma unroll
                for (int i = 0; i < 4; i++) accS[mt][nt][i] = 0.f;
#pragma unroll
        for (int ks = 0; ks < 12; ks++) {
            uint32_t af[4][4], bf[4][2];
#pragma unroll
            for (int mt = 0; mt < 4; mt++)
                ldsm4(af[mt], sb + FA_QS + aoffQ + mt * (16 * QROWB) + ks * 32);
#pragma unroll
            for (int p = 0; p < 2; p++) {
                uint32_t r[4];
                ldsm4(r, sb + FA_KS + boffK + p * (16 * QROWB) + ks * 32);
                bf[2 * p][0] = r[0]; bf[2 * p][1] = r[1];
                bf[2 * p + 1][0] = r[2]; bf[2 * p + 1][1] = r[3];
            }
#pragma unroll
            for (int mt = 0; mt < 4; mt++)
#pragma unroll
                for (int nt = 0; nt < 4; nt++)
                    mma16(accS[mt][nt], af[mt], bf[nt]);
        }
        if (kb == by) {
#pragma unroll
            for (int mt = 0; mt < 4; mt++) {
                int r0 = wy * 64 + mt * 16 + elr, r1 = r0 + 8;
#pragma unroll
                for (int nt = 0; nt < 4; nt++) {
                    int c = wx * 32 + nt * 8 + 2 * elk;
                    if (c > r0)     accS[mt][nt][0] = -3.4e38f;
                    if (c + 1 > r0) accS[mt][nt][1] = -3.4e38f;
                    if (c > r1)     accS[mt][nt][2] = -3.4e38f;
                    if (c + 1 > r1) accS[mt][nt][3] = -3.4e38f;
                }
            }
        }
        float lmax[4][2];
#pragma unroll
        for (int mt = 0; mt < 4; mt++) {
            float a = -3.4e38f, b = -3.4e38f;
#pragma unroll
            for (int nt = 0; nt < 4; nt++) {
                a = fmaxf(a, fmaxf(accS[mt][nt][0], accS[mt][nt][1]));
                b = fmaxf(b, fmaxf(accS[mt][nt][2], accS[mt][nt][3]));
            }
            lmax[mt][0] = a; lmax[mt][1] = b;
        }
#pragma unroll
        for (int off = 1; off <= 2; off <<= 1)
#pragma unroll
            for (int mt = 0; mt < 4; mt++) {
                lmax[mt][0] = fmaxf(lmax[mt][0], __shfl_xor_sync(0xffffffffu, lmax[mt][0], off));
                lmax[mt][1] = fmaxf(lmax[mt][1], __shfl_xor_sync(0xffffffffu, lmax[mt][1], off));
            }
        if (elk == 0) {
#pragma unroll
            for (int mt = 0; mt < 4; mt++) {
                int m = wy * 64 + mt * 16 + elr;
                rowA[wx * 128 + m] = lmax[mt][0];
                rowA[wx * 128 + m + 8] = lmax[mt][1];
            }
        }
        __syncthreads();
        if (kb + 1 <= by) issueK(kb + 1);
        cpcommit();

        float mnew[4][2];
#pragma unroll
        for (int mt = 0; mt < 4; mt++) {
#pragma unroll
            for (int hf = 0; hf < 2; hf++) {
                int m = wy * 64 + mt * 16 + elr + hf * 8;
                float v = fmaxf(fmaxf(rowA[m], rowA[128 + m]),
                                fmaxf(rowA[256 + m], rowA[384 + m]));
                mnew[mt][hf] = fmaxf(mold[mt][hf], v);
            }
        }
        float lsum[4][2];
#pragma unroll
        for (int mt = 0; mt < 4; mt++) { lsum[mt][0] = 0.f; lsum[mt][1] = 0.f; }
#pragma unroll
        for (int mt = 0; mt < 4; mt++) {
            int r0 = wy * 64 + mt * 16 + elr;
#pragma unroll
            for (int nt = 0; nt < 4; nt++) {
                int c = wx * 32 + nt * 8 + 2 * elk;
                float p0 = __expf(accS[mt][nt][0] - mnew[mt][0]);
                float p1 = __expf(accS[mt][nt][1] - mnew[mt][0]);
                float p2 = __expf(accS[mt][nt][2] - mnew[mt][1]);
                float p3 = __expf(accS[mt][nt][3] - mnew[mt][1]);
                lsum[mt][0] += p0 + p1;
                lsum[mt][1] += p2 + p3;
                *(__half2*)(smraw + FA_PS + r0 * VROWB + c * 2) =
                    __float22half2_rn(make_float2(p0, p1));
                *(__half2*)(smraw + FA_PS + (r0 + 8) * VROWB + c * 2) =
                    __float22half2_rn(make_float2(p2, p3));
            }
        }
#pragma unroll
        for (int off = 1; off <= 2; off <<= 1)
#pragma unroll
            for (int mt = 0; mt < 4; mt++) {
                lsum[mt][0] += __shfl_xor_sync(0xffffffffu, lsum[mt][0], off);
                lsum[mt][1] += __shfl_xor_sync(0xffffffffu, lsum[mt][1], off);
            }
        if (elk == 0) {
#pragma unroll
            for (int mt = 0; mt < 4; mt++) {
                int m = wy * 64 + mt * 16 + elr;
                rowB[wx * 128 + m] = lsum[mt][0];
                rowB[wx * 128 + m + 8] = lsum[mt][1];
            }
        }
        cpwait1();
        __syncthreads();

#pragma unroll
        for (int mt = 0; mt < 4; mt++) {
#pragma unroll
            for (int hf = 0; hf < 2; hf++) {
                int m = wy * 64 + mt * 16 + elr + hf * 8;
                float rs = rowB[m] + rowB[128 + m] + rowB[256 + m] + rowB[384 + m];
                float fsc = __expf(mold[mt][hf] - mnew[mt][hf]);
                lrun[mt][hf] = lrun[mt][hf] * fsc + rs;
                mold[mt][hf] = mnew[mt][hf];
#pragma unroll
                for (int nt = 0; nt < 4; nt++) {
                    accO[mt][nt][hf * 2 + 0] *= fsc;
                    accO[mt][nt][hf * 2 + 1] *= fsc;
                }
            }
        }
#pragma unroll
        for (int ks = 0; ks < 8; ks++) {
            uint32_t af[4][4], bf[4][2];
#pragma unroll
            for (int mt = 0; mt < 4; mt++)
                ldsm4(af[mt], sb + FA_PS + aoffP + mt * (16 * VROWB) + ks * 32);
#pragma unroll
            for (int p = 0; p < 2; p++) {
                uint32_t r[4];
                ldsm4(r, sb + FA_VS + boffV + p * (16 * VROWB) + ks * 32);
                bf[2 * p][0] = r[0]; bf[2 * p][1] = r[1];
                bf[2 * p + 1][0] = r[2]; bf[2 * p + 1][1] = r[3];
            }
#pragma unroll
            for (int mt = 0; mt < 4; mt++)
#pragma unroll
                for (int nt = 0; nt < 4; nt++)
                    mma16(accO[mt][nt], af[mt], bf[nt]);
        }
        __syncthreads();
        if (kb + 1 <= by) issueV(kb + 1);
        cpcommit();
    }

    __half* Og = attn + (long)zb * Sn * DIMn + zh * VHn;
#pragma unroll
    for (int mt = 0; mt < 4; mt++) {
        float i0 = 1.f / lrun[mt][0], i1 = 1.f / lrun[mt][1];
        int m = by * 128 + wy * 64 + mt * 16 + elr;
#pragma unroll
        for (int nt = 0; nt < 4; nt++) {
            int d = wx * 32 + nt * 8 + 2 * elk;
            *(__half2*)(Og + (long)m * DIMn + d) =
                __float22half2_rn(make_float2(accO[mt][nt][0] * i0, accO[mt][nt][1] * i0));
            *(__half2*)(Og + (long)(m + 8) * DIMn + d) =
                __float22half2_rn(make_float2(accO[mt][nt][2] * i1, accO[mt][nt][3] * i1));
        }
    }
}

// ---------------- coalesced weight fp32 -> fp16 (grid-stride) ----------------
__global__ void cvt4_k(const float4* __restrict__ src, uint2* __restrict__ dst, long n4)
{
    long stride = (long)gridDim.x * blockDim.x;
    for (long i = (long)blockIdx.x * blockDim.x + threadIdx.x; i < n4; i += stride) {
        float4 a = src[i];
        uint2 o;
        o.x = h2u(__floats2half2_rn(a.x, a.y));
        o.y = h2u(__floats2half2_rn(a.z, a.w));
        dst[i] = o;
    }
}
__global__ void cvtmoe4_k(const float4* __restrict__ src, uint2* __restrict__ dst,
                          long perExp4, long dstStride4, long dstOff4, long total4)
{
    long stride = (long)gridDim.x * blockDim.x;
    for (long i = (long)blockIdx.x * blockDim.x + threadIdx.x; i < total4; i += stride) {
        long e = i / perExp4, r = i - e * perExp4;
        float4 a = src[i];
        uint2 o;
        o.x = h2u(__floats2half2_rn(a.x, a.y));
        o.y = h2u(__floats2half2_rn(a.z, a.w));
        dst[e * dstStride4 + dstOff4 + r] = o;
    }
}

// ---------------- reductions ----------------
__device__ __forceinline__ float warpSum(float v) {
#pragma unroll
    for (int o = 16; o; o >>= 1) v += __shfl_xor_sync(0xffffffffu, v, o);
    return v;
}

// ---------------- rmsnorm: fp32 in -> fp16 out ----------------
__global__ void rmsnorm_h(const float* __restrict__ x, const float* __restrict__ w,
                          __half* __restrict__ y, int D, int ldx, int ldy)
{
    long t = blockIdx.x;
    const float* xr = x + t * ldx;
    __half* yr = y + t * ldy;
    float s = 0.f;
    for (int d = threadIdx.x; d < D; d += blockDim.x) { float v = xr[d]; s += v * v; }
    __shared__ float sh[32];
    __shared__ float bc;
    s = warpSum(s);
    int lane = threadIdx.x & 31, wp = threadIdx.x >> 5;
    if (!lane) sh[wp] = s;
    __syncthreads();
    if (threadIdx.x < 32) {
        float r = (threadIdx.x < (blockDim.x >> 5)) ? sh[threadIdx.x] : 0.f;
        r = warpSum(r);
        if (!threadIdx.x) bc = rsqrtf(r / D + 1e-6f);
    }
    __syncthreads();
    float sc = bc;
    for (int d = threadIdx.x; d < D; d += blockDim.x)
        yr[d] = __float2half_rn(xr[d] * sc * w[d]);
}

// ---------------- rope on k_pe (fp32, strided source) ----------------
__global__ void rope_kpe_k(const float* __restrict__ kvsrc, int ld,
                           const float* __restrict__ fc, const float* __restrict__ fs,
                           float* __restrict__ kpe)
{
    long t = blockIdx.x;
    int j = threadIdx.x;
    int pos = (int)(t % Sn);
    float x1 = kvsrc[t * (long)ld + 2 * j];
    float x2 = kvsrc[t * (long)ld + 2 * j + 1];
    float c = fc[pos * 32 + j], s = fs[pos * 32 + j];
    kpe[t * ROPEn + 2 * j]     = x1 * c - x2 * s;
    kpe[t * ROPEn + 2 * j + 1] = x1 * s + x2 * c;
}

// ---------------- rope + scale on q: fp32 (strided) in -> fp16 out ----------------
__global__ void ropescale_qh(const float* __restrict__ qkv, const float* __restrict__ fc,
                             const float* __restrict__ fs, __half* __restrict__ qh)
{
    long th = blockIdx.x;
    long t = th >> 4;
    int hh = (int)(th & 15);
    int pos = (int)(t % Sn);
    const float* r = qkv + t * QKVP + hh * QDn;
    __half* o = qh + th * QDn;
    int i = threadIdx.x;
    const float sc = 0.07216878364870322f;   // 1/sqrt(192)
    if (i < 64) {
        o[2 * i]     = __float2half_rn(r[2 * i] * sc);
        o[2 * i + 1] = __float2half_rn(r[2 * i + 1] * sc);
    } else {
        int j = i - 64;
        float x1 = r[128 + 2 * j], x2 = r[128 + 2 * j + 1];
        float c = fc[pos * 32 + j], s = fs[pos * 32 + j];
        o[128 + 2 * j]     = __float2half_rn((x1 * c - x2 * s) * sc);
        o[128 + 2 * j + 1] = __float2half_rn((x1 * s + x2 * c) * sc);
    }
}

// ---------------- [k_nope | k_pe] concat -> fp16 ----------------
__global__ void kcat_h(const float* __restrict__ kvb, const float* __restrict__ kpe,
                       __half* __restrict__ kcat)
{
    int s = blockIdx.x, z = blockIdx.y, j = threadIdx.x;
    long t = (long)(z >> 4) * Sn + s;
    float v = (j < NOPEn) ? kvb[t * KVBP + (z & 15) * 256 + j]
                          : kpe[t * ROPEn + (j - NOPEn)];
    kcat[((long)z * Sn + s) * QDn + j] = __float2half_rn(v);
}

// ---------------- transpose V -> vT fp16 ----------------
__global__ void vtrans_h(const float* __restrict__ kvb, __half* __restrict__ vT)
{
    __shared__ float tsm[32][33];
    int z = blockIdx.z, zb = z >> 4, zh = z & 15;
    int kt = blockIdx.x * 32, dt = blockIdx.y * 32;
    int tx = threadIdx.x, ty = threadIdx.y;
#pragma unroll
    for (int i = 0; i < 4; i++) {
        int k = kt + ty + i * 8;
        tsm[ty + i * 8][tx] = kvb[((long)zb * Sn + k) * KVBP + zh * 256 + NOPEn + dt + tx];
    }
    __syncthreads();
#pragma unroll
    for (int i = 0; i < 4; i++) {
        int d = dt + ty + i * 8;
        vT[((long)z * VHn + d) * Sn + kt + tx] = __float2half_rn(tsm[tx][ty + i * 8]);
    }
}

// ---------------- router (reads fp16 nh) ----------------
__global__ void router_h(const __half* __restrict__ nh, const float* __restrict__ rw,
                         int* __restrict__ counts, int* __restrict__ bucket_ts,
                         float* __restrict__ bucket_gate)
{
    long t = blockIdx.x;
    int wp = threadIdx.x >> 5, lane = threadIdx.x & 31;
    const __half* xr = nh + t * DIMn;
    float s = 0.f;
    for (int d = lane; d < DIMn; d += 32) s += __half2float(xr[d]) * rw[(long)wp * DIMn + d];
    s = warpSum(s);
    __shared__ float logit[NEn];
    if (!lane) logit[wp] = s;
    __syncthreads();
    if (threadIdx.x == 0) {
        float mx = logit[0];
#pragma unroll
        for (int e = 1; e < NEn; e++) mx = fmaxf(mx, logit[e]);
        float p[NEn];
#pragma unroll
        for (int e = 0; e < NEn; e++) p[e] = expf(logit[e] - mx);
        int i0 = 0;
#pragma unroll
        for (int e = 1; e < NEn; e++) if (p[e] > p[i0]) i0 = e;
        int i1 = (i0 == 0) ? 1 : 0;
#pragma unroll
        for (int e = 0; e < NEn; e++) if (e != i0 && p[e] > p[i1]) i1 = e;
        float denom = p[i0] + p[i1];
        float g0 = p[i0] / denom, g1 = p[i1] / denom;
        int pos0 = atomicAdd(&counts[i0], 1);
        bucket_ts[i0 * Tn + pos0] = (int)(t * 2);
        bucket_gate[i0 * Tn + pos0] = g0;
        int pos1 = atomicAdd(&counts[i1], 1);
        bucket_ts[i1 * Tn + pos1] = (int)(t * 2 + 1);
        bucket_gate[i1 * Tn + pos1] = g1;
    }
}

__global__ void offsets_k(const int* __restrict__ counts, int* __restrict__ off,
                          int* __restrict__ tile_expert)
{
    for (int tl = 0; tl < MOE_TILES; tl++) tile_expert[tl] = -1;
    int o = 0;
    for (int e = 0; e < NEn; e++) {
        off[e] = o;
        int nt = (counts[e] + 127) >> 7;
        for (int i = 0; i < nt; i++) tile_expert[(o >> 7) + i] = e;
        o += nt * 128;
    }
    off[NEn] = o;
}

__global__ void compact_k(const int* __restrict__ counts, const int* __restrict__ off,
                          const int* __restrict__ bucket_ts, const float* __restrict__ bucket_gate,
                          int* __restrict__ flat_tok, int* __restrict__ tok2row,
                          float* __restrict__ tok2gate)
{
    int e = blockIdx.x;
    int cnt = counts[e], base = off[e];
    for (int i = threadIdx.x; i < cnt; i += blockDim.x) {
        int ts = bucket_ts[e * Tn + i];
        int r = base + i;
        flat_tok[r] = ts >> 1;
        tok2row[ts] = r;
        tok2gate[ts] = bucket_gate[e * Tn + i];
    }
}

__global__ void gather_h(const __half* __restrict__ nh, const int* __restrict__ flat_tok,
                         __half* __restrict__ xg)
{
    long r = blockIdx.x;
    int t = flat_tok[r];
    uint4* dst = (uint4*)(xg + r * DIMn);
    int nch = DIMn / 8;
    if (t < 0) {
        uint4 zz = make_uint4(0u, 0u, 0u, 0u);
        for (int i = threadIdx.x; i < nch; i += blockDim.x) dst[i] = zz;
    } else {
        const uint4* src = (const uint4*)(nh + (long)t * DIMn);
        for (int i = threadIdx.x; i < nch; i += blockDim.x) dst[i] = src[i];
    }
}

__global__ void silumul2_h(const __half* __restrict__ t13, __half* __restrict__ outp,
                           int inter, long rows)
{
    long h2pr = inter / 2;
    long i = (long)blockIdx.x * blockDim.x + threadIdx.x;
    if (i < rows * h2pr) {
        long r = i / h2pr, j = i - r * h2pr;
        const __half2* pa = (const __half2*)(t13 + (size_t)r * 2 * inter);
        const __half2* pb = (const __half2*)(t13 + (size_t)r * 2 * inter + inter);
        float2 x = __half22float2(pa[j]);
        float2 y = __half22float2(pb[j]);
        float s0 = x.x / (1.f + expf(-x.x));
        float s1 = x.y / (1.f + expf(-x.y));
        ((__half2*)(outp + (size_t)r * inter))[j] =
            __float22half2_rn(make_float2(s0 * y.x, s1 * y.y));
    }
}

// ---------------- combine: h fp32 + sh fp16 + gated eo fp16 ----------------
__global__ void combine_k(const float* __restrict__ h, const __half* __restrict__ sh,
                          const __half* __restrict__ eo, const int* __restrict__ tok2row,
                          const float* __restrict__ tok2gate, float* __restrict__ out)
{
    long t = blockIdx.x;
    int r0 = tok2row[t * 2], r1 = tok2row[t * 2 + 1];
    float g0 = tok2gate[t * 2], g1 = tok2gate[t * 2 + 1];
    const float4* H = (const float4*)(h + t * DIMn);
    const __half2* SH = (const __half2*)(sh + t * DIMn);
    const __half2* E0 = (const __half2*)(eo + (long)r0 * DIMn);
    const __half2* E1 = (const __half2*)(eo + (long)r1 * DIMn);
    float4* O = (float4*)(out + t * DIMn);
    for (int i = threadIdx.x; i < DIMn / 4; i += blockDim.x) {
        float4 a = H[i];
        float2 s0 = __half22float2(SH[2 * i]),     s1 = __half22float2(SH[2 * i + 1]);
        float2 c0 = __half22float2(E0[2 * i]),     c1 = __half22float2(E0[2 * i + 1]);
        float2 d0 = __half22float2(E1[2 * i]),     d1 = __half22float2(E1[2 * i + 1]);
        float4 o;
        o.x = a.x + s0.x + g0 * c0.x + g1 * d0.x;
        o.y = a.y + s0.y + g0 * c0.y + g1 * d0.y;
        o.z = a.z + s1.x + g0 * c1.x + g1 * d1.x;
        o.w = a.w + s1.y + g0 * c1.y + g1 * d1.y;
        O[i] = o;
    }
}

// ---------------- host ----------------
#define SYM(p, s) do { void* _q = nullptr; cudaGetSymbolAddress(&_q, s); p = (decltype(p))_q; } while (0)

static void launch_hgemm(const __half* A, const __half* B, void* C, const float* addend,
                         int M, int N, int K, int lda, int ldb, int ldc,
                         long sA0, long sA1, long sB0, long sB1, long sC0, long sC1,
                         int ZH, int Z, const int* tileExpert, long wStride, int flags)
{
    dim3 grid((N + TNW - 1) / TNW, M / 128, Z);
    hgemm_k<<<grid, 256, HG_SMEM>>>(A, B, C, addend, M, N, K, lda, ldb, ldc,
        sA0, sA1, sB0, sB1, sC0, sC1, ZH, tileExpert, wStride, flags);
}

static void launch_cvt(const float* src, __half* dst, long n)
{
    long n4 = n / 4;
    int blocks = (int)((n4 / 4 + 255) / 256);
    if (blocks < 148) blocks = 148;
    cvt4_k<<<blocks, 256>>>((const float4*)src, (uint2*)dst, n4);
}

extern "C" void kernel_launch(void* const* d_in, const int* in_sizes, int n_in,
                              void* d_out, int out_size)
{
    cudaFuncSetAttribute(hgemm_k, cudaFuncAttributeMaxDynamicSharedMemorySize, HG_SMEM);
    cudaFuncSetAttribute(fattn_k, cudaFuncAttributeMaxDynamicSharedMemorySize, FA_SMEM);

    const float* x       = (const float*)d_in[0];
    const float* fcos    = (const float*)d_in[1];
    const float* fsin    = (const float*)d_in[2];
    const float* attn_w  = (const float*)d_in[3];
    const float* wq      = (const float*)d_in[4];
    const float* wkv_a   = (const float*)d_in[5];
    const float* kv_w    = (const float*)d_in[6];
    const float* wkv_b   = (const float*)d_in[7];
    const float* wo      = (const float*)d_in[8];
    const float* ffn_w   = (const float*)d_in[9];
    const float* rw      = (const float*)d_in[10];
    const float* e_w1    = (const float*)d_in[11];
    const float* e_w3    = (const float*)d_in[12];
    const float* e_w2    = (const float*)d_in[13];
    const float* s_w1    = (const float*)d_in[14];
    const float* s_w3    = (const float*)d_in[15];
    const float* s_w2    = (const float*)d_in[16];
    float* out = (float*)d_out;

    float *qkv, *kpe, *kvb, *h;
    __half *nx_h, *ckv_h, *qh, *kcat, *vT, *attn_h, *nh_h, *xg, *t13h, *t1h, *s13h, *s1h;
    __half *eo_h, *sh_h;
    __half *wqa_h, *wkvb_h, *wo_h, *ew13_h, *ew2_h, *sw13_h, *sw2_h;
    int *counts, *off, *tile_expert, *bucket_ts, *flat_tok, *tok2row;
    float *bucket_gate, *tok2gate;
    SYM(qkv, g_qkv); SYM(kpe, g_kpe); SYM(kvb, g_kvb); SYM(h, g_h);
    SYM(nx_h, g_nx_h); SYM(ckv_h, g_ckv_h); SYM(qh, g_qh); SYM(kcat, g_kcat_h);
    SYM(vT, g_vT_h); SYM(attn_h, g_attn_h); SYM(nh_h, g_nh_h);
    SYM(xg, g_xg_h); SYM(t13h, g_t13h); SYM(t1h, g_t1h); SYM(s13h, g_s13h); SYM(s1h, g_s1h);
    SYM(eo_h, g_eo_h); SYM(sh_h, g_sh_h);
    SYM(wqa_h, g_wqa_h); SYM(wkvb_h, g_wkvb_h); SYM(wo_h, g_wo_h);
    SYM(ew13_h, g_ew13_h); SYM(ew2_h, g_ew2_h); SYM(sw13_h, g_sw13_h); SYM(sw2_h, g_sw2_h);
    SYM(counts, g_counts); SYM(off, g_off); SYM(tile_expert, g_tile_expert);
    SYM(bucket_ts, g_bucket_ts); SYM(bucket_gate, g_bucket_gate);
    SYM(flat_tok, g_flat_tok); SYM(tok2row, g_tok2row); SYM(tok2gate, g_tok2gate);

    const long PE4 = (long)MINTERn * DIMn / 4;

    // 0. weight conversion (coalesced; wq and wkv_a concatenated)
    launch_cvt(wq, wqa_h, (long)QPROJ * DIMn);
    launch_cvt(wkv_a, wqa_h + (size_t)QPROJ * DIMn, (long)KVAP * DIMn);
    launch_cvt(wkv_b, wkvb_h, (long)KVBP * KVRn);
    launch_cvt(wo, wo_h, (long)DIMn * DIMn);
    {
        long tot4 = (long)NEn * PE4;
        int blocks = (int)((tot4 / 4 + 255) / 256);
        cvtmoe4_k<<<blocks, 256>>>((const float4*)e_w1, (uint2*)ew13_h, PE4, 2 * PE4, 0, tot4);
        cvtmoe4_k<<<blocks, 256>>>((const float4*)e_w3, (uint2*)ew13_h, PE4, 2 * PE4, PE4, tot4);
    }
    launch_cvt(e_w2, ew2_h, (long)NEn * DIMn * MINTERn);
    launch_cvt(s_w1, sw13_h, (long)SHIn * DIMn);
    launch_cvt(s_w3, sw13_h + (size_t)SHIn * DIMn, (long)SHIn * DIMn);
    launch_cvt(s_w2, sw2_h, (long)DIMn * SHIn);

    // 1. attention-input rmsnorm -> fp16
    rmsnorm_h<<<Tn, 256>>>(x, attn_w, nx_h, DIMn, DIMn, DIMn);
    // 2+3. fused q + kv_a projection (fp32 out, N=3648)
    launch_hgemm(nx_h, wqa_h, qkv, nullptr, Tn, QKVP, DIMn, DIMn, DIMn, QKVP,
                 0, 0, 0, 0, 0, 0, 1, 1, nullptr, 0, 0);
    // 4. c_kv rmsnorm -> fp16 (kv part of qkv)
    rmsnorm_h<<<Tn, 256>>>(qkv + QPROJ, kv_w, ckv_h, KVRn, QKVP, KVRn);
    // 5. rope k_pe (strided source inside qkv)
    rope_kpe_k<<<Tn, 32>>>(qkv + QPROJ + KVRn, QKVP, fcos, fsin, kpe);
    // 6. kv_b projection (fp32 out)
    launch_hgemm(ckv_h, wkvb_h, kvb, nullptr, Tn, KVBP, KVRn, KVRn, KVRn, KVBP,
                 0, 0, 0, 0, 0, 0, 1, 1, nullptr, 0, 0);
    // 7. rope + scale q -> fp16 (strided source inside qkv)
    ropescale_qh<<<Tn * NHn, 96>>>(qkv, fcos, fsin, qh);
    // 8. kcat + vT -> fp16
    { dim3 g(Sn, ZSn); kcat_h<<<g, QDn>>>(kvb, kpe, kcat); }
    { dim3 g(Sn / 32, VHn / 32, ZSn); dim3 b(32, 8); vtrans_h<<<g, b>>>(kvb, vT); }
    // 9-11. fused flash attention -> attn fp16
    { dim3 g(16, ZSn); fattn_k<<<g, 256, FA_SMEM>>>(qh, kcat, vT, attn_h); }
    // 12. h = x + attn @ wo^T
    launch_hgemm(attn_h, wo_h, h, x, Tn, DIMn, DIMn, DIMn, DIMn, DIMn,
                 0, 0, 0, 0, 0, 0, 1, 1, nullptr, 0, 1);
    // 13. ffn rmsnorm -> fp16
    rmsnorm_h<<<Tn, 256>>>(h, ffn_w, nh_h, DIMn, DIMn, DIMn);
    // 14. routing
    cudaMemsetAsync(counts, 0, NEn * sizeof(int), 0);
    cudaMemsetAsync(flat_tok, 0xFF, MOE_ROWS * sizeof(int), 0);
    router_h<<<Tn, 256>>>(nh_h, rw, counts, bucket_ts, bucket_gate);
    offsets_k<<<1, 1>>>(counts, off, tile_expert);
    compact_k<<<NEn, 256>>>(counts, off, bucket_ts, bucket_gate, flat_tok, tok2row, tok2gate);
    gather_h<<<MOE_ROWS, 256>>>(nh_h, flat_tok, xg);
    // 15. expert FFN (grouped, fused w1||w3; fp16 eo)
    launch_hgemm(xg, ew13_h, t13h, nullptr, MOE_ROWS, 2 * MINTERn, DIMn,
                 DIMn, DIMn, 2 * MINTERn,
                 0, 0, 0, 0, 0, 0, 1, 1, tile_expert, 2L * MINTERn * DIMn, 8);
    {
        long n2 = (long)MOE_ROWS * MINTERn / 2;
        silumul2_h<<<(int)((n2 + 255) / 256), 256>>>(t13h, t1h, MINTERn, MOE_ROWS);
    }
    launch_hgemm(t1h, ew2_h, eo_h, nullptr, MOE_ROWS, DIMn, MINTERn, MINTERn, MINTERn, DIMn,
                 0, 0, 0, 0, 0, 0, 1, 1, tile_expert, (long)DIMn * MINTERn, 8);
    // 16. shared FFN (fused w1||w3; fp16 sh)
    launch_hgemm(nh_h, sw13_h, s13h, nullptr, Tn, 2 * SHIn, DIMn, DIMn, DIMn, 2 * SHIn,
                 0, 0, 0, 0, 0, 0, 1, 1, nullptr, 0, 8);
    {
        long n2 = (long)Tn * SHIn / 2;
        silumul2_h<<<(int)((n2 + 255) / 256), 256>>>(s13h, s1h, SHIn, Tn);
    }
    launch_hgemm(s1h, sw2_h, sh_h, nullptr, Tn, DIMn, SHIn, SHIn, SHIn, DIMn,
                 0, 0, 0, 0, 0, 0, 1, 1, nullptr, 0, 8);
    // 17. combine
    combine_k<<<Tn, 256>>>(h, sh_h, eo_h, tok2row, tok2gate, out);
}

// round 17
// speedup vs baseline: 1.5281x; 1.0060x over previous
#include <cuda_runtime.h>
#include <cuda_fp16.h>
#include <math.h>
#include <stdint.h>
#include <string.h>

// ---------------- problem constants ----------------
#define Tn     4096
#define Sn     2048
#define DIMn   2048
#define NHn    16
#define NOPEn  128
#define ROPEn  64
#define QDn    192
#define VHn    128
#define KVRn   512
#define NEn    8
#define MINTERn 1408
#define SHIn   2816
#define QPROJ  3072
#define KVAP   576
#define QKVP   3648            // QPROJ + KVAP
#define KVBP   4096
#define MOE_ROWS 9216
#define MOE_TILES 72
#define ZSn    32

// ---------------- fp32 scratch ----------------
__device__ float g_qkv[(size_t)Tn*QKVP];
__device__ float g_kpe[(size_t)Tn*ROPEn];
__device__ float g_kvb[(size_t)Tn*KVBP];
__device__ float g_h[(size_t)Tn*DIMn];
__device__ int   g_counts[NEn];
__device__ int   g_off[NEn+1];
__device__ int   g_tile_expert[MOE_TILES];
__device__ int   g_bucket_ts[NEn*Tn];
__device__ float g_bucket_gate[NEn*Tn];
__device__ int   g_flat_tok[MOE_ROWS];
__device__ int   g_tok2row[Tn*2];
__device__ float g_tok2gate[Tn*2];
// ---------------- fp16 scratch ----------------
__device__ __half g_nx_h[(size_t)Tn*DIMn];
__device__ __half g_ckv_h[(size_t)Tn*KVRn];
__device__ __half g_qh[(size_t)Tn*QPROJ];
__device__ __half g_kcat_h[(size_t)ZSn*Sn*QDn];
__device__ __half g_vT_h[(size_t)ZSn*VHn*Sn];
__device__ __half g_attn_h[(size_t)Tn*DIMn];
__device__ __half g_nh_h[(size_t)Tn*DIMn];
__device__ __half g_xg_h[(size_t)MOE_ROWS*DIMn];
__device__ __half g_t13h[(size_t)MOE_ROWS*2*MINTERn];
__device__ __half g_t1h[(size_t)MOE_ROWS*MINTERn];
__device__ __half g_s13h[(size_t)Tn*2*SHIn];
__device__ __half g_s1h[(size_t)Tn*SHIn];
__device__ __half g_eo_h[(size_t)MOE_ROWS*DIMn];
__device__ __half g_sh_h[(size_t)Tn*DIMn];
// fp16 weight copies
__device__ __half g_wqa_h[(size_t)QKVP*DIMn];
__device__ __half g_wkvb_h[(size_t)KVBP*KVRn];
__device__ __half g_wo_h[(size_t)DIMn*DIMn];
__device__ __half g_ew13_h[(size_t)NEn*2*MINTERn*DIMn];
__device__ __half g_ew2_h[(size_t)NEn*DIMn*MINTERn];
__device__ __half g_sw13_h[(size_t)2*SHIn*DIMn];
__device__ __half g_sw2_h[(size_t)DIMn*SHIn];

// ---------------- helpers ----------------
__device__ __forceinline__ uint32_t h2u(__half2 h) {
    uint32_t u; memcpy(&u, &h, 4); return u;
}
__device__ __forceinline__ void mma16(float* c, const uint32_t* a, const uint32_t* b) {
    asm volatile("mma.sync.aligned.m16n8k16.row.col.f32.f16.f16.f32 "
        "{%0,%1,%2,%3}, {%4,%5,%6,%7}, {%8,%9}, {%0,%1,%2,%3};"
        : "+f"(c[0]), "+f"(c[1]), "+f"(c[2]), "+f"(c[3])
        : "r"(a[0]), "r"(a[1]), "r"(a[2]), "r"(a[3]), "r"(b[0]), "r"(b[1]));
}
__device__ __forceinline__ void ldsm4(uint32_t* r, uint32_t addr) {
    asm volatile("ldmatrix.sync.aligned.m8n8.x4.shared.b16 {%0,%1,%2,%3}, [%4];"
        : "=r"(r[0]), "=r"(r[1]), "=r"(r[2]), "=r"(r[3]) : "r"(addr));
}
__device__ __forceinline__ void cpasync16(uint32_t dst, const void* src, int sz) {
    asm volatile("cp.async.cg.shared.global [%0], [%1], 16, %2;"
                 :: "r"(dst), "l"(src), "r"(sz));
}
__device__ __forceinline__ void cpcommit() { asm volatile("cp.async.commit_group;"); }
__device__ __forceinline__ void cpwait1() { asm volatile("cp.async.wait_group 1;"); }
__device__ __forceinline__ void cpwait2() { asm volatile("cp.async.wait_group 2;"); }

// ---------------- fp16 tensor GEMM, 128x128 CTA, 4-stage, 2 CTAs/SM ----------------
// flags: 1 add addend(fp32 out), 8 fp16 out
#define LDPH 20
#define AROWB (LDPH*4)               // 80 bytes
#define TNW 128
#define NTT 4
#define ABY (128*AROWB)
#define STG (2*ABY)
#define HG_SMEM (4*STG)              // 81920 B

__global__ __launch_bounds__(256, 2) void hgemm_k(
    const __half* __restrict__ A, const __half* __restrict__ B, void* __restrict__ Cv,
    const float* __restrict__ addend,
    int M, int N, int K, int lda, int ldb, int ldc,
    long sA0, long sA1, long sB0, long sB1, long sC0, long sC1, int ZH,
    const int* __restrict__ tileExpert, long wStride, int flags)
{
    int bx = blockIdx.x, by = blockIdx.y, z = blockIdx.z;
    if (tileExpert) { int te = tileExpert[by]; if (te < 0) return; B += (long)te * wStride; }
    int zb = z / ZH, zh = z - zb * ZH;
    A += zb * sA0 + (long)zh * sA1;
    B += zb * sB0 + (long)zh * sB1;
    int NT = K >> 5;

    extern __shared__ char smraw[];
    uint32_t sb = (uint32_t)__cvta_generic_to_shared(smraw);

    int tid = threadIdx.x;
    int wid = tid >> 5, lane = tid & 31;
    int wy = wid & 1, wx = wid >> 1;

    int grp = lane >> 3, lrow = lane & 7;
    uint32_t aoff = (uint32_t)((wy * 64 + (grp & 1) * 8 + lrow) * AROWB + (grp >> 1) * 16);
    uint32_t boff = (uint32_t)((wx * 32 + (grp >> 1) * 8 + lrow) * AROWB + (grp & 1) * 16);

    int ar0 = tid >> 2, ac0 = tid & 3;
    int bsz[2];
#pragma unroll
    for (int ch = 0; ch < 2; ch++) {
        int row = ar0 + ch * 64;
        bsz[ch] = ((bx * TNW + row) < N) ? 16 : 0;
    }
    const __half* bsrc0 = B;

    auto issue = [&](int s, int k0) {
        uint32_t Ab = sb + s * STG;
        uint32_t Bb = Ab + ABY;
#pragma unroll
        for (int ch = 0; ch < 2; ch++) {
            int row = ar0 + ch * 64;
            const __half* src = A + (long)(by * 128 + row) * lda + k0 + ac0 * 8;
            cpasync16(Ab + row * AROWB + ac0 * 16, src, 16);
        }
#pragma unroll
        for (int ch = 0; ch < 2; ch++) {
            int row = ar0 + ch * 64;
            const __half* src = bsz[ch] ? (B + (long)(bx * TNW + row) * ldb + k0 + ac0 * 8) : bsrc0;
            cpasync16(Bb + row * AROWB + ac0 * 16, src, bsz[ch]);
        }
    };

#pragma unroll
    for (int s = 0; s < 3; s++) {
        if (s < NT) issue(s, s * 32);
        cpcommit();
    }

    float acc[4][NTT][4];
#pragma unroll
    for (int mt = 0; mt < 4; mt++)
#pragma unroll
        for (int nt = 0; nt < NTT; nt++)
#pragma unroll
            for (int i = 0; i < 4; i++) acc[mt][nt][i] = 0.f;

    for (int it = 0; it < NT; ++it) {
        cpwait2();
        __syncthreads();
        if (it + 3 < NT) issue((it + 3) & 3, (it + 3) * 32);
        cpcommit();

        int st = it & 3;
        uint32_t Abase = sb + st * STG + aoff;
        uint32_t Bbase = sb + st * STG + ABY + boff;
#pragma unroll
        for (int ks = 0; ks < 2; ks++) {
            uint32_t af[4][4], bf[NTT][2];
#pragma unroll
            for (int mt = 0; mt < 4; mt++)
                ldsm4(af[mt], Abase + mt * (16 * AROWB) + ks * 32);
#pragma unroll
            for (int p = 0; p < NTT / 2; p++) {
                uint32_t r[4];
                ldsm4(r, Bbase + p * (16 * AROWB) + ks * 32);
                bf[2 * p][0] = r[0]; bf[2 * p][1] = r[1];
                bf[2 * p + 1][0] = r[2]; bf[2 * p + 1][1] = r[3];
            }
#pragma unroll
            for (int mt = 0; mt < 4; mt++)
#pragma unroll
                for (int nt = 0; nt < NTT; nt++)
                    mma16(acc[mt][nt], af[mt], bf[nt]);
        }
        // NOTE: no trailing __syncthreads(). Stage (it+3)&3 written at the next
        // iteration was last read at it-1; the top barrier of the next iteration
        // already orders those reads before the overwrite.
    }

    bool doadd = (flags & 1) != 0;
    bool outh = (flags & 8) != 0;
    float* Cf = (float*)Cv + zb * sC0 + (long)zh * sC1;
    __half* Ch = (__half*)Cv + zb * sC0 + (long)zh * sC1;
    const float* Af = addend ? (addend + zb * sC0 + (long)zh * sC1) : nullptr;
    int elr = lane >> 2, elk = lane & 3;
#pragma unroll
    for (int mt = 0; mt < 4; mt++) {
        int m0 = by * 128 + wy * 64 + mt * 16 + elr;
#pragma unroll
        for (int nt = 0; nt < NTT; nt++) {
            int c0 = bx * TNW + wx * 32 + nt * 8 + 2 * elk;
            if (c0 < N) {
                float2 v0 = make_float2(acc[mt][nt][0], acc[mt][nt][1]);
                float2 v1 = make_float2(acc[mt][nt][2], acc[mt][nt][3]);
                if (outh) {
                    *(__half2*)(Ch + (long)m0 * ldc + c0) = __float22half2_rn(v0);
                    *(__half2*)(Ch + (long)(m0 + 8) * ldc + c0) = __float22half2_rn(v1);
                } else {
                    if (doadd) {
                        float2 o0 = *(const float2*)(Af + (long)m0 * ldc + c0);
                        float2 o1 = *(const float2*)(Af + (long)(m0 + 8) * ldc + c0);
                        v0.x += o0.x; v0.y += o0.y; v1.x += o1.x; v1.y += o1.y;
                    }
                    *(float2*)(Cf + (long)m0 * ldc + c0) = v0;
                    *(float2*)(Cf + (long)(m0 + 8) * ldc + c0) = v1;
                }
            }
        }
    }
}

// ---------------- fused flash attention ----------------
#define QROWB 400
#define VROWB 272
#define FA_QS 0
#define FA_KS (128*QROWB)
#define FA_VS (2*128*QROWB)
#define FA_PS (FA_VS + 128*VROWB)
#define FA_RA (FA_PS + 128*VROWB)
#define FA_RB (FA_RA + 2048)
#define FA_SMEM (FA_RB + 2048)

__global__ __launch_bounds__(256) void fattn_k(
    const __half* __restrict__ qh, const __half* __restrict__ kcat,
    const __half* __restrict__ vT, __half* __restrict__ attn)
{
    int by = (int)gridDim.x - 1 - blockIdx.x;
    int z = blockIdx.y;
    int zb = z >> 4, zh = z & 15;

    extern __shared__ char smraw[];
    uint32_t sb = (uint32_t)__cvta_generic_to_shared(smraw);
    float* rowA = (float*)(smraw + FA_RA);
    float* rowB = (float*)(smraw + FA_RB);

    int tid = threadIdx.x;
    int wid = tid >> 5, lane = tid & 31;
    int wy = wid & 1, wx = wid >> 1;
    int grp = lane >> 3, lrow = lane & 7;
    int elr = lane >> 2, elk = lane & 3;

    uint32_t aoffQ = (uint32_t)((wy * 64 + (grp & 1) * 8 + lrow) * QROWB + (grp >> 1) * 16);
    uint32_t boffK = (uint32_t)((wx * 32 + (grp >> 1) * 8 + lrow) * QROWB + (grp & 1) * 16);
    uint32_t aoffP = (uint32_t)((wy * 64 + (grp & 1) * 8 + lrow) * VROWB + (grp >> 1) * 16);
    uint32_t boffV = (uint32_t)((wx * 32 + (grp >> 1) * 8 + lrow) * VROWB + (grp & 1) * 16);

    const __half* Qg = qh + ((long)zb * Sn + (long)by * 128) * QPROJ + zh * QDn;
    const __half* Kg = kcat + (long)z * Sn * QDn;
    const __half* Vg = vT + (long)z * VHn * Sn;

    auto issueK = [&](int kb) {
#pragma unroll
        for (int ch = 0; ch < 12; ch++) {
            int idx = tid + ch * 256;
            int row = idx / 24, cq = idx - row * 24;
            cpasync16(sb + FA_KS + row * QROWB + cq * 16,
                      Kg + ((long)kb * 128 + row) * QDn + cq * 8, 16);
        }
    };
    auto issueV = [&](int kb) {
#pragma unroll
        for (int ch = 0; ch < 8; ch++) {
            int idx = tid + ch * 256;
            int row = idx >> 4, cq = idx & 15;
            cpasync16(sb + FA_VS + row * VROWB + cq * 16,
                      Vg + (long)row * Sn + kb * 128 + cq * 8, 16);
        }
    };

#pragma unroll
    for (int ch = 0; ch < 12; ch++) {
        int idx = tid + ch * 256;
        int row = idx / 24, cq = idx - row * 24;
        cpasync16(sb + FA_QS + row * QROWB + cq * 16, Qg + (long)row * QPROJ + cq * 8, 16);
    }
    cpcommit();
    issueK(0); cpcommit();
    issueV(0); cpcommit();

    float accO[4][4][4];
    float mold[4][2], lrun[4][2];
#pragma unroll
    for (int mt = 0; mt < 4; mt++) {
#pragma unroll
        for (int nt = 0; nt < 4; nt++)
#pragma unroll
            for (int i = 0; i < 4; i++) accO[mt][nt][i] = 0.f;
        mold[mt][0] = -3.4e38f; mold[mt][1] = -3.4e38f;
        lrun[mt][0] = 0.f; lrun[mt][1] = 0.f;
    }

    for (int kb = 0; kb <= by; kb++) {
        cpwait1();
        __syncthreads();

        float accS[4][4][4];
#pragma unroll
        for (int mt = 0; mt < 4; mt++)
#pragma unroll
            for (int nt = 0; nt < 4; nt++)
#pragma unroll
                for (int i = 0; i < 4; i++) accS[mt][nt][i] = 0.f;
#pragma unroll
        for (int ks = 0; ks < 12; ks++) {
            uint32_t af[4][4], bf[4][2];
#pragma unroll
            for (int mt = 0; mt < 4; mt++)
                ldsm4(af[mt], sb + FA_QS + aoffQ + mt * (16 * QROWB) + ks * 32);
#pragma unroll
            for (int p = 0; p < 2; p++) {
                uint32_t r[4];
                ldsm4(r, sb + FA_KS + boffK + p * (16 * QROWB) + ks * 32);
                bf[2 * p][0] = r[0]; bf[2 * p][1] = r[1];
                bf[2 * p + 1][0] = r[2]; bf[2 * p + 1][1] = r[3];
            }
#pragma unroll
            for (int mt = 0; mt < 4; mt++)
#pragma unroll
                for (int nt = 0; nt < 4; nt++)
                    mma16(accS[mt][nt], af[mt], bf[nt]);
        }
        if (kb == by) {
#pragma unroll
            for (int mt = 0; mt < 4; mt++) {
                int r0 = wy * 64 + mt * 16 + elr, r1 = r0 + 8;
#pragma unroll
                for (int nt = 0; nt < 4; nt++) {
                    int c = wx * 32 + nt * 8 + 2 * elk;
                    if (c > r0)     accS[mt][nt][0] = -3.4e38f;
                    if (c + 1 > r0) accS[mt][nt][1] = -3.4e38f;
                    if (c > r1)     accS[mt][nt][2] = -3.4e38f;
                    if (c + 1 > r1) accS[mt][nt][3] = -3.4e38f;
                }
            }
        }
        float lmax[4][2];
#pragma unroll
        for (int mt = 0; mt < 4; mt++) {
            float a = -3.4e38f, b = -3.4e38f;
#pragma unroll
            for (int nt = 0; nt < 4; nt++) {
                a = fmaxf(a, fmaxf(accS[mt][nt][0], accS[mt][nt][1]));
                b = fmaxf(b, fmaxf(accS[mt][nt][2], accS[mt][nt][3]));
            }
            lmax[mt][0] = a; lmax[mt][1] = b;
        }
#pragma unroll
        for (int off = 1; off <= 2; off <<= 1)
#pragma unroll
            for (int mt = 0; mt < 4; mt++) {
                lmax[mt][0] = fmaxf(lmax[mt][0], __shfl_xor_sync(0xffffffffu, lmax[mt][0], off));
                lmax[mt][1] = fmaxf(lmax[mt][1], __shfl_xor_sync(0xffffffffu, lmax[mt][1], off));
            }
        if (elk == 0) {
#pragma unroll
            for (int mt = 0; mt < 4; mt++) {
                int m = wy * 64 + mt * 16 + elr;
                rowA[wx * 128 + m] = lmax[mt][0];
                rowA[wx * 128 + m + 8] = lmax[mt][1];
            }
        }
        __syncthreads();
        if (kb + 1 <= by) issueK(kb + 1);
        cpcommit();

        float mnew[4][2];
#pragma unroll
        for (int mt = 0; mt < 4; mt++) {
#pragma unroll
            for (int hf = 0; hf < 2; hf++) {
                int m = wy * 64 + mt * 16 + elr + hf * 8;
                float v = fmaxf(fmaxf(rowA[m], rowA[128 + m]),
                                fmaxf(rowA[256 + m], rowA[384 + m]));
                mnew[mt][hf] = fmaxf(mold[mt][hf], v);
            }
        }
        float lsum[4][2];
#pragma unroll
        for (int mt = 0; mt < 4; mt++) { lsum[mt][0] = 0.f; lsum[mt][1] = 0.f; }
#pragma unroll
        for (int mt = 0; mt < 4; mt++) {
            int r0 = wy * 64 + mt * 16 + elr;
#pragma unroll
            for (int nt = 0; nt < 4; nt++) {
                int c = wx * 32 + nt * 8 + 2 * elk;
                float p0 = __expf(accS[mt][nt][0] - mnew[mt][0]);
                float p1 = __expf(accS[mt][nt][1] - mnew[mt][0]);
                float p2 = __expf(accS[mt][nt][2] - mnew[mt][1]);
                float p3 = __expf(accS[mt][nt][3] - mnew[mt][1]);
                lsum[mt][0] += p0 + p1;
                lsum[mt][1] += p2 + p3;
                *(__half2*)(smraw + FA_PS + r0 * VROWB + c * 2) =
                    __float22half2_rn(make_float2(p0, p1));
                *(__half2*)(smraw + FA_PS + (r0 + 8) * VROWB + c * 2) =
                    __float22half2_rn(make_float2(p2, p3));
            }
        }
#pragma unroll
        for (int off = 1; off <= 2; off <<= 1)
#pragma unroll
            for (int mt = 0; mt < 4; mt++) {
                lsum[mt][0] += __shfl_xor_sync(0xffffffffu, lsum[mt][0], off);
                lsum[mt][1] += __shfl_xor_sync(0xffffffffu, lsum[mt][1], off);
            }
        if (elk == 0) {
#pragma unroll
            for (int mt = 0; mt < 4; mt++) {
                int m = wy * 64 + mt * 16 + elr;
                rowB[wx * 128 + m] = lsum[mt][0];
                rowB[wx * 128 + m + 8] = lsum[mt][1];
            }
        }
        cpwait1();
        __syncthreads();

#pragma unroll
        for (int mt = 0; mt < 4; mt++) {
#pragma unroll
            for (int hf = 0; hf < 2; hf++) {
                int m = wy * 64 + mt * 16 + elr + hf * 8;
                float rs = rowB[m] + rowB[128 + m] + rowB[256 + m] + rowB[384 + m];
                float fsc = __expf(mold[mt][hf] - mnew[mt][hf]);
                lrun[mt][hf] = lrun[mt][hf] * fsc + rs;
                mold[mt][hf] = mnew[mt][hf];
#pragma unroll
                for (int nt = 0; nt < 4; nt++) {
                    accO[mt][nt][hf * 2 + 0] *= fsc;
                    accO[mt][nt][hf * 2 + 1] *= fsc;
                }
            }
        }
#pragma unroll
        for (int ks = 0; ks < 8; ks++) {
            uint32_t af[4][4], bf[4][2];
#pragma unroll
            for (int mt = 0; mt < 4; mt++)
                ldsm4(af[mt], sb + FA_PS + aoffP + mt * (16 * VROWB) + ks * 32);
#pragma unroll
            for (int p = 0; p < 2; p++) {
                uint32_t r[4];
                ldsm4(r, sb + FA_VS + boffV + p * (16 * VROWB) + ks * 32);
                bf[2 * p][0] = r[0]; bf[2 * p][1] = r[1];
                bf[2 * p + 1][0] = r[2]; bf[2 * p + 1][1] = r[3];
            }
#pragma unroll
            for (int mt = 0; mt < 4; mt++)
#pragma unroll
                for (int nt = 0; nt < 4; nt++)
                    mma16(accO[mt][nt], af[mt], bf[nt]);
        }
        __syncthreads();
        if (kb + 1 <= by) issueV(kb + 1);
        cpcommit();
    }

    __half* Og = attn + (long)zb * Sn * DIMn + zh * VHn;
#pragma unroll
    for (int mt = 0; mt < 4; mt++) {
        float i0 = 1.f / lrun[mt][0], i1 = 1.f / lrun[mt][1];
        int m = by * 128 + wy * 64 + mt * 16 + elr;
#pragma unroll
        for (int nt = 0; nt < 4; nt++) {
            int d = wx * 32 + nt * 8 + 2 * elk;
            *(__half2*)(Og + (long)m * DIMn + d) =
                __float22half2_rn(make_float2(accO[mt][nt][0] * i0, accO[mt][nt][1] * i0));
            *(__half2*)(Og + (long)(m + 8) * DIMn + d) =
                __float22half2_rn(make_float2(accO[mt][nt][2] * i1, accO[mt][nt][3] * i1));
        }
    }
}

// ---------------- coalesced weight fp32 -> fp16 (grid-stride) ----------------
__global__ void cvt4_k(const float4* __restrict__ src, uint2* __restrict__ dst, long n4)
{
    long stride = (long)gridDim.x * blockDim.x;
    for (long i = (long)blockIdx.x * blockDim.x + threadIdx.x; i < n4; i += stride) {
        float4 a = src[i];
        uint2 o;
        o.x = h2u(__floats2half2_rn(a.x, a.y));
        o.y = h2u(__floats2half2_rn(a.z, a.w));
        dst[i] = o;
    }
}
__global__ void cvtmoe4_k(const float4* __restrict__ src, uint2* __restrict__ dst,
                          long perExp4, long dstStride4, long dstOff4, long total4)
{
    long stride = (long)gridDim.x * blockDim.x;
    for (long i = (long)blockIdx.x * blockDim.x + threadIdx.x; i < total4; i += stride) {
        long e = i / perExp4, r = i - e * perExp4;
        float4 a = src[i];
        uint2 o;
        o.x = h2u(__floats2half2_rn(a.x, a.y));
        o.y = h2u(__floats2half2_rn(a.z, a.w));
        dst[e * dstStride4 + dstOff4 + r] = o;
    }
}

// ---------------- reductions ----------------
__device__ __forceinline__ float warpSum(float v) {
#pragma unroll
    for (int o = 16; o; o >>= 1) v += __shfl_xor_sync(0xffffffffu, v, o);
    return v;
}

// ---------------- rmsnorm: fp32 in -> fp16 out ----------------
__global__ void rmsnorm_h(const float* __restrict__ x, const float* __restrict__ w,
                          __half* __restrict__ y, int D, int ldx, int ldy)
{
    long t = blockIdx.x;
    const float* xr = x + t * ldx;
    __half* yr = y + t * ldy;
    float s = 0.f;
    for (int d = threadIdx.x; d < D; d += blockDim.x) { float v = xr[d]; s += v * v; }
    __shared__ float sh[32];
    __shared__ float bc;
    s = warpSum(s);
    int lane = threadIdx.x & 31, wp = threadIdx.x >> 5;
    if (!lane) sh[wp] = s;
    __syncthreads();
    if (threadIdx.x < 32) {
        float r = (threadIdx.x < (blockDim.x >> 5)) ? sh[threadIdx.x] : 0.f;
        r = warpSum(r);
        if (!threadIdx.x) bc = rsqrtf(r / D + 1e-6f);
    }
    __syncthreads();
    float sc = bc;
    for (int d = threadIdx.x; d < D; d += blockDim.x)
        yr[d] = __float2half_rn(xr[d] * sc * w[d]);
}

// ---------------- rope on k_pe (fp32, strided source) ----------------
__global__ void rope_kpe_k(const float* __restrict__ kvsrc, int ld,
                           const float* __restrict__ fc, const float* __restrict__ fs,
                           float* __restrict__ kpe)
{
    long t = blockIdx.x;
    int j = threadIdx.x;
    int pos = (int)(t % Sn);
    float x1 = kvsrc[t * (long)ld + 2 * j];
    float x2 = kvsrc[t * (long)ld + 2 * j + 1];
    float c = fc[pos * 32 + j], s = fs[pos * 32 + j];
    kpe[t * ROPEn + 2 * j]     = x1 * c - x2 * s;
    kpe[t * ROPEn + 2 * j + 1] = x1 * s + x2 * c;
}

// ---------------- rope + scale on q: fp32 (strided) in -> fp16 out ----------------
__global__ void ropescale_qh(const float* __restrict__ qkv, const float* __restrict__ fc,
                             const float* __restrict__ fs, __half* __restrict__ qh)
{
    long th = blockIdx.x;
    long t = th >> 4;
    int hh = (int)(th & 15);
    int pos = (int)(t % Sn);
    const float* r = qkv + t * QKVP + hh * QDn;
    __half* o = qh + th * QDn;
    int i = threadIdx.x;
    const float sc = 0.07216878364870322f;   // 1/sqrt(192)
    if (i < 64) {
        o[2 * i]     = __float2half_rn(r[2 * i] * sc);
        o[2 * i + 1] = __float2half_rn(r[2 * i + 1] * sc);
    } else {
        int j = i - 64;
        float x1 = r[128 + 2 * j], x2 = r[128 + 2 * j + 1];
        float c = fc[pos * 32 + j], s = fs[pos * 32 + j];
        o[128 + 2 * j]     = __float2half_rn((x1 * c - x2 * s) * sc);
        o[128 + 2 * j + 1] = __float2half_rn((x1 * s + x2 * c) * sc);
    }
}

// ---------------- [k_nope | k_pe] concat -> fp16 ----------------
__global__ void kcat_h(const float* __restrict__ kvb, const float* __restrict__ kpe,
                       __half* __restrict__ kcat)
{
    int s = blockIdx.x, z = blockIdx.y, j = threadIdx.x;
    long t = (long)(z >> 4) * Sn + s;
    float v = (j < NOPEn) ? kvb[t * KVBP + (z & 15) * 256 + j]
                          : kpe[t * ROPEn + (j - NOPEn)];
    kcat[((long)z * Sn + s) * QDn + j] = __float2half_rn(v);
}

// ---------------- transpose V -> vT fp16 ----------------
__global__ void vtrans_h(const float* __restrict__ kvb, __half* __restrict__ vT)
{
    __shared__ float tsm[32][33];
    int z = blockIdx.z, zb = z >> 4, zh = z & 15;
    int kt = blockIdx.x * 32, dt = blockIdx.y * 32;
    int tx = threadIdx.x, ty = threadIdx.y;
#pragma unroll
    for (int i = 0; i < 4; i++) {
        int k = kt + ty + i * 8;
        tsm[ty + i * 8][tx] = kvb[((long)zb * Sn + k) * KVBP + zh * 256 + NOPEn + dt + tx];
    }
    __syncthreads();
#pragma unroll
    for (int i = 0; i < 4; i++) {
        int d = dt + ty + i * 8;
        vT[((long)z * VHn + d) * Sn + kt + tx] = __float2half_rn(tsm[tx][ty + i * 8]);
    }
}

// ---------------- router (reads fp16 nh) ----------------
__global__ void router_h(const __half* __restrict__ nh, const float* __restrict__ rw,
                         int* __restrict__ counts, int* __restrict__ bucket_ts,
                         float* __restrict__ bucket_gate)
{
    long t = blockIdx.x;
    int wp = threadIdx.x >> 5, lane = threadIdx.x & 31;
    const __half* xr = nh + t * DIMn;
    float s = 0.f;
    for (int d = lane; d < DIMn; d += 32) s += __half2float(xr[d]) * rw[(long)wp * DIMn + d];
    s = warpSum(s);
    __shared__ float logit[NEn];
    if (!lane) logit[wp] = s;
    __syncthreads();
    if (threadIdx.x == 0) {
        float mx = logit[0];
#pragma unroll
        for (int e = 1; e < NEn; e++) mx = fmaxf(mx, logit[e]);
        float p[NEn];
#pragma unroll
        for (int e = 0; e < NEn; e++) p[e] = expf(logit[e] - mx);
        int i0 = 0;
#pragma unroll
        for (int e = 1; e < NEn; e++) if (p[e] > p[i0]) i0 = e;
        int i1 = (i0 == 0) ? 1 : 0;
#pragma unroll
        for (int e = 0; e < NEn; e++) if (e != i0 && p[e] > p[i1]) i1 = e;
        float denom = p[i0] + p[i1];
        float g0 = p[i0] / denom, g1 = p[i1] / denom;
        int pos0 = atomicAdd(&counts[i0], 1);
        bucket_ts[i0 * Tn + pos0] = (int)(t * 2);
        bucket_gate[i0 * Tn + pos0] = g0;
        int pos1 = atomicAdd(&counts[i1], 1);
        bucket_ts[i1 * Tn + pos1] = (int)(t * 2 + 1);
        bucket_gate[i1 * Tn + pos1] = g1;
    }
}

__global__ void offsets_k(const int* __restrict__ counts, int* __restrict__ off,
                          int* __restrict__ tile_expert)
{
    for (int tl = 0; tl < MOE_TILES; tl++) tile_expert[tl] = -1;
    int o = 0;
    for (int e = 0; e < NEn; e++) {
        off[e] = o;
        int nt = (counts[e] + 127) >> 7;
        for (int i = 0; i < nt; i++) tile_expert[(o >> 7) + i] = e;
        o += nt * 128;
    }
    off[NEn] = o;
}

__global__ void compact_k(const int* __restrict__ counts, const int* __restrict__ off,
                          const int* __restrict__ bucket_ts, const float* __restrict__ bucket_gate,
                          int* __restrict__ flat_tok, int* __restrict__ tok2row,
                          float* __restrict__ tok2gate)
{
    int e = blockIdx.x;
    int cnt = counts[e], base = off[e];
    for (int i = threadIdx.x; i < cnt; i += blockDim.x) {
        int ts = bucket_ts[e * Tn + i];
        int r = base + i;
        flat_tok[r] = ts >> 1;
        tok2row[ts] = r;
        tok2gate[ts] = bucket_gate[e * Tn + i];
    }
}

__global__ void gather_h(const __half* __restrict__ nh, const int* __restrict__ flat_tok,
                         __half* __restrict__ xg)
{
    long r = blockIdx.x;
    int t = flat_tok[r];
    uint4* dst = (uint4*)(xg + r * DIMn);
    int nch = DIMn / 8;
    if (t < 0) {
        uint4 zz = make_uint4(0u, 0u, 0u, 0u);
        for (int i = threadIdx.x; i < nch; i += blockDim.x) dst[i] = zz;
    } else {
        const uint4* src = (const uint4*)(nh + (long)t * DIMn);
        for (int i = threadIdx.x; i < nch; i += blockDim.x) dst[i] = src[i];
    }
}

__global__ void silumul2_h(const __half* __restrict__ t13, __half* __restrict__ outp,
                           int inter, long rows)
{
    long h2pr = inter / 2;
    long i = (long)blockIdx.x * blockDim.x + threadIdx.x;
    if (i < rows * h2pr) {
        long r = i / h2pr, j = i - r * h2pr;
        const __half2* pa = (const __half2*)(t13 + (size_t)r * 2 * inter);
        const __half2* pb = (const __half2*)(t13 + (size_t)r * 2 * inter + inter);
        float2 x = __half22float2(pa[j]);
        float2 y = __half22float2(pb[j]);
        float s0 = x.x / (1.f + expf(-x.x));
        float s1 = x.y / (1.f + expf(-x.y));
        ((__half2*)(outp + (size_t)r * inter))[j] =
            __float22half2_rn(make_float2(s0 * y.x, s1 * y.y));
    }
}

// ---------------- combine: h fp32 + sh fp16 + gated eo fp16 ----------------
__global__ void combine_k(const float* __restrict__ h, const __half* __restrict__ sh,
                          const __half* __restrict__ eo, const int* __restrict__ tok2row,
                          const float* __restrict__ tok2gate, float* __restrict__ out)
{
    long t = blockIdx.x;
    int r0 = tok2row[t * 2], r1 = tok2row[t * 2 + 1];
    float g0 = tok2gate[t * 2], g1 = tok2gate[t * 2 + 1];
    const float4* H = (const float4*)(h + t * DIMn);
    const __half2* SH = (const __half2*)(sh + t * DIMn);
    const __half2* E0 = (const __half2*)(eo + (long)r0 * DIMn);
    const __half2* E1 = (const __half2*)(eo + (long)r1 * DIMn);
    float4* O = (float4*)(out + t * DIMn);
    for (int i = threadIdx.x; i < DIMn / 4; i += blockDim.x) {
        float4 a = H[i];
        float2 s0 = __half22float2(SH[2 * i]),     s1 = __half22float2(SH[2 * i + 1]);
        float2 c0 = __half22float2(E0[2 * i]),     c1 = __half22float2(E0[2 * i + 1]);
        float2 d0 = __half22float2(E1[2 * i]),     d1 = __half22float2(E1[2 * i + 1]);
        float4 o;
        o.x = a.x + s0.x + g0 * c0.x + g1 * d0.x;
        o.y = a.y + s0.y + g0 * c0.y + g1 * d0.y;
        o.z = a.z + s1.x + g0 * c1.x + g1 * d1.x;
        o.w = a.w + s1.y + g0 * c1.y + g1 * d1.y;
        O[i] = o;
    }
}

// ---------------- host ----------------
#define SYM(p, s) do { void* _q = nullptr; cudaGetSymbolAddress(&_q, s); p = (decltype(p))_q; } while (0)

static void launch_hgemm(const __half* A, const __half* B, void* C, const float* addend,
                         int M, int N, int K, int lda, int ldb, int ldc,
                         long sA0, long sA1, long sB0, long sB1, long sC0, long sC1,
                         int ZH, int Z, const int* tileExpert, long wStride, int flags)
{
    dim3 grid((N + TNW - 1) / TNW, M / 128, Z);
    hgemm_k<<<grid, 256, HG_SMEM>>>(A, B, C, addend, M, N, K, lda, ldb, ldc,
        sA0, sA1, sB0, sB1, sC0, sC1, ZH, tileExpert, wStride, flags);
}

static void launch_cvt(const float* src, __half* dst, long n)
{
    long n4 = n / 4;
    int blocks = (int)((n4 / 4 + 255) / 256);
    if (blocks < 148) blocks = 148;
    cvt4_k<<<blocks, 256>>>((const float4*)src, (uint2*)dst, n4);
}

extern "C" void kernel_launch(void* const* d_in, const int* in_sizes, int n_in,
                              void* d_out, int out_size)
{
    cudaFuncSetAttribute(hgemm_k, cudaFuncAttributeMaxDynamicSharedMemorySize, HG_SMEM);
    cudaFuncSetAttribute(fattn_k, cudaFuncAttributeMaxDynamicSharedMemorySize, FA_SMEM);

    const float* x       = (const float*)d_in[0];
    const float* fcos    = (const float*)d_in[1];
    const float* fsin    = (const float*)d_in[2];
    const float* attn_w  = (const float*)d_in[3];
    const float* wq      = (const float*)d_in[4];
    const float* wkv_a   = (const float*)d_in[5];
    const float* kv_w    = (const float*)d_in[6];
    const float* wkv_b   = (const float*)d_in[7];
    const float* wo      = (const float*)d_in[8];
    const float* ffn_w   = (const float*)d_in[9];
    const float* rw      = (const float*)d_in[10];
    const float* e_w1    = (const float*)d_in[11];
    const float* e_w3    = (const float*)d_in[12];
    const float* e_w2    = (const float*)d_in[13];
    const float* s_w1    = (const float*)d_in[14];
    const float* s_w3    = (const float*)d_in[15];
    const float* s_w2    = (const float*)d_in[16];
    float* out = (float*)d_out;

    float *qkv, *kpe, *kvb, *h;
    __half *nx_h, *ckv_h, *qh, *kcat, *vT, *attn_h, *nh_h, *xg, *t13h, *t1h, *s13h, *s1h;
    __half *eo_h, *sh_h;
    __half *wqa_h, *wkvb_h, *wo_h, *ew13_h, *ew2_h, *sw13_h, *sw2_h;
    int *counts, *off, *tile_expert, *bucket_ts, *flat_tok, *tok2row;
    float *bucket_gate, *tok2gate;
    SYM(qkv, g_qkv); SYM(kpe, g_kpe); SYM(kvb, g_kvb); SYM(h, g_h);
    SYM(nx_h, g_nx_h); SYM(ckv_h, g_ckv_h); SYM(qh, g_qh); SYM(kcat, g_kcat_h);
    SYM(vT, g_vT_h); SYM(attn_h, g_attn_h); SYM(nh_h, g_nh_h);
    SYM(xg, g_xg_h); SYM(t13h, g_t13h); SYM(t1h, g_t1h); SYM(s13h, g_s13h); SYM(s1h, g_s1h);
    SYM(eo_h, g_eo_h); SYM(sh_h, g_sh_h);
    SYM(wqa_h, g_wqa_h); SYM(wkvb_h, g_wkvb_h); SYM(wo_h, g_wo_h);
    SYM(ew13_h, g_ew13_h); SYM(ew2_h, g_ew2_h); SYM(sw13_h, g_sw13_h); SYM(sw2_h, g_sw2_h);
    SYM(counts, g_counts); SYM(off, g_off); SYM(tile_expert, g_tile_expert);
    SYM(bucket_ts, g_bucket_ts); SYM(bucket_gate, g_bucket_gate);
    SYM(flat_tok, g_flat_tok); SYM(tok2row, g_tok2row); SYM(tok2gate, g_tok2gate);

    const long PE4 = (long)MINTERn * DIMn / 4;

    // 0. weight conversion (coalesced; wq and wkv_a concatenated)
    launch_cvt(wq, wqa_h, (long)QPROJ * DIMn);
    launch_cvt(wkv_a, wqa_h + (size_t)QPROJ * DIMn, (long)KVAP * DIMn);
    launch_cvt(wkv_b, wkvb_h, (long)KVBP * KVRn);
    launch_cvt(wo, wo_h, (long)DIMn * DIMn);
    {
        long tot4 = (long)NEn * PE4;
        int blocks = (int)((tot4 / 4 + 255) / 256);
        cvtmoe4_k<<<blocks, 256>>>((const float4*)e_w1, (uint2*)ew13_h, PE4, 2 * PE4, 0, tot4);
        cvtmoe4_k<<<blocks, 256>>>((const float4*)e_w3, (uint2*)ew13_h, PE4, 2 * PE4, PE4, tot4);
    }
    launch_cvt(e_w2, ew2_h, (long)NEn * DIMn * MINTERn);
    launch_cvt(s_w1, sw13_h, (long)SHIn * DIMn);
    launch_cvt(s_w3, sw13_h + (size_t)SHIn * DIMn, (long)SHIn * DIMn);
    launch_cvt(s_w2, sw2_h, (long)DIMn * SHIn);

    // 1. attention-input rmsnorm -> fp16
    rmsnorm_h<<<Tn, 256>>>(x, attn_w, nx_h, DIMn, DIMn, DIMn);
    // 2+3. fused q + kv_a projection (fp32 out, N=3648)
    launch_hgemm(nx_h, wqa_h, qkv, nullptr, Tn, QKVP, DIMn, DIMn, DIMn, QKVP,
                 0, 0, 0, 0, 0, 0, 1, 1, nullptr, 0, 0);
    // 4. c_kv rmsnorm -> fp16 (kv part of qkv)
    rmsnorm_h<<<Tn, 256>>>(qkv + QPROJ, kv_w, ckv_h, KVRn, QKVP, KVRn);
    // 5. rope k_pe (strided source inside qkv)
    rope_kpe_k<<<Tn, 32>>>(qkv + QPROJ + KVRn, QKVP, fcos, fsin, kpe);
    // 6. kv_b projection (fp32 out)
    launch_hgemm(ckv_h, wkvb_h, kvb, nullptr, Tn, KVBP, KVRn, KVRn, KVRn, KVBP,
                 0, 0, 0, 0, 0, 0, 1, 1, nullptr, 0, 0);
    // 7. rope + scale q -> fp16 (strided source inside qkv)
    ropescale_qh<<<Tn * NHn, 96>>>(qkv, fcos, fsin, qh);
    // 8. kcat + vT -> fp16
    { dim3 g(Sn, ZSn); kcat_h<<<g, QDn>>>(kvb, kpe, kcat); }
    { dim3 g(Sn / 32, VHn / 32, ZSn); dim3 b(32, 8); vtrans_h<<<g, b>>>(kvb, vT); }
    // 9-11. fused flash attention -> attn fp16
    { dim3 g(16, ZSn); fattn_k<<<g, 256, FA_SMEM>>>(qh, kcat, vT, attn_h); }
    // 12. h = x + attn @ wo^T
    launch_hgemm(attn_h, wo_h, h, x, Tn, DIMn, DIMn, DIMn, DIMn, DIMn,
                 0, 0, 0, 0, 0, 0, 1, 1, nullptr, 0, 1);
    // 13. ffn rmsnorm -> fp16
    rmsnorm_h<<<Tn, 256>>>(h, ffn_w, nh_h, DIMn, DIMn, DIMn);
    // 14. routing
    cudaMemsetAsync(counts, 0, NEn * sizeof(int), 0);
    cudaMemsetAsync(flat_tok, 0xFF, MOE_ROWS * sizeof(int), 0);
    router_h<<<Tn, 256>>>(nh_h, rw, counts, bucket_ts, bucket_gate);
    offsets_k<<<1, 1>>>(counts, off, tile_expert);
    compact_k<<<NEn, 256>>>(counts, off, bucket_ts, bucket_gate, flat_tok, tok2row, tok2gate);
    gather_h<<<MOE_ROWS, 256>>>(nh_h, flat_tok, xg);
    // 15. expert FFN (grouped, fused w1||w3; fp16 eo)
    launch_hgemm(xg, ew13_h, t13h, nullptr, MOE_ROWS, 2 * MINTERn, DIMn,
                 DIMn, DIMn, 2 * MINTERn,
                 0, 0, 0, 0, 0, 0, 1, 1, tile_expert, 2L * MINTERn * DIMn, 8);
    {
        long n2 = (long)MOE_ROWS * MINTERn / 2;
        silumul2_h<<<(int)((n2 + 255) / 256), 256>>>(t13h, t1h, MINTERn, MOE_ROWS);
    }
    launch_hgemm(t1h, ew2_h, eo_h, nullptr, MOE_ROWS, DIMn, MINTERn, MINTERn, MINTERn, DIMn,
                 0, 0, 0, 0, 0, 0, 1, 1, tile_expert, (long)DIMn * MINTERn, 8);
    // 16. shared FFN (fused w1||w3; fp16 sh)
    launch_hgemm(nh_h, sw13_h, s13h, nullptr, Tn, 2 * SHIn, DIMn, DIMn, DIMn, 2 * SHIn,
                 0, 0, 0, 0, 0, 0, 1, 1, nullptr, 0, 8);
    {
        long n2 = (long)Tn * SHIn / 2;
        silumul2_h<<<(int)((n2 + 255) / 256), 256>>>(s13h, s1h, SHIn, Tn);
    }
    launch_hgemm(s1h, sw2_h, sh_h, nullptr, Tn, DIMn, SHIn, SHIn, SHIn, DIMn,
                 0, 0, 0, 0, 0, 0, 1, 1, nullptr, 0, 8);
    // 17. combine
    combine_k<<<Tn, 256>>>(h, sh_h, eo_h, tok2row, tok2gate, out);
}